// round 5
// baseline (speedup 1.0000x reference)
#include <cuda_runtime.h>
#include <math.h>

// Shapes (fixed by the problem)
#define B_  2
#define S_  2048
#define D_  1024
#define H_  16
#define DH_ 64
#define M_  (B_*S_)   // 4096 rows

// Scratch (allocation-free: __device__ globals)
__device__ float g_h [M_*D_];   // layernorm output        (B,S,D)
__device__ float g_q [M_*D_];   // q   in (B,H,S,DH)
__device__ float g_k [M_*D_];   // k_c in (B,H,S,DH)
__device__ float g_v [M_*D_];   // v_c in (B,H,S,DH)
__device__ float g_ao[M_*D_];   // gated attention output  (B,S,D)

// ---------------------------------------------------------------------------
// 1) LayerNorm: one block per row (1024 elems, 256 threads x 4)
// ---------------------------------------------------------------------------
__global__ __launch_bounds__(256) void ln_kernel(const float* __restrict__ x,
                                                 const float* __restrict__ gamma,
                                                 const float* __restrict__ beta) {
    int row = blockIdx.x;
    const float* xr = x + (size_t)row * D_;
    float v[4];
    float s = 0.f, s2 = 0.f;
#pragma unroll
    for (int i = 0; i < 4; i++) {
        v[i] = xr[threadIdx.x + i * 256];
        s += v[i]; s2 += v[i] * v[i];
    }
#pragma unroll
    for (int o = 16; o; o >>= 1) {
        s  += __shfl_xor_sync(0xffffffffu, s,  o);
        s2 += __shfl_xor_sync(0xffffffffu, s2, o);
    }
    __shared__ float red[16];
    int w = threadIdx.x >> 5;
    if ((threadIdx.x & 31) == 0) { red[w] = s; red[w + 8] = s2; }
    __syncthreads();
    float ts = 0.f, ts2 = 0.f;
#pragma unroll
    for (int i = 0; i < 8; i++) { ts += red[i]; ts2 += red[i + 8]; }
    float mean = ts * (1.0f / D_);
    float var  = ts2 * (1.0f / D_) - mean * mean;
    float rstd = rsqrtf(var + 1e-5f);
    float* hr = g_h + (size_t)row * D_;
#pragma unroll
    for (int i = 0; i < 4; i++) {
        int c = threadIdx.x + i * 256;
        hr[c] = (v[i] - mean) * rstd * gamma[c] + beta[c];
    }
}

// ---------------------------------------------------------------------------
// 2) QKV GEMM: g_h (4096x1024) @ W (1024x1024) -> head layout (B,H,S,DH)
//    which: 0=Q (plain), 1=K (compress), 2=V (compress)
//    64x64 tiles, BK=16, 256 threads, 4x4 per thread
// ---------------------------------------------------------------------------
__global__ __launch_bounds__(256) void gemm_qkv_kernel(const float* __restrict__ W,
                                                       const float* __restrict__ exps,
                                                       int which) {
    __shared__ __align__(16) float As[16][68];  // [k][m]
    __shared__ __align__(16) float Bs[16][68];  // [k][n]
    int m0 = blockIdx.y * 64, n0 = blockIdx.x * 64;
    int t = threadIdx.x, tx = t & 15, ty = t >> 4;
    float acc[4][4] = {};
    int ar = t >> 2,  ac = (t & 3) * 4;   // A tile: 64 rows x 16 k
    int br = t >> 4,  bc = (t & 15) * 4;  // W tile: 16 k x 64 n
    const float* Ap = g_h + (size_t)(m0 + ar) * D_ + ac;
    const float* Wp = W + (size_t)br * D_ + n0 + bc;

    for (int k0 = 0; k0 < D_; k0 += 16) {
        float4 a4 = *(const float4*)(Ap + k0);
        float4 w4 = *(const float4*)(Wp + (size_t)k0 * D_);
        As[ac + 0][ar] = a4.x; As[ac + 1][ar] = a4.y;
        As[ac + 2][ar] = a4.z; As[ac + 3][ar] = a4.w;
        *(float4*)&Bs[br][bc] = w4;
        __syncthreads();
#pragma unroll
        for (int kk = 0; kk < 16; kk++) {
            float4 af = *(const float4*)&As[kk][ty * 4];
            float4 bf = *(const float4*)&Bs[kk][tx * 4];
            float aa[4] = {af.x, af.y, af.z, af.w};
            float bb[4] = {bf.x, bf.y, bf.z, bf.w};
#pragma unroll
            for (int i = 0; i < 4; i++)
#pragma unroll
                for (int j = 0; j < 4; j++) acc[i][j] += aa[i] * bb[j];
        }
        __syncthreads();
    }

    float* out = (which == 0) ? g_q : (which == 1) ? g_k : g_v;
    int head = blockIdx.x;                 // BN(64) == DH(64): one head per n-tile
    float e = exps[head];
    bool comp = (which != 0);
#pragma unroll
    for (int i = 0; i < 4; i++) {
        int m = m0 + ty * 4 + i;
        int b = m >> 11, s = m & (S_ - 1);
        float* orow = out + (((size_t)b * H_ + head) * S_ + s) * DH_ + tx * 4;
#pragma unroll
        for (int j = 0; j < 4; j++) {
            float vv = acc[i][j];
            if (comp) {
                float mag = fmaxf(fabsf(vv), 1e-8f);
                float r = exp2f(e * log2f(mag));
                vv = (vv > 0.f) ? r : (vv < 0.f ? -r : 0.f);
            }
            orow[j] = vv;
        }
    }
}

// ---------------------------------------------------------------------------
// 3) Flash attention: 64 q-rows per block, 64-key tiles, online softmax.
//    scores' = (q.k)/(8*tau) + log(T_k+1e-6)/tau, causal; out gated by T_q / l
// ---------------------------------------------------------------------------
__global__ __launch_bounds__(256) void attn_kernel(const float* __restrict__ phase,
                                                   const float* __restrict__ cph,
                                                   const float* __restrict__ bal) {
    extern __shared__ __align__(16) float sm[];
    float* QsT = sm;              // [d][row]  64x68
    float* KsT = QsT + 64 * 68;   // [d][key]  64x68
    float* Vs  = KsT + 64 * 68;   // [key][d]  64x68
    float* Ps  = Vs  + 64 * 68;   // [row][key] 64x68
    float* lk  = Ps  + 64 * 68;   // [64] key log-resonance / tau

    int bh = blockIdx.y, b = bh >> 4, h = bh & 15;
    int qt = blockIdx.x, s0 = qt * 64;
    int t = threadIdx.x, tx = t & 15, ty = t >> 4;

    float bv  = bal[0];
    float tau = fminf(fmaxf(1.0f / (2.0f * bv + 1e-8f), 0.1f), 10.0f);
    float itau = 1.0f / tau;
    float qsc  = 0.125f * itau;   // 1/(sqrt(64)*tau)
    float cp   = cph[h];

    // load Q tile transposed [d][row]
    const float* qg = g_q + ((size_t)bh * S_ + s0) * DH_;
    {
        int r = t >> 2, c0 = (t & 3) * 4;
#pragma unroll
        for (int cc = 0; cc < 4; cc++) {
            int c = cc * 16 + c0;
            float4 f = *(const float4*)(qg + (size_t)r * DH_ + c);
            QsT[(c + 0) * 68 + r] = f.x; QsT[(c + 1) * 68 + r] = f.y;
            QsT[(c + 2) * 68 + r] = f.z; QsT[(c + 3) * 68 + r] = f.w;
        }
    }

    float acc[4][4] = {};
    float mrow[4], lrow[4];
#pragma unroll
    for (int i = 0; i < 4; i++) { mrow[i] = -1e30f; lrow[i] = 0.f; }

    for (int kt = 0; kt <= qt; kt++) {
        int kb = kt * 64;
        __syncthreads();   // protect Vs/Ps from previous iteration readers
        const float* kg = g_k + ((size_t)bh * S_ + kb) * DH_;
        const float* vg = g_v + ((size_t)bh * S_ + kb) * DH_;
        {
            int r = t >> 2, c0 = (t & 3) * 4;
#pragma unroll
            for (int cc = 0; cc < 4; cc++) {
                int c = cc * 16 + c0;
                float4 f = *(const float4*)(kg + (size_t)r * DH_ + c);
                KsT[(c + 0) * 68 + r] = f.x; KsT[(c + 1) * 68 + r] = f.y;
                KsT[(c + 2) * 68 + r] = f.z; KsT[(c + 3) * 68 + r] = f.w;
                float4 g2 = *(const float4*)(vg + (size_t)r * DH_ + c);
                *(float4*)&Vs[r * 68 + c] = g2;
            }
        }
        if (t < 64) {
            float ph = phase[(size_t)b * S_ + kb + t];
            float c = cosf((ph - cp) * 0.5f);
            lk[t] = logf(c * c + 1e-6f) * itau;
        }
        __syncthreads();

        // S tile: rows ty*4.., keys tx*4..
        float sreg[4][4] = {};
#pragma unroll 16
        for (int dd = 0; dd < 64; dd++) {
            float4 af = *(const float4*)&QsT[dd * 68 + ty * 4];
            float4 bf = *(const float4*)&KsT[dd * 68 + tx * 4];
            float aa[4] = {af.x, af.y, af.z, af.w};
            float bb[4] = {bf.x, bf.y, bf.z, bf.w};
#pragma unroll
            for (int i = 0; i < 4; i++)
#pragma unroll
                for (int j = 0; j < 4; j++) sreg[i][j] += aa[i] * bb[j];
        }

        float lkj[4];
#pragma unroll
        for (int j = 0; j < 4; j++) lkj[j] = lk[tx * 4 + j];
        bool diag = (kt == qt);
#pragma unroll
        for (int i = 0; i < 4; i++) {
            int qrow = ty * 4 + i;
#pragma unroll
            for (int j = 0; j < 4; j++) {
                float sc = sreg[i][j] * qsc + lkj[j];
                if (diag && (tx * 4 + j) > qrow) sc = -1e30f;
                sreg[i][j] = sc;
            }
        }

        // online softmax per row (row group = 16 lanes sharing ty)
#pragma unroll
        for (int i = 0; i < 4; i++) {
            float rm = fmaxf(fmaxf(sreg[i][0], sreg[i][1]),
                             fmaxf(sreg[i][2], sreg[i][3]));
#pragma unroll
            for (int o = 8; o; o >>= 1) rm = fmaxf(rm, __shfl_xor_sync(0xffffffffu, rm, o));
            float mn = fmaxf(mrow[i], rm);
            float al = __expf(mrow[i] - mn);
            float rs = 0.f;
#pragma unroll
            for (int j = 0; j < 4; j++) {
                float p = __expf(sreg[i][j] - mn);
                sreg[i][j] = p; rs += p;
            }
#pragma unroll
            for (int o = 8; o; o >>= 1) rs += __shfl_xor_sync(0xffffffffu, rs, o);
            lrow[i] = lrow[i] * al + rs;
            mrow[i] = mn;
#pragma unroll
            for (int j = 0; j < 4; j++) acc[i][j] *= al;
        }

        // store P natural [row][key] (contiguous float4, ~conflict-free)
#pragma unroll
        for (int i = 0; i < 4; i++)
            *(float4*)&Ps[(ty * 4 + i) * 68 + tx * 4] =
                make_float4(sreg[i][0], sreg[i][1], sreg[i][2], sreg[i][3]);
        __syncthreads();

        // O += P @ V : rows ty*4.., dims tx*4..
#pragma unroll 4
        for (int kk = 0; kk < 64; kk += 4) {
            float4 pr[4];
#pragma unroll
            for (int i = 0; i < 4; i++)
                pr[i] = *(const float4*)&Ps[(ty * 4 + i) * 68 + kk];
#pragma unroll
            for (int u = 0; u < 4; u++) {
                float4 vf = *(const float4*)&Vs[(kk + u) * 68 + tx * 4];
                float vb4[4] = {vf.x, vf.y, vf.z, vf.w};
                float pu[4] = {
                    (u == 0) ? pr[0].x : (u == 1) ? pr[0].y : (u == 2) ? pr[0].z : pr[0].w,
                    (u == 0) ? pr[1].x : (u == 1) ? pr[1].y : (u == 2) ? pr[1].z : pr[1].w,
                    (u == 0) ? pr[2].x : (u == 1) ? pr[2].y : (u == 2) ? pr[2].z : pr[2].w,
                    (u == 0) ? pr[3].x : (u == 1) ? pr[3].y : (u == 2) ? pr[3].z : pr[3].w};
#pragma unroll
                for (int i = 0; i < 4; i++)
#pragma unroll
                    for (int j = 0; j < 4; j++) acc[i][j] += pu[i] * vb4[j];
            }
        }
    }

    // epilogue: divide by l, gate by query-side resonance, write (B,S,D)
#pragma unroll
    for (int i = 0; i < 4; i++) {
        int srow = s0 + ty * 4 + i;
        float ph = phase[(size_t)b * S_ + srow];
        float cq = cosf((ph - cp) * 0.5f);
        float g = (cq * cq) / lrow[i];
        float* orow = g_ao + ((size_t)b * S_ + srow) * D_ + h * DH_ + tx * 4;
        *(float4*)orow = make_float4(acc[i][0] * g, acc[i][1] * g,
                                     acc[i][2] * g, acc[i][3] * g);
    }
}

// ---------------------------------------------------------------------------
// 4) Output GEMM + residual: y = x + g_ao @ Wo
// ---------------------------------------------------------------------------
__global__ __launch_bounds__(256) void gemm_out_kernel(const float* __restrict__ Wo,
                                                       const float* __restrict__ x,
                                                       float* __restrict__ y) {
    __shared__ __align__(16) float As[16][68];
    __shared__ __align__(16) float Bs[16][68];
    int m0 = blockIdx.y * 64, n0 = blockIdx.x * 64;
    int t = threadIdx.x, tx = t & 15, ty = t >> 4;
    float acc[4][4] = {};
    int ar = t >> 2,  ac = (t & 3) * 4;
    int br = t >> 4,  bc = (t & 15) * 4;
    const float* Ap = g_ao + (size_t)(m0 + ar) * D_ + ac;
    const float* Wp = Wo + (size_t)br * D_ + n0 + bc;

    for (int k0 = 0; k0 < D_; k0 += 16) {
        float4 a4 = *(const float4*)(Ap + k0);
        float4 w4 = *(const float4*)(Wp + (size_t)k0 * D_);
        As[ac + 0][ar] = a4.x; As[ac + 1][ar] = a4.y;
        As[ac + 2][ar] = a4.z; As[ac + 3][ar] = a4.w;
        *(float4*)&Bs[br][bc] = w4;
        __syncthreads();
#pragma unroll
        for (int kk = 0; kk < 16; kk++) {
            float4 af = *(const float4*)&As[kk][ty * 4];
            float4 bf = *(const float4*)&Bs[kk][tx * 4];
            float aa[4] = {af.x, af.y, af.z, af.w};
            float bb[4] = {bf.x, bf.y, bf.z, bf.w};
#pragma unroll
            for (int i = 0; i < 4; i++)
#pragma unroll
                for (int j = 0; j < 4; j++) acc[i][j] += aa[i] * bb[j];
        }
        __syncthreads();
    }
#pragma unroll
    for (int i = 0; i < 4; i++) {
        size_t idx = (size_t)(m0 + ty * 4 + i) * D_ + n0 + tx * 4;
        float4 xr = *(const float4*)(x + idx);
        *(float4*)(y + idx) = make_float4(xr.x + acc[i][0], xr.y + acc[i][1],
                                          xr.z + acc[i][2], xr.w + acc[i][3]);
    }
}

// ---------------------------------------------------------------------------
extern "C" void kernel_launch(void* const* d_in, const int* in_sizes, int n_in,
                              void* d_out, int out_size) {
    const float* x     = (const float*)d_in[0];
    const float* phase = (const float*)d_in[1];
    const float* Wq    = (const float*)d_in[2];
    const float* Wk    = (const float*)d_in[3];
    const float* Wv    = (const float*)d_in[4];
    const float* Wo    = (const float*)d_in[5];
    const float* gamma = (const float*)d_in[6];
    const float* beta  = (const float*)d_in[7];
    const float* exps  = (const float*)d_in[8];
    const float* cph   = (const float*)d_in[9];
    const float* bal   = (const float*)d_in[10];
    float* y = (float*)d_out;

    ln_kernel<<<M_, 256>>>(x, gamma, beta);

    dim3 gg(D_ / 64, M_ / 64);
    gemm_qkv_kernel<<<gg, 256>>>(Wq, exps, 0);
    gemm_qkv_kernel<<<gg, 256>>>(Wk, exps, 1);
    gemm_qkv_kernel<<<gg, 256>>>(Wv, exps, 2);

    const int ATT_SMEM = (4 * 64 * 68 + 64) * (int)sizeof(float);  // ~69.9 KB
    cudaFuncSetAttribute((const void*)attn_kernel,
                         cudaFuncAttributeMaxDynamicSharedMemorySize, ATT_SMEM);
    attn_kernel<<<dim3(S_ / 64, B_ * H_), 256, ATT_SMEM>>>(phase, cph, bal);

    gemm_out_kernel<<<gg, 256>>>(Wo, x, y);
}

// round 8
// speedup vs baseline: 1.4446x; 1.4446x over previous
#include <cuda_runtime.h>
#include <cuda_bf16.h>
#include <math.h>
#include <stdint.h>

// Shapes (fixed)
#define B_  2
#define S_  2048
#define D_  1024
#define H_  16
#define DH_ 64
#define M_  (B_*S_)   // 4096

// ---------------------------------------------------------------------------
// Scratch (__device__ globals; allocation-free)
// ---------------------------------------------------------------------------
__device__ __nv_bfloat16 g_h_hi [M_*D_];
__device__ __nv_bfloat16 g_h_lo [M_*D_];
__device__ __nv_bfloat16 g_wt_hi[4][D_*D_];   // transposed weights [N][K]
__device__ __nv_bfloat16 g_wt_lo[4][D_*D_];
__device__ float g_q [M_*D_];                 // (B,H,S,DH)
__device__ float g_k [M_*D_];
__device__ float g_v [M_*D_];
__device__ __nv_bfloat16 g_ao_hi[M_*D_];      // gated attn out, (B,S,D)
__device__ __nv_bfloat16 g_ao_lo[M_*D_];

// ---------------------------------------------------------------------------
// helpers
// ---------------------------------------------------------------------------
__device__ __forceinline__ uint32_t smem_u32(const void* p) {
    uint32_t a;
    asm("{ .reg .u64 t; cvta.to.shared.u64 t, %1; cvt.u32.u64 %0, t; }"
        : "=r"(a) : "l"(p));
    return a;
}
__device__ __forceinline__ void ldsm4(uint32_t* r, uint32_t addr) {
    asm volatile("ldmatrix.sync.aligned.m8n8.x4.shared.b16 {%0,%1,%2,%3}, [%4];"
                 : "=r"(r[0]), "=r"(r[1]), "=r"(r[2]), "=r"(r[3]) : "r"(addr));
}
__device__ __forceinline__ void mma16816(float* c, const uint32_t* a,
                                         const uint32_t* b) {
    asm volatile(
        "mma.sync.aligned.m16n8k16.row.col.f32.bf16.bf16.f32 "
        "{%0,%1,%2,%3}, {%4,%5,%6,%7}, {%8,%9}, {%0,%1,%2,%3};"
        : "+f"(c[0]), "+f"(c[1]), "+f"(c[2]), "+f"(c[3])
        : "r"(a[0]), "r"(a[1]), "r"(a[2]), "r"(a[3]), "r"(b[0]), "r"(b[1]));
}

// ---------------------------------------------------------------------------
// 1) LayerNorm -> hi/lo bf16
// ---------------------------------------------------------------------------
__global__ __launch_bounds__(256) void ln_kernel(const float* __restrict__ x,
                                                 const float* __restrict__ gamma,
                                                 const float* __restrict__ beta) {
    int row = blockIdx.x;
    const float* xr = x + (size_t)row * D_;
    float v[4];
    float s = 0.f, s2 = 0.f;
#pragma unroll
    for (int i = 0; i < 4; i++) {
        v[i] = xr[threadIdx.x + i * 256];
        s += v[i]; s2 += v[i] * v[i];
    }
#pragma unroll
    for (int o = 16; o; o >>= 1) {
        s  += __shfl_xor_sync(0xffffffffu, s,  o);
        s2 += __shfl_xor_sync(0xffffffffu, s2, o);
    }
    __shared__ float red[16];
    int w = threadIdx.x >> 5;
    if ((threadIdx.x & 31) == 0) { red[w] = s; red[w + 8] = s2; }
    __syncthreads();
    float ts = 0.f, ts2 = 0.f;
#pragma unroll
    for (int i = 0; i < 8; i++) { ts += red[i]; ts2 += red[i + 8]; }
    float mean = ts * (1.0f / D_);
    float var  = ts2 * (1.0f / D_) - mean * mean;
    float rstd = rsqrtf(var + 1e-5f);
#pragma unroll
    for (int i = 0; i < 4; i++) {
        int c = threadIdx.x + i * 256;
        float hv = (v[i] - mean) * rstd * gamma[c] + beta[c];
        __nv_bfloat16 hb = __float2bfloat16(hv);
        g_h_hi[(size_t)row * D_ + c] = hb;
        g_h_lo[(size_t)row * D_ + c] = __float2bfloat16(hv - __bfloat162float(hb));
    }
}

// ---------------------------------------------------------------------------
// 2) Weight transpose+convert: W[k][n] -> Wt_hi/lo[n][k]
// ---------------------------------------------------------------------------
__global__ __launch_bounds__(256) void wconv_kernel(const float* __restrict__ W,
                                                    __nv_bfloat16* __restrict__ Thi,
                                                    __nv_bfloat16* __restrict__ Tlo) {
    __shared__ float tl[32][33];
    int n0 = blockIdx.x * 32, k0 = blockIdx.y * 32;
    int tx = threadIdx.x, ty = threadIdx.y;
#pragma unroll
    for (int j = 0; j < 4; j++) {
        int k = k0 + ty + j * 8;
        tl[ty + j * 8][tx] = W[(size_t)k * D_ + n0 + tx];
    }
    __syncthreads();
#pragma unroll
    for (int j = 0; j < 4; j++) {
        int n = n0 + ty + j * 8;
        float v = tl[tx][ty + j * 8];
        __nv_bfloat16 hb = __float2bfloat16(v);
        Thi[(size_t)n * D_ + k0 + tx] = hb;
        Tlo[(size_t)n * D_ + k0 + tx] = __float2bfloat16(v - __bfloat162float(hb));
    }
}

// ---------------------------------------------------------------------------
// 3) HMMA GEMM: C[128x64] tile = A[128xK] @ Wt[64xK]^T, hi/lo split (3 mmas)
//    which: 0=Q 1=K(compress) 2=V(compress) 3=out(+residual -> y)
// ---------------------------------------------------------------------------
#define BK   32
#define PADK 40   // bf16 per smem row (80B): conflict-free ldmatrix

__global__ __launch_bounds__(256) void gemm_mma_kernel(
        const __nv_bfloat16* __restrict__ Ahi, const __nv_bfloat16* __restrict__ Alo,
        const __nv_bfloat16* __restrict__ Bhi, const __nv_bfloat16* __restrict__ Blo,
        const float* __restrict__ exps, const float* __restrict__ x,
        float* __restrict__ y, int which) {
    __shared__ __align__(16) __nv_bfloat16 sA[2][128 * PADK];
    __shared__ __align__(16) __nv_bfloat16 sB[2][64 * PADK];
    int t = threadIdx.x, lane = t & 31, wid = t >> 5;
    int wm = wid & 3, wn = wid >> 2;
    int m0 = blockIdx.y * 128, n0 = blockIdx.x * 64;
    float acc[2][4][4] = {};

    for (int kc = 0; kc < D_ / BK; kc++) {
        int k0 = kc * BK;
        __syncthreads();
#pragma unroll
        for (int i = 0; i < 2; i++) {
            int idx = t + i * 256;
            int row = idx >> 2, c8 = (idx & 3) * 8;
            size_t go = (size_t)(m0 + row) * D_ + k0 + c8;
            *(uint4*)&sA[0][row * PADK + c8] = *(const uint4*)(Ahi + go);
            *(uint4*)&sA[1][row * PADK + c8] = *(const uint4*)(Alo + go);
        }
        {
            int row = t >> 2, c8 = (t & 3) * 8;
            size_t go = (size_t)(n0 + row) * D_ + k0 + c8;
            *(uint4*)&sB[0][row * PADK + c8] = *(const uint4*)(Bhi + go);
            *(uint4*)&sB[1][row * PADK + c8] = *(const uint4*)(Blo + go);
        }
        __syncthreads();
#pragma unroll
        for (int ks = 0; ks < BK; ks += 16) {
            uint32_t ah[2][4], al[2][4], bh[2][4], bl[2][4];
#pragma unroll
            for (int mi = 0; mi < 2; mi++) {
                int ar = wm * 32 + mi * 16 + (lane & 15);
                int ac = ks + ((lane >> 4) << 3);
                ldsm4(ah[mi], smem_u32(&sA[0][ar * PADK + ac]));
                ldsm4(al[mi], smem_u32(&sA[1][ar * PADK + ac]));
            }
#pragma unroll
            for (int p = 0; p < 2; p++) {
                int br = wn * 32 + p * 16 + (lane & 7) + ((lane & 16) ? 8 : 0);
                int bc = ks + ((lane & 8) ? 8 : 0);
                ldsm4(bh[p], smem_u32(&sB[0][br * PADK + bc]));
                ldsm4(bl[p], smem_u32(&sB[1][br * PADK + bc]));
            }
#pragma unroll
            for (int mi = 0; mi < 2; mi++)
#pragma unroll
                for (int nj = 0; nj < 4; nj++) {
                    const uint32_t* fbh = &bh[nj >> 1][(nj & 1) * 2];
                    const uint32_t* fbl = &bl[nj >> 1][(nj & 1) * 2];
                    mma16816(acc[mi][nj], ah[mi], fbh);
                    mma16816(acc[mi][nj], ah[mi], fbl);
                    mma16816(acc[mi][nj], al[mi], fbh);
                }
        }
    }

    // Epilogue
    int head = blockIdx.x;
    float e = (which == 1 || which == 2) ? exps[head] : 0.f;
    float* qkv = (which == 0) ? g_q : (which == 1) ? g_k : g_v;
#pragma unroll
    for (int mi = 0; mi < 2; mi++)
#pragma unroll
        for (int nj = 0; nj < 4; nj++)
#pragma unroll
            for (int h2 = 0; h2 < 2; h2++) {
                int m = m0 + wm * 32 + mi * 16 + (lane >> 2) + h2 * 8;
                int nc = wn * 32 + nj * 8 + (lane & 3) * 2;
                float v0 = acc[mi][nj][h2 * 2];
                float v1 = acc[mi][nj][h2 * 2 + 1];
                if (which < 3) {
                    if (which != 0) {
                        float mg0 = fmaxf(fabsf(v0), 1e-8f);
                        float r0 = exp2f(e * log2f(mg0));
                        v0 = (v0 > 0.f) ? r0 : (v0 < 0.f ? -r0 : 0.f);
                        float mg1 = fmaxf(fabsf(v1), 1e-8f);
                        float r1 = exp2f(e * log2f(mg1));
                        v1 = (v1 > 0.f) ? r1 : (v1 < 0.f ? -r1 : 0.f);
                    }
                    int b = m >> 11, s = m & (S_ - 1);
                    float* dst = qkv + (((size_t)b * H_ + head) * S_ + s) * DH_ + nc;
                    *(float2*)dst = make_float2(v0, v1);
                } else {
                    size_t off = (size_t)m * D_ + n0 + nc;
                    float2 xr = *(const float2*)(x + off);
                    *(float2*)(y + off) = make_float2(xr.x + v0, xr.y + v1);
                }
            }
}

// ---------------------------------------------------------------------------
// 4) Flash attention (fp32 SIMT; epilogue -> hi/lo bf16)
// ---------------------------------------------------------------------------
__global__ __launch_bounds__(256) void attn_kernel(const float* __restrict__ phase,
                                                   const float* __restrict__ cph,
                                                   const float* __restrict__ bal) {
    extern __shared__ __align__(16) float sm[];
    float* QsT = sm;
    float* KsT = QsT + 64 * 68;
    float* Vs  = KsT + 64 * 68;
    float* Ps  = Vs  + 64 * 68;
    float* lk  = Ps  + 64 * 68;

    int bh = blockIdx.y, b = bh >> 4, h = bh & 15;
    int qt = blockIdx.x, s0 = qt * 64;
    int t = threadIdx.x, tx = t & 15, ty = t >> 4;

    float bv  = bal[0];
    float tau = fminf(fmaxf(1.0f / (2.0f * bv + 1e-8f), 0.1f), 10.0f);
    float itau = 1.0f / tau;
    float qsc  = 0.125f * itau;
    float cp   = cph[h];

    const float* qg = g_q + ((size_t)bh * S_ + s0) * DH_;
    {
        int r = t >> 2, c0 = (t & 3) * 4;
#pragma unroll
        for (int cc = 0; cc < 4; cc++) {
            int c = cc * 16 + c0;
            float4 f = *(const float4*)(qg + (size_t)r * DH_ + c);
            QsT[(c + 0) * 68 + r] = f.x; QsT[(c + 1) * 68 + r] = f.y;
            QsT[(c + 2) * 68 + r] = f.z; QsT[(c + 3) * 68 + r] = f.w;
        }
    }

    float acc[4][4] = {};
    float mrow[4], lrow[4];
#pragma unroll
    for (int i = 0; i < 4; i++) { mrow[i] = -1e30f; lrow[i] = 0.f; }

    for (int kt = 0; kt <= qt; kt++) {
        int kb = kt * 64;
        __syncthreads();
        const float* kg = g_k + ((size_t)bh * S_ + kb) * DH_;
        const float* vg = g_v + ((size_t)bh * S_ + kb) * DH_;
        {
            int r = t >> 2, c0 = (t & 3) * 4;
#pragma unroll
            for (int cc = 0; cc < 4; cc++) {
                int c = cc * 16 + c0;
                float4 f = *(const float4*)(kg + (size_t)r * DH_ + c);
                KsT[(c + 0) * 68 + r] = f.x; KsT[(c + 1) * 68 + r] = f.y;
                KsT[(c + 2) * 68 + r] = f.z; KsT[(c + 3) * 68 + r] = f.w;
                float4 g2 = *(const float4*)(vg + (size_t)r * DH_ + c);
                *(float4*)&Vs[r * 68 + c] = g2;
            }
        }
        if (t < 64) {
            float ph = phase[(size_t)b * S_ + kb + t];
            float c = cosf((ph - cp) * 0.5f);
            lk[t] = logf(c * c + 1e-6f) * itau;
        }
        __syncthreads();

        float sreg[4][4] = {};
#pragma unroll 16
        for (int dd = 0; dd < 64; dd++) {
            float4 af = *(const float4*)&QsT[dd * 68 + ty * 4];
            float4 bf = *(const float4*)&KsT[dd * 68 + tx * 4];
            float aa[4] = {af.x, af.y, af.z, af.w};
            float bb[4] = {bf.x, bf.y, bf.z, bf.w};
#pragma unroll
            for (int i = 0; i < 4; i++)
#pragma unroll
                for (int j = 0; j < 4; j++) sreg[i][j] += aa[i] * bb[j];
        }

        float lkj[4];
#pragma unroll
        for (int j = 0; j < 4; j++) lkj[j] = lk[tx * 4 + j];
        bool diag = (kt == qt);
#pragma unroll
        for (int i = 0; i < 4; i++) {
            int qrow = ty * 4 + i;
#pragma unroll
            for (int j = 0; j < 4; j++) {
                float sc = sreg[i][j] * qsc + lkj[j];
                if (diag && (tx * 4 + j) > qrow) sc = -1e30f;
                sreg[i][j] = sc;
            }
        }

#pragma unroll
        for (int i = 0; i < 4; i++) {
            float rm = fmaxf(fmaxf(sreg[i][0], sreg[i][1]),
                             fmaxf(sreg[i][2], sreg[i][3]));
#pragma unroll
            for (int o = 8; o; o >>= 1) rm = fmaxf(rm, __shfl_xor_sync(0xffffffffu, rm, o));
            float mn = fmaxf(mrow[i], rm);
            float al = __expf(mrow[i] - mn);
            float rs = 0.f;
#pragma unroll
            for (int j = 0; j < 4; j++) {
                float p = __expf(sreg[i][j] - mn);
                sreg[i][j] = p; rs += p;
            }
#pragma unroll
            for (int o = 8; o; o >>= 1) rs += __shfl_xor_sync(0xffffffffu, rs, o);
            lrow[i] = lrow[i] * al + rs;
            mrow[i] = mn;
#pragma unroll
            for (int j = 0; j < 4; j++) acc[i][j] *= al;
        }

#pragma unroll
        for (int i = 0; i < 4; i++)
            *(float4*)&Ps[(ty * 4 + i) * 68 + tx * 4] =
                make_float4(sreg[i][0], sreg[i][1], sreg[i][2], sreg[i][3]);
        __syncthreads();

#pragma unroll 4
        for (int kk = 0; kk < 64; kk += 4) {
            float4 pr[4];
#pragma unroll
            for (int i = 0; i < 4; i++)
                pr[i] = *(const float4*)&Ps[(ty * 4 + i) * 68 + kk];
#pragma unroll
            for (int u = 0; u < 4; u++) {
                float4 vf = *(const float4*)&Vs[(kk + u) * 68 + tx * 4];
                float vb4[4] = {vf.x, vf.y, vf.z, vf.w};
                float pu[4] = {
                    (u == 0) ? pr[0].x : (u == 1) ? pr[0].y : (u == 2) ? pr[0].z : pr[0].w,
                    (u == 0) ? pr[1].x : (u == 1) ? pr[1].y : (u == 2) ? pr[1].z : pr[1].w,
                    (u == 0) ? pr[2].x : (u == 1) ? pr[2].y : (u == 2) ? pr[2].z : pr[2].w,
                    (u == 0) ? pr[3].x : (u == 1) ? pr[3].y : (u == 2) ? pr[3].z : pr[3].w};
#pragma unroll
                for (int i = 0; i < 4; i++)
#pragma unroll
                    for (int j = 0; j < 4; j++) acc[i][j] += pu[i] * vb4[j];
            }
        }
    }

#pragma unroll
    for (int i = 0; i < 4; i++) {
        int srow = s0 + ty * 4 + i;
        float ph = phase[(size_t)b * S_ + srow];
        float cq = cosf((ph - cp) * 0.5f);
        float g = (cq * cq) / lrow[i];
        size_t off = ((size_t)b * S_ + srow) * D_ + h * DH_ + tx * 4;
#pragma unroll
        for (int j = 0; j < 4; j++) {
            float ov = acc[i][j] * g;
            __nv_bfloat16 hb = __float2bfloat16(ov);
            g_ao_hi[off + j] = hb;
            g_ao_lo[off + j] = __float2bfloat16(ov - __bfloat162float(hb));
        }
    }
}

// ---------------------------------------------------------------------------
extern "C" void kernel_launch(void* const* d_in, const int* in_sizes, int n_in,
                              void* d_out, int out_size) {
    const float* x     = (const float*)d_in[0];
    const float* phase = (const float*)d_in[1];
    const float* Wq    = (const float*)d_in[2];
    const float* Wk    = (const float*)d_in[3];
    const float* Wv    = (const float*)d_in[4];
    const float* Wo    = (const float*)d_in[5];
    const float* gamma = (const float*)d_in[6];
    const float* beta  = (const float*)d_in[7];
    const float* exps  = (const float*)d_in[8];
    const float* cph   = (const float*)d_in[9];
    const float* bal   = (const float*)d_in[10];
    float* y = (float*)d_out;

    static __nv_bfloat16 *wthi[4], *wtlo[4];
    static __nv_bfloat16 *hhi, *hlo, *aohi, *aolo;
    static bool got = false;
    if (!got) {
        cudaGetSymbolAddress((void**)&wthi[0], g_wt_hi);
        cudaGetSymbolAddress((void**)&wtlo[0], g_wt_lo);
        for (int i = 1; i < 4; i++) {
            wthi[i] = wthi[0] + (size_t)i * D_ * D_;
            wtlo[i] = wtlo[0] + (size_t)i * D_ * D_;
        }
        cudaGetSymbolAddress((void**)&hhi, g_h_hi);
        cudaGetSymbolAddress((void**)&hlo, g_h_lo);
        cudaGetSymbolAddress((void**)&aohi, g_ao_hi);
        cudaGetSymbolAddress((void**)&aolo, g_ao_lo);
        got = true;
    }

    ln_kernel<<<M_, 256>>>(x, gamma, beta);

    dim3 wg(32, 32);
    wconv_kernel<<<wg, dim3(32, 8)>>>(Wq, wthi[0], wtlo[0]);
    wconv_kernel<<<wg, dim3(32, 8)>>>(Wk, wthi[1], wtlo[1]);
    wconv_kernel<<<wg, dim3(32, 8)>>>(Wv, wthi[2], wtlo[2]);
    wconv_kernel<<<wg, dim3(32, 8)>>>(Wo, wthi[3], wtlo[3]);

    dim3 gg(D_ / 64, M_ / 128);
    gemm_mma_kernel<<<gg, 256>>>(hhi, hlo, wthi[0], wtlo[0], exps, x, y, 0);
    gemm_mma_kernel<<<gg, 256>>>(hhi, hlo, wthi[1], wtlo[1], exps, x, y, 1);
    gemm_mma_kernel<<<gg, 256>>>(hhi, hlo, wthi[2], wtlo[2], exps, x, y, 2);

    const int ATT_SMEM = (4 * 64 * 68 + 64) * (int)sizeof(float);
    cudaFuncSetAttribute((const void*)attn_kernel,
                         cudaFuncAttributeMaxDynamicSharedMemorySize, ATT_SMEM);
    attn_kernel<<<dim3(S_ / 64, B_ * H_), 256, ATT_SMEM>>>(phase, cph, bal);

    gemm_mma_kernel<<<gg, 256>>>(aohi, aolo, wthi[3], wtlo[3], exps, x, y, 3);
}

// round 9
// speedup vs baseline: 1.4508x; 1.0043x over previous
#include <cuda_runtime.h>
#include <cuda_bf16.h>
#include <math.h>
#include <stdint.h>

// Shapes (fixed)
#define B_  2
#define S_  2048
#define D_  1024
#define H_  16
#define DH_ 64
#define M_  (B_*S_)   // 4096

// ---------------------------------------------------------------------------
// Scratch (__device__ globals; allocation-free)
// ---------------------------------------------------------------------------
__device__ __nv_bfloat16 g_h_hi [M_*D_];
__device__ __nv_bfloat16 g_h_lo [M_*D_];
__device__ __nv_bfloat16 g_wt_hi[4][D_*D_];   // transposed weights [N][K]
__device__ __nv_bfloat16 g_wt_lo[4][D_*D_];
__device__ float g_q [M_*D_];                 // (B,H,S,DH)
__device__ float g_k [M_*D_];
__device__ float g_v [M_*D_];
__device__ __nv_bfloat16 g_ao_hi[M_*D_];      // gated attn out, (B,S,D)
__device__ __nv_bfloat16 g_ao_lo[M_*D_];

// ---------------------------------------------------------------------------
// helpers
// ---------------------------------------------------------------------------
__device__ __forceinline__ uint32_t smem_u32(const void* p) {
    uint32_t a;
    asm("{ .reg .u64 t; cvta.to.shared.u64 t, %1; cvt.u32.u64 %0, t; }"
        : "=r"(a) : "l"(p));
    return a;
}
__device__ __forceinline__ void ldsm4(uint32_t* r, uint32_t addr) {
    asm volatile("ldmatrix.sync.aligned.m8n8.x4.shared.b16 {%0,%1,%2,%3}, [%4];"
                 : "=r"(r[0]), "=r"(r[1]), "=r"(r[2]), "=r"(r[3]) : "r"(addr));
}
__device__ __forceinline__ void mma16816(float* c, const uint32_t* a,
                                         const uint32_t* b) {
    asm volatile(
        "mma.sync.aligned.m16n8k16.row.col.f32.bf16.bf16.f32 "
        "{%0,%1,%2,%3}, {%4,%5,%6,%7}, {%8,%9}, {%0,%1,%2,%3};"
        : "+f"(c[0]), "+f"(c[1]), "+f"(c[2]), "+f"(c[3])
        : "r"(a[0]), "r"(a[1]), "r"(a[2]), "r"(a[3]), "r"(b[0]), "r"(b[1]));
}

// ---------------------------------------------------------------------------
// 1) LayerNorm -> hi/lo bf16
// ---------------------------------------------------------------------------
__global__ __launch_bounds__(256) void ln_kernel(const float* __restrict__ x,
                                                 const float* __restrict__ gamma,
                                                 const float* __restrict__ beta) {
    int row = blockIdx.x;
    const float* xr = x + (size_t)row * D_;
    float v[4];
    float s = 0.f, s2 = 0.f;
#pragma unroll
    for (int i = 0; i < 4; i++) {
        v[i] = xr[threadIdx.x + i * 256];
        s += v[i]; s2 += v[i] * v[i];
    }
#pragma unroll
    for (int o = 16; o; o >>= 1) {
        s  += __shfl_xor_sync(0xffffffffu, s,  o);
        s2 += __shfl_xor_sync(0xffffffffu, s2, o);
    }
    __shared__ float red[16];
    int w = threadIdx.x >> 5;
    if ((threadIdx.x & 31) == 0) { red[w] = s; red[w + 8] = s2; }
    __syncthreads();
    float ts = 0.f, ts2 = 0.f;
#pragma unroll
    for (int i = 0; i < 8; i++) { ts += red[i]; ts2 += red[i + 8]; }
    float mean = ts * (1.0f / D_);
    float var  = ts2 * (1.0f / D_) - mean * mean;
    float rstd = rsqrtf(var + 1e-5f);
#pragma unroll
    for (int i = 0; i < 4; i++) {
        int c = threadIdx.x + i * 256;
        float hv = (v[i] - mean) * rstd * gamma[c] + beta[c];
        __nv_bfloat16 hb = __float2bfloat16(hv);
        g_h_hi[(size_t)row * D_ + c] = hb;
        g_h_lo[(size_t)row * D_ + c] = __float2bfloat16(hv - __bfloat162float(hb));
    }
}

// ---------------------------------------------------------------------------
// 2) Weight transpose+convert: W[k][n] -> Wt_hi/lo[n][k]
// ---------------------------------------------------------------------------
__global__ __launch_bounds__(256) void wconv_kernel(const float* __restrict__ W,
                                                    __nv_bfloat16* __restrict__ Thi,
                                                    __nv_bfloat16* __restrict__ Tlo) {
    __shared__ float tl[32][33];
    int n0 = blockIdx.x * 32, k0 = blockIdx.y * 32;
    int tx = threadIdx.x, ty = threadIdx.y;
#pragma unroll
    for (int j = 0; j < 4; j++) {
        int k = k0 + ty + j * 8;
        tl[ty + j * 8][tx] = W[(size_t)k * D_ + n0 + tx];
    }
    __syncthreads();
#pragma unroll
    for (int j = 0; j < 4; j++) {
        int n = n0 + ty + j * 8;
        float v = tl[tx][ty + j * 8];
        __nv_bfloat16 hb = __float2bfloat16(v);
        Thi[(size_t)n * D_ + k0 + tx] = hb;
        Tlo[(size_t)n * D_ + k0 + tx] = __float2bfloat16(v - __bfloat162float(hb));
    }
}

// ---------------------------------------------------------------------------
// 3) HMMA GEMM: C[128x64] tile = A[128xK] @ Wt[64xK]^T, hi/lo split (3 mmas)
//    which: 0=Q 1=K(compress) 2=V(compress) 3=out(+residual -> y)
// ---------------------------------------------------------------------------
#define BK   32
#define PADK 40   // bf16 per smem row (80B): conflict-free ldmatrix

__global__ __launch_bounds__(256) void gemm_mma_kernel(
        const __nv_bfloat16* __restrict__ Ahi, const __nv_bfloat16* __restrict__ Alo,
        const __nv_bfloat16* __restrict__ Bhi, const __nv_bfloat16* __restrict__ Blo,
        const float* __restrict__ exps, const float* __restrict__ x,
        float* __restrict__ y, int which) {
    __shared__ __align__(16) __nv_bfloat16 sA[2][128 * PADK];
    __shared__ __align__(16) __nv_bfloat16 sB[2][64 * PADK];
    int t = threadIdx.x, lane = t & 31, wid = t >> 5;
    int wm = wid & 3, wn = wid >> 2;
    int m0 = blockIdx.y * 128, n0 = blockIdx.x * 64;
    float acc[2][4][4] = {};

    for (int kc = 0; kc < D_ / BK; kc++) {
        int k0 = kc * BK;
        __syncthreads();
#pragma unroll
        for (int i = 0; i < 2; i++) {
            int idx = t + i * 256;
            int row = idx >> 2, c8 = (idx & 3) * 8;
            size_t go = (size_t)(m0 + row) * D_ + k0 + c8;
            *(uint4*)&sA[0][row * PADK + c8] = *(const uint4*)(Ahi + go);
            *(uint4*)&sA[1][row * PADK + c8] = *(const uint4*)(Alo + go);
        }
        {
            int row = t >> 2, c8 = (t & 3) * 8;
            size_t go = (size_t)(n0 + row) * D_ + k0 + c8;
            *(uint4*)&sB[0][row * PADK + c8] = *(const uint4*)(Bhi + go);
            *(uint4*)&sB[1][row * PADK + c8] = *(const uint4*)(Blo + go);
        }
        __syncthreads();
#pragma unroll
        for (int ks = 0; ks < BK; ks += 16) {
            uint32_t ah[2][4], al[2][4], bh[2][4], bl[2][4];
#pragma unroll
            for (int mi = 0; mi < 2; mi++) {
                int ar = wm * 32 + mi * 16 + (lane & 15);
                int ac = ks + ((lane >> 4) << 3);
                ldsm4(ah[mi], smem_u32(&sA[0][ar * PADK + ac]));
                ldsm4(al[mi], smem_u32(&sA[1][ar * PADK + ac]));
            }
#pragma unroll
            for (int p = 0; p < 2; p++) {
                int br = wn * 32 + p * 16 + (lane & 7) + ((lane & 16) ? 8 : 0);
                int bc = ks + ((lane & 8) ? 8 : 0);
                ldsm4(bh[p], smem_u32(&sB[0][br * PADK + bc]));
                ldsm4(bl[p], smem_u32(&sB[1][br * PADK + bc]));
            }
#pragma unroll
            for (int mi = 0; mi < 2; mi++)
#pragma unroll
                for (int nj = 0; nj < 4; nj++) {
                    const uint32_t* fbh = &bh[nj >> 1][(nj & 1) * 2];
                    const uint32_t* fbl = &bl[nj >> 1][(nj & 1) * 2];
                    mma16816(acc[mi][nj], ah[mi], fbh);
                    mma16816(acc[mi][nj], ah[mi], fbl);
                    mma16816(acc[mi][nj], al[mi], fbh);
                }
        }
    }

    // Epilogue
    int head = blockIdx.x;
    float e = (which == 1 || which == 2) ? exps[head] : 0.f;
    float* qkv = (which == 0) ? g_q : (which == 1) ? g_k : g_v;
#pragma unroll
    for (int mi = 0; mi < 2; mi++)
#pragma unroll
        for (int nj = 0; nj < 4; nj++)
#pragma unroll
            for (int h2 = 0; h2 < 2; h2++) {
                int m = m0 + wm * 32 + mi * 16 + (lane >> 2) + h2 * 8;
                int nc = wn * 32 + nj * 8 + (lane & 3) * 2;
                float v0 = acc[mi][nj][h2 * 2];
                float v1 = acc[mi][nj][h2 * 2 + 1];
                if (which < 3) {
                    if (which != 0) {
                        float mg0 = fmaxf(fabsf(v0), 1e-8f);
                        float r0 = exp2f(e * log2f(mg0));
                        v0 = (v0 > 0.f) ? r0 : (v0 < 0.f ? -r0 : 0.f);
                        float mg1 = fmaxf(fabsf(v1), 1e-8f);
                        float r1 = exp2f(e * log2f(mg1));
                        v1 = (v1 > 0.f) ? r1 : (v1 < 0.f ? -r1 : 0.f);
                    }
                    int b = m >> 11, s = m & (S_ - 1);
                    float* dst = qkv + (((size_t)b * H_ + head) * S_ + s) * DH_ + nc;
                    *(float2*)dst = make_float2(v0, v1);
                } else {
                    size_t off = (size_t)m * D_ + n0 + nc;
                    float2 xr = *(const float2*)(x + off);
                    *(float2*)(y + off) = make_float2(xr.x + v0, xr.y + v1);
                }
            }
}

// ---------------------------------------------------------------------------
// 4) Flash attention (fp32 SIMT; epilogue -> hi/lo bf16)
// ---------------------------------------------------------------------------
__global__ __launch_bounds__(256) void attn_kernel(const float* __restrict__ phase,
                                                   const float* __restrict__ cph,
                                                   const float* __restrict__ bal) {
    extern __shared__ __align__(16) float sm[];
    float* QsT = sm;
    float* KsT = QsT + 64 * 68;
    float* Vs  = KsT + 64 * 68;
    float* Ps  = Vs  + 64 * 68;
    float* lk  = Ps  + 64 * 68;

    int bh = blockIdx.y, b = bh >> 4, h = bh & 15;
    int qt = blockIdx.x, s0 = qt * 64;
    int t = threadIdx.x, tx = t & 15, ty = t >> 4;

    float bv  = bal[0];
    float tau = fminf(fmaxf(1.0f / (2.0f * bv + 1e-8f), 0.1f), 10.0f);
    float itau = 1.0f / tau;
    float qsc  = 0.125f * itau;
    float cp   = cph[h];

    const float* qg = g_q + ((size_t)bh * S_ + s0) * DH_;
    {
        int r = t >> 2, c0 = (t & 3) * 4;
#pragma unroll
        for (int cc = 0; cc < 4; cc++) {
            int c = cc * 16 + c0;
            float4 f = *(const float4*)(qg + (size_t)r * DH_ + c);
            QsT[(c + 0) * 68 + r] = f.x; QsT[(c + 1) * 68 + r] = f.y;
            QsT[(c + 2) * 68 + r] = f.z; QsT[(c + 3) * 68 + r] = f.w;
        }
    }

    float acc[4][4] = {};
    float mrow[4], lrow[4];
#pragma unroll
    for (int i = 0; i < 4; i++) { mrow[i] = -1e30f; lrow[i] = 0.f; }

    for (int kt = 0; kt <= qt; kt++) {
        int kb = kt * 64;
        __syncthreads();
        const float* kg = g_k + ((size_t)bh * S_ + kb) * DH_;
        const float* vg = g_v + ((size_t)bh * S_ + kb) * DH_;
        {
            int r = t >> 2, c0 = (t & 3) * 4;
#pragma unroll
            for (int cc = 0; cc < 4; cc++) {
                int c = cc * 16 + c0;
                float4 f = *(const float4*)(kg + (size_t)r * DH_ + c);
                KsT[(c + 0) * 68 + r] = f.x; KsT[(c + 1) * 68 + r] = f.y;
                KsT[(c + 2) * 68 + r] = f.z; KsT[(c + 3) * 68 + r] = f.w;
                float4 g2 = *(const float4*)(vg + (size_t)r * DH_ + c);
                *(float4*)&Vs[r * 68 + c] = g2;
            }
        }
        if (t < 64) {
            float ph = phase[(size_t)b * S_ + kb + t];
            float c = cosf((ph - cp) * 0.5f);
            lk[t] = logf(c * c + 1e-6f) * itau;
        }
        __syncthreads();

        float sreg[4][4] = {};
#pragma unroll 16
        for (int dd = 0; dd < 64; dd++) {
            float4 af = *(const float4*)&QsT[dd * 68 + ty * 4];
            float4 bf = *(const float4*)&KsT[dd * 68 + tx * 4];
            float aa[4] = {af.x, af.y, af.z, af.w};
            float bb[4] = {bf.x, bf.y, bf.z, bf.w};
#pragma unroll
            for (int i = 0; i < 4; i++)
#pragma unroll
                for (int j = 0; j < 4; j++) sreg[i][j] += aa[i] * bb[j];
        }

        float lkj[4];
#pragma unroll
        for (int j = 0; j < 4; j++) lkj[j] = lk[tx * 4 + j];
        bool diag = (kt == qt);
#pragma unroll
        for (int i = 0; i < 4; i++) {
            int qrow = ty * 4 + i;
#pragma unroll
            for (int j = 0; j < 4; j++) {
                float sc = sreg[i][j] * qsc + lkj[j];
                if (diag && (tx * 4 + j) > qrow) sc = -1e30f;
                sreg[i][j] = sc;
            }
        }

#pragma unroll
        for (int i = 0; i < 4; i++) {
            float rm = fmaxf(fmaxf(sreg[i][0], sreg[i][1]),
                             fmaxf(sreg[i][2], sreg[i][3]));
#pragma unroll
            for (int o = 8; o; o >>= 1) rm = fmaxf(rm, __shfl_xor_sync(0xffffffffu, rm, o));
            float mn = fmaxf(mrow[i], rm);
            float al = __expf(mrow[i] - mn);
            float rs = 0.f;
#pragma unroll
            for (int j = 0; j < 4; j++) {
                float p = __expf(sreg[i][j] - mn);
                sreg[i][j] = p; rs += p;
            }
#pragma unroll
            for (int o = 8; o; o >>= 1) rs += __shfl_xor_sync(0xffffffffu, rs, o);
            lrow[i] = lrow[i] * al + rs;
            mrow[i] = mn;
#pragma unroll
            for (int j = 0; j < 4; j++) acc[i][j] *= al;
        }

#pragma unroll
        for (int i = 0; i < 4; i++)
            *(float4*)&Ps[(ty * 4 + i) * 68 + tx * 4] =
                make_float4(sreg[i][0], sreg[i][1], sreg[i][2], sreg[i][3]);
        __syncthreads();

#pragma unroll 4
        for (int kk = 0; kk < 64; kk += 4) {
            float4 pr[4];
#pragma unroll
            for (int i = 0; i < 4; i++)
                pr[i] = *(const float4*)&Ps[(ty * 4 + i) * 68 + kk];
#pragma unroll
            for (int u = 0; u < 4; u++) {
                float4 vf = *(const float4*)&Vs[(kk + u) * 68 + tx * 4];
                float vb4[4] = {vf.x, vf.y, vf.z, vf.w};
                float pu[4] = {
                    (u == 0) ? pr[0].x : (u == 1) ? pr[0].y : (u == 2) ? pr[0].z : pr[0].w,
                    (u == 0) ? pr[1].x : (u == 1) ? pr[1].y : (u == 2) ? pr[1].z : pr[1].w,
                    (u == 0) ? pr[2].x : (u == 1) ? pr[2].y : (u == 2) ? pr[2].z : pr[2].w,
                    (u == 0) ? pr[3].x : (u == 1) ? pr[3].y : (u == 2) ? pr[3].z : pr[3].w};
#pragma unroll
                for (int i = 0; i < 4; i++)
#pragma unroll
                    for (int j = 0; j < 4; j++) acc[i][j] += pu[i] * vb4[j];
            }
        }
    }

#pragma unroll
    for (int i = 0; i < 4; i++) {
        int srow = s0 + ty * 4 + i;
        float ph = phase[(size_t)b * S_ + srow];
        float cq = cosf((ph - cp) * 0.5f);
        float g = (cq * cq) / lrow[i];
        size_t off = ((size_t)b * S_ + srow) * D_ + h * DH_ + tx * 4;
#pragma unroll
        for (int j = 0; j < 4; j++) {
            float ov = acc[i][j] * g;
            __nv_bfloat16 hb = __float2bfloat16(ov);
            g_ao_hi[off + j] = hb;
            g_ao_lo[off + j] = __float2bfloat16(ov - __bfloat162float(hb));
        }
    }
}

// ---------------------------------------------------------------------------
extern "C" void kernel_launch(void* const* d_in, const int* in_sizes, int n_in,
                              void* d_out, int out_size) {
    const float* x     = (const float*)d_in[0];
    const float* phase = (const float*)d_in[1];
    const float* Wq    = (const float*)d_in[2];
    const float* Wk    = (const float*)d_in[3];
    const float* Wv    = (const float*)d_in[4];
    const float* Wo    = (const float*)d_in[5];
    const float* gamma = (const float*)d_in[6];
    const float* beta  = (const float*)d_in[7];
    const float* exps  = (const float*)d_in[8];
    const float* cph   = (const float*)d_in[9];
    const float* bal   = (const float*)d_in[10];
    float* y = (float*)d_out;

    static __nv_bfloat16 *wthi[4], *wtlo[4];
    static __nv_bfloat16 *hhi, *hlo, *aohi, *aolo;
    static bool got = false;
    if (!got) {
        cudaGetSymbolAddress((void**)&wthi[0], g_wt_hi);
        cudaGetSymbolAddress((void**)&wtlo[0], g_wt_lo);
        for (int i = 1; i < 4; i++) {
            wthi[i] = wthi[0] + (size_t)i * D_ * D_;
            wtlo[i] = wtlo[0] + (size_t)i * D_ * D_;
        }
        cudaGetSymbolAddress((void**)&hhi, g_h_hi);
        cudaGetSymbolAddress((void**)&hlo, g_h_lo);
        cudaGetSymbolAddress((void**)&aohi, g_ao_hi);
        cudaGetSymbolAddress((void**)&aolo, g_ao_lo);
        got = true;
    }

    ln_kernel<<<M_, 256>>>(x, gamma, beta);

    dim3 wg(32, 32);
    wconv_kernel<<<wg, dim3(32, 8)>>>(Wq, wthi[0], wtlo[0]);
    wconv_kernel<<<wg, dim3(32, 8)>>>(Wk, wthi[1], wtlo[1]);
    wconv_kernel<<<wg, dim3(32, 8)>>>(Wv, wthi[2], wtlo[2]);
    wconv_kernel<<<wg, dim3(32, 8)>>>(Wo, wthi[3], wtlo[3]);

    dim3 gg(D_ / 64, M_ / 128);
    gemm_mma_kernel<<<gg, 256>>>(hhi, hlo, wthi[0], wtlo[0], exps, x, y, 0);
    gemm_mma_kernel<<<gg, 256>>>(hhi, hlo, wthi[1], wtlo[1], exps, x, y, 1);
    gemm_mma_kernel<<<gg, 256>>>(hhi, hlo, wthi[2], wtlo[2], exps, x, y, 2);

    const int ATT_SMEM = (4 * 64 * 68 + 64) * (int)sizeof(float);
    cudaFuncSetAttribute((const void*)attn_kernel,
                         cudaFuncAttributeMaxDynamicSharedMemorySize, ATT_SMEM);
    attn_kernel<<<dim3(S_ / 64, B_ * H_), 256, ATT_SMEM>>>(phase, cph, bal);

    gemm_mma_kernel<<<gg, 256>>>(aohi, aolo, wthi[3], wtlo[3], exps, x, y, 3);
}

// round 10
// speedup vs baseline: 2.2448x; 1.5472x over previous
#include <cuda_runtime.h>
#include <cuda_bf16.h>
#include <cuda_fp16.h>
#include <math.h>
#include <stdint.h>

#define B_  2
#define S_  2048
#define D_  1024
#define H_  16
#define DH_ 64
#define M_  (B_*S_)

// ---------------------------------------------------------------------------
// Scratch
// ---------------------------------------------------------------------------
__device__ __nv_bfloat16 g_h_hi [M_*D_];
__device__ __nv_bfloat16 g_h_lo [M_*D_];
__device__ __nv_bfloat16 g_wt_hi[4][D_*D_];
__device__ __nv_bfloat16 g_wt_lo[4][D_*D_];
__device__ __nv_bfloat16 g_q_hi [M_*D_];   // (B,H,S,DH)
__device__ __nv_bfloat16 g_q_lo [M_*D_];
__device__ __nv_bfloat16 g_k_hi [M_*D_];
__device__ __nv_bfloat16 g_k_lo [M_*D_];
__device__ __half        g_v_hi [M_*D_];
__device__ __half        g_v_lo [M_*D_];
__device__ __nv_bfloat16 g_ao_hi[M_*D_];   // (B,S,D)
__device__ __nv_bfloat16 g_ao_lo[M_*D_];

// ---------------------------------------------------------------------------
// helpers
// ---------------------------------------------------------------------------
__device__ __forceinline__ uint32_t smem_u32(const void* p) {
    uint32_t a;
    asm("{ .reg .u64 t; cvta.to.shared.u64 t, %1; cvt.u32.u64 %0, t; }"
        : "=r"(a) : "l"(p));
    return a;
}
__device__ __forceinline__ void ldsm4(uint32_t* r, uint32_t addr) {
    asm volatile("ldmatrix.sync.aligned.m8n8.x4.shared.b16 {%0,%1,%2,%3}, [%4];"
                 : "=r"(r[0]), "=r"(r[1]), "=r"(r[2]), "=r"(r[3]) : "r"(addr));
}
__device__ __forceinline__ void ldsm4t(uint32_t* r, uint32_t addr) {
    asm volatile("ldmatrix.sync.aligned.m8n8.x4.trans.shared.b16 {%0,%1,%2,%3}, [%4];"
                 : "=r"(r[0]), "=r"(r[1]), "=r"(r[2]), "=r"(r[3]) : "r"(addr));
}
__device__ __forceinline__ void mma_bf(float* c, const uint32_t* a, const uint32_t* b) {
    asm volatile(
        "mma.sync.aligned.m16n8k16.row.col.f32.bf16.bf16.f32 "
        "{%0,%1,%2,%3}, {%4,%5,%6,%7}, {%8,%9}, {%0,%1,%2,%3};"
        : "+f"(c[0]), "+f"(c[1]), "+f"(c[2]), "+f"(c[3])
        : "r"(a[0]), "r"(a[1]), "r"(a[2]), "r"(a[3]), "r"(b[0]), "r"(b[1]));
}
__device__ __forceinline__ void mma_hf(float* c, const uint32_t* a, const uint32_t* b) {
    asm volatile(
        "mma.sync.aligned.m16n8k16.row.col.f32.f16.f16.f32 "
        "{%0,%1,%2,%3}, {%4,%5,%6,%7}, {%8,%9}, {%0,%1,%2,%3};"
        : "+f"(c[0]), "+f"(c[1]), "+f"(c[2]), "+f"(c[3])
        : "r"(a[0]), "r"(a[1]), "r"(a[2]), "r"(a[3]), "r"(b[0]), "r"(b[1]));
}
__device__ __forceinline__ void cpa16(uint32_t smaddr, const void* g) {
    asm volatile("cp.async.cg.shared.global [%0], [%1], 16;"
                 :: "r"(smaddr), "l"(__cvta_generic_to_global(g)));
}
#define CP_COMMIT() asm volatile("cp.async.commit_group;" ::: "memory")
#define CP_WAIT1()  asm volatile("cp.async.wait_group 1;" ::: "memory")
#define CP_WAIT0()  asm volatile("cp.async.wait_group 0;" ::: "memory")

__device__ __forceinline__ void packbf2(float x0, float x1, uint32_t& hi, uint32_t& lo) {
    asm("cvt.rn.bf16x2.f32 %0, %1, %2;" : "=r"(hi) : "f"(x1), "f"(x0));
    float h0 = __int_as_float(hi << 16);
    float h1 = __int_as_float(hi & 0xFFFF0000u);
    asm("cvt.rn.bf16x2.f32 %0, %1, %2;" : "=r"(lo) : "f"(x1 - h1), "f"(x0 - h0));
}
__device__ __forceinline__ void packhf2(float x0, float x1, uint32_t& hi, uint32_t& lo) {
    __half2 h = __floats2half2_rn(x0, x1);
    hi = *reinterpret_cast<uint32_t*>(&h);
    float2 hf = __half22float2(h);
    __half2 l = __floats2half2_rn(x0 - hf.x, x1 - hf.y);
    lo = *reinterpret_cast<uint32_t*>(&l);
}
__device__ __forceinline__ uint32_t packh(float x0, float x1) {
    __half2 h = __floats2half2_rn(x0, x1);
    return *reinterpret_cast<uint32_t*>(&h);
}
// exp2 on the fma pipe; valid for z <= 0 (clamped at -80)
__device__ __forceinline__ float exp2_fast(float z) {
    z = fmaxf(z, -80.f);
    float fm = z + 12582912.f;
    int i = __float_as_int(fm) - 0x4B400000;
    float f = z - (fm - 12582912.f);
    float p = 1.333356e-3f;
    p = fmaf(p, f, 9.618129e-3f);
    p = fmaf(p, f, 5.5504109e-2f);
    p = fmaf(p, f, 2.40226507e-1f);
    p = fmaf(p, f, 6.93147181e-1f);
    p = fmaf(p, f, 1.0f);
    return p * __int_as_float((i + 127) << 23);
}

// ---------------------------------------------------------------------------
// 1) LayerNorm -> hi/lo bf16
// ---------------------------------------------------------------------------
__global__ __launch_bounds__(256) void ln_kernel(const float* __restrict__ x,
                                                 const float* __restrict__ gamma,
                                                 const float* __restrict__ beta) {
    int row = blockIdx.x;
    const float* xr = x + (size_t)row * D_;
    float v[4];
    float s = 0.f, s2 = 0.f;
#pragma unroll
    for (int i = 0; i < 4; i++) {
        v[i] = xr[threadIdx.x + i * 256];
        s += v[i]; s2 += v[i] * v[i];
    }
#pragma unroll
    for (int o = 16; o; o >>= 1) {
        s  += __shfl_xor_sync(0xffffffffu, s,  o);
        s2 += __shfl_xor_sync(0xffffffffu, s2, o);
    }
    __shared__ float red[16];
    int w = threadIdx.x >> 5;
    if ((threadIdx.x & 31) == 0) { red[w] = s; red[w + 8] = s2; }
    __syncthreads();
    float ts = 0.f, ts2 = 0.f;
#pragma unroll
    for (int i = 0; i < 8; i++) { ts += red[i]; ts2 += red[i + 8]; }
    float mean = ts * (1.0f / D_);
    float var  = ts2 * (1.0f / D_) - mean * mean;
    float rstd = rsqrtf(var + 1e-5f);
#pragma unroll
    for (int i = 0; i < 4; i++) {
        int c = threadIdx.x + i * 256;
        float hv = (v[i] - mean) * rstd * gamma[c] + beta[c];
        __nv_bfloat16 hb = __float2bfloat16(hv);
        g_h_hi[(size_t)row * D_ + c] = hb;
        g_h_lo[(size_t)row * D_ + c] = __float2bfloat16(hv - __bfloat162float(hb));
    }
}

// ---------------------------------------------------------------------------
// 2) Weight transpose+convert
// ---------------------------------------------------------------------------
__global__ __launch_bounds__(256) void wconv_kernel(const float* __restrict__ W,
                                                    __nv_bfloat16* __restrict__ Thi,
                                                    __nv_bfloat16* __restrict__ Tlo) {
    __shared__ float tl[32][33];
    int n0 = blockIdx.x * 32, k0 = blockIdx.y * 32;
    int tx = threadIdx.x, ty = threadIdx.y;
#pragma unroll
    for (int j = 0; j < 4; j++)
        tl[ty + j * 8][tx] = W[(size_t)(k0 + ty + j * 8) * D_ + n0 + tx];
    __syncthreads();
#pragma unroll
    for (int j = 0; j < 4; j++) {
        int n = n0 + ty + j * 8;
        float v = tl[tx][ty + j * 8];
        __nv_bfloat16 hb = __float2bfloat16(v);
        Thi[(size_t)n * D_ + k0 + tx] = hb;
        Tlo[(size_t)n * D_ + k0 + tx] = __float2bfloat16(v - __bfloat162float(hb));
    }
}

// ---------------------------------------------------------------------------
// 3) HMMA GEMM (unchanged core; new epilogue formats)
// ---------------------------------------------------------------------------
#define BK   32
#define PADK 40

__global__ __launch_bounds__(256) void gemm_mma_kernel(
        const __nv_bfloat16* __restrict__ Ahi, const __nv_bfloat16* __restrict__ Alo,
        const __nv_bfloat16* __restrict__ Bhi, const __nv_bfloat16* __restrict__ Blo,
        const float* __restrict__ exps, const float* __restrict__ x,
        float* __restrict__ y, int which) {
    __shared__ __align__(16) __nv_bfloat16 sA[2][128 * PADK];
    __shared__ __align__(16) __nv_bfloat16 sB[2][64 * PADK];
    int t = threadIdx.x, lane = t & 31, wid = t >> 5;
    int wm = wid & 3, wn = wid >> 2;
    int m0 = blockIdx.y * 128, n0 = blockIdx.x * 64;
    float acc[2][4][4] = {};

    for (int kc = 0; kc < D_ / BK; kc++) {
        int k0 = kc * BK;
        __syncthreads();
#pragma unroll
        for (int i = 0; i < 2; i++) {
            int idx = t + i * 256;
            int row = idx >> 2, c8 = (idx & 3) * 8;
            size_t go = (size_t)(m0 + row) * D_ + k0 + c8;
            *(uint4*)&sA[0][row * PADK + c8] = *(const uint4*)(Ahi + go);
            *(uint4*)&sA[1][row * PADK + c8] = *(const uint4*)(Alo + go);
        }
        {
            int row = t >> 2, c8 = (t & 3) * 8;
            size_t go = (size_t)(n0 + row) * D_ + k0 + c8;
            *(uint4*)&sB[0][row * PADK + c8] = *(const uint4*)(Bhi + go);
            *(uint4*)&sB[1][row * PADK + c8] = *(const uint4*)(Blo + go);
        }
        __syncthreads();
#pragma unroll
        for (int ks = 0; ks < BK; ks += 16) {
            uint32_t ah[2][4], al[2][4], bh[2][4], bl[2][4];
#pragma unroll
            for (int mi = 0; mi < 2; mi++) {
                int ar = wm * 32 + mi * 16 + (lane & 15);
                int ac = ks + ((lane >> 4) << 3);
                ldsm4(ah[mi], smem_u32(&sA[0][ar * PADK + ac]));
                ldsm4(al[mi], smem_u32(&sA[1][ar * PADK + ac]));
            }
#pragma unroll
            for (int p = 0; p < 2; p++) {
                int br = wn * 32 + p * 16 + (lane & 7) + ((lane & 16) ? 8 : 0);
                int bc = ks + ((lane & 8) ? 8 : 0);
                ldsm4(bh[p], smem_u32(&sB[0][br * PADK + bc]));
                ldsm4(bl[p], smem_u32(&sB[1][br * PADK + bc]));
            }
#pragma unroll
            for (int mi = 0; mi < 2; mi++)
#pragma unroll
                for (int nj = 0; nj < 4; nj++) {
                    const uint32_t* fbh = &bh[nj >> 1][(nj & 1) * 2];
                    const uint32_t* fbl = &bl[nj >> 1][(nj & 1) * 2];
                    mma_bf(acc[mi][nj], ah[mi], fbh);
                    mma_bf(acc[mi][nj], ah[mi], fbl);
                    mma_bf(acc[mi][nj], al[mi], fbh);
                }
        }
    }

    int head = blockIdx.x;
    float e = (which == 1 || which == 2) ? exps[head] : 0.f;
#pragma unroll
    for (int mi = 0; mi < 2; mi++)
#pragma unroll
        for (int nj = 0; nj < 4; nj++)
#pragma unroll
            for (int h2 = 0; h2 < 2; h2++) {
                int m = m0 + wm * 32 + mi * 16 + (lane >> 2) + h2 * 8;
                int nc = wn * 32 + nj * 8 + (lane & 3) * 2;
                float v0 = acc[mi][nj][h2 * 2];
                float v1 = acc[mi][nj][h2 * 2 + 1];
                if (which < 3) {
                    if (which != 0) {
                        float mg0 = fmaxf(fabsf(v0), 1e-8f);
                        float r0 = exp2f(e * log2f(mg0));
                        v0 = (v0 > 0.f) ? r0 : (v0 < 0.f ? -r0 : 0.f);
                        float mg1 = fmaxf(fabsf(v1), 1e-8f);
                        float r1 = exp2f(e * log2f(mg1));
                        v1 = (v1 > 0.f) ? r1 : (v1 < 0.f ? -r1 : 0.f);
                    }
                    int b = m >> 11, s = m & (S_ - 1);
                    size_t off = (((size_t)b * H_ + head) * S_ + s) * DH_ + nc;
                    uint32_t hi, lo;
                    if (which == 2) {
                        packhf2(v0, v1, hi, lo);
                        *(uint32_t*)&g_v_hi[off] = hi;
                        *(uint32_t*)&g_v_lo[off] = lo;
                    } else if (which == 1) {
                        packbf2(v0, v1, hi, lo);
                        *(uint32_t*)&g_k_hi[off] = hi;
                        *(uint32_t*)&g_k_lo[off] = lo;
                    } else {
                        packbf2(v0, v1, hi, lo);
                        *(uint32_t*)&g_q_hi[off] = hi;
                        *(uint32_t*)&g_q_lo[off] = lo;
                    }
                } else {
                    size_t off = (size_t)m * D_ + n0 + nc;
                    float2 xr = *(const float2*)(x + off);
                    *(float2*)(y + off) = make_float2(xr.x + v0, xr.y + v1);
                }
            }
}

// ---------------------------------------------------------------------------
// 4) HMMA flash attention: 128 q-rows/CTA, 64-key tiles, cp.async 2-stage
// ---------------------------------------------------------------------------
#define APAD_B 144          // bytes per smem row (72 halfs)
#define A_KH 0
#define A_KL 9216
#define A_VH 18432
#define A_VL 27648
#define ABUF 36864
#define A_LK 73728
#define ATT_SMEM (73728 + 512)

__global__ __launch_bounds__(256) void attn_kernel(const float* __restrict__ phase,
                                                   const float* __restrict__ cph,
                                                   const float* __restrict__ bal) {
    extern __shared__ __align__(128) char asmem[];
    uint32_t sb = smem_u32(asmem);
    float* lk2 = (float*)(asmem + A_LK);

    int t = threadIdx.x, lane = t & 31, w = t >> 5;
    int bh = blockIdx.y, b = bh >> 4, h = bh & 15;
    int qt = blockIdx.x, m0 = qt * 128;
    int wr0 = m0 + w * 16;
    int r = lane >> 2, c = lane & 3;
    int nkt = 2 * qt + 2;

    float bv  = bal[0];
    float tau = fminf(fmaxf(1.0f / (2.0f * bv + 1e-8f), 0.1f), 10.0f);
    float itau = 1.0f / tau;
    float qscl = 0.125f * itau * 1.44269504f;
    float cp   = cph[h];

    // Q fragments (hi/lo) straight from global
    uint32_t qh[4][4], ql[4][4];
    {
        const __nv_bfloat16* qhp = g_q_hi + ((size_t)bh * S_ + wr0) * DH_;
        const __nv_bfloat16* qlp = g_q_lo + ((size_t)bh * S_ + wr0) * DH_;
#pragma unroll
        for (int ks = 0; ks < 4; ks++) {
            int k0 = ks * 16 + 2 * c;
            qh[ks][0] = *(const uint32_t*)(qhp + (size_t)r * DH_ + k0);
            qh[ks][1] = *(const uint32_t*)(qhp + (size_t)(r + 8) * DH_ + k0);
            qh[ks][2] = *(const uint32_t*)(qhp + (size_t)r * DH_ + k0 + 8);
            qh[ks][3] = *(const uint32_t*)(qhp + (size_t)(r + 8) * DH_ + k0 + 8);
            ql[ks][0] = *(const uint32_t*)(qlp + (size_t)r * DH_ + k0);
            ql[ks][1] = *(const uint32_t*)(qlp + (size_t)(r + 8) * DH_ + k0);
            ql[ks][2] = *(const uint32_t*)(qlp + (size_t)r * DH_ + k0 + 8);
            ql[ks][3] = *(const uint32_t*)(qlp + (size_t)(r + 8) * DH_ + k0 + 8);
        }
    }

    float o[8][4] = {};
    float mx[2] = {-1e30f, -1e30f}, lsum[2] = {0.f, 0.f};

#define LOAD_TILE(kt_, buf_) do {                                              \
    int kb_ = (kt_) * 64;                                                      \
    uint32_t bo_ = sb + (buf_) * ABUF;                                         \
    size_t gb_ = ((size_t)bh * S_ + kb_) * DH_;                                \
    _Pragma("unroll")                                                          \
    for (int i_ = 0; i_ < 2; i_++) {                                           \
        int idx_ = t + i_ * 256;                                               \
        int row_ = idx_ >> 3, seg_ = idx_ & 7;                                 \
        uint32_t d_ = bo_ + row_ * APAD_B + seg_ * 16;                         \
        size_t go_ = gb_ + (size_t)row_ * DH_ + seg_ * 8;                      \
        cpa16(d_ + A_KH, g_k_hi + go_);                                        \
        cpa16(d_ + A_KL, g_k_lo + go_);                                        \
        cpa16(d_ + A_VH, g_v_hi + go_);                                        \
        cpa16(d_ + A_VL, g_v_lo + go_);                                        \
    }                                                                          \
} while (0)

    LOAD_TILE(0, 0);
    CP_COMMIT();

    for (int kt = 0; kt < nkt; kt++) {
        int kb = kt * 64;
        if (kt + 1 < nkt) { LOAD_TILE(kt + 1, (kt + 1) & 1); CP_COMMIT(); }
        if (t < 64) {
            float ph = phase[(size_t)b * S_ + kb + t];
            float cc = cosf((ph - cp) * 0.5f);
            lk2[(kt & 1) * 64 + t] = log2f(cc * cc + 1e-6f) * itau;
        }
        if (kt + 1 < nkt) { CP_WAIT1(); } else { CP_WAIT0(); }
        __syncthreads();

        if (kb <= wr0 + 15) {
            uint32_t bo = sb + (kt & 1) * ABUF;
            float s[8][4];
#pragma unroll
            for (int nj = 0; nj < 8; nj++)
                s[nj][0] = s[nj][1] = s[nj][2] = s[nj][3] = 0.f;
#pragma unroll
            for (int ks = 0; ks < 4; ks++)
#pragma unroll
                for (int ng = 0; ng < 4; ng++) {
                    uint32_t kh4[4], kl4[4];
                    int srow = ng * 16 + (lane & 7) + ((lane & 16) ? 8 : 0);
                    int scol = ks * 16 + ((lane & 8) ? 8 : 0);
                    ldsm4(kh4, bo + A_KH + srow * APAD_B + scol * 2);
                    ldsm4(kl4, bo + A_KL + srow * APAD_B + scol * 2);
                    mma_bf(s[2 * ng], qh[ks], &kh4[0]);
                    mma_bf(s[2 * ng], qh[ks], &kl4[0]);
                    mma_bf(s[2 * ng], ql[ks], &kh4[0]);
                    mma_bf(s[2 * ng + 1], qh[ks], &kh4[2]);
                    mma_bf(s[2 * ng + 1], qh[ks], &kl4[2]);
                    mma_bf(s[2 * ng + 1], ql[ks], &kh4[2]);
                }

            // log2-domain scores + causal mask + tile max
            bool needmask = (kb + 63 > wr0);
            const float* lkp = &lk2[(kt & 1) * 64];
            float tmax[2] = {-1e30f, -1e30f};
#pragma unroll
            for (int nj = 0; nj < 8; nj++) {
                int key0 = kb + nj * 8 + 2 * c;
                float l0 = lkp[nj * 8 + 2 * c], l1 = lkp[nj * 8 + 2 * c + 1];
#pragma unroll
                for (int e = 0; e < 4; e++) {
                    float z = s[nj][e] * qscl + ((e & 1) ? l1 : l0);
                    if (needmask) {
                        int qrow = wr0 + r + ((e >> 1) ? 8 : 0);
                        if (key0 + (e & 1) > qrow) z = -1e30f;
                    }
                    s[nj][e] = z;
                    int half = e >> 1;
                    tmax[half] = fmaxf(tmax[half], z);
                }
            }
#pragma unroll
            for (int i = 0; i < 2; i++) {
                tmax[i] = fmaxf(tmax[i], __shfl_xor_sync(0xffffffffu, tmax[i], 1));
                tmax[i] = fmaxf(tmax[i], __shfl_xor_sync(0xffffffffu, tmax[i], 2));
            }
            float alpha[2], rsum[2] = {0.f, 0.f};
#pragma unroll
            for (int i = 0; i < 2; i++) {
                float mn = fmaxf(mx[i], tmax[i]);
                alpha[i] = exp2_fast(mx[i] - mn);
                mx[i] = mn;
            }
#pragma unroll
            for (int nj = 0; nj < 8; nj++)
#pragma unroll
                for (int e = 0; e < 4; e++) {
                    int half = e >> 1;
                    float p = exp2_fast(s[nj][e] - mx[half]);
                    s[nj][e] = p;
                    rsum[half] += p;
                }
#pragma unroll
            for (int i = 0; i < 2; i++) {
                rsum[i] += __shfl_xor_sync(0xffffffffu, rsum[i], 1);
                rsum[i] += __shfl_xor_sync(0xffffffffu, rsum[i], 2);
                lsum[i] = lsum[i] * alpha[i] + rsum[i];
            }
#pragma unroll
            for (int nj = 0; nj < 8; nj++) {
                o[nj][0] *= alpha[0]; o[nj][1] *= alpha[0];
                o[nj][2] *= alpha[1]; o[nj][3] *= alpha[1];
            }
            // pack P to fp16 A-fragments
            uint32_t pa[4][4];
#pragma unroll
            for (int ks = 0; ks < 4; ks++) {
                pa[ks][0] = packh(s[2 * ks][0], s[2 * ks][1]);
                pa[ks][1] = packh(s[2 * ks][2], s[2 * ks][3]);
                pa[ks][2] = packh(s[2 * ks + 1][0], s[2 * ks + 1][1]);
                pa[ks][3] = packh(s[2 * ks + 1][2], s[2 * ks + 1][3]);
            }
            // O += P @ V (V via trans ldmatrix from [key][dh])
#pragma unroll
            for (int ng = 0; ng < 4; ng++)
#pragma unroll
                for (int ks = 0; ks < 4; ks++) {
                    uint32_t vh4[4], vl4[4];
                    int srow = ks * 16 + (lane & 7) + ((lane & 8) ? 8 : 0);
                    int scol = ng * 16 + ((lane & 16) ? 8 : 0);
                    ldsm4t(vh4, bo + A_VH + srow * APAD_B + scol * 2);
                    ldsm4t(vl4, bo + A_VL + srow * APAD_B + scol * 2);
                    mma_hf(o[2 * ng],     pa[ks], &vh4[0]);
                    mma_hf(o[2 * ng],     pa[ks], &vl4[0]);
                    mma_hf(o[2 * ng + 1], pa[ks], &vh4[2]);
                    mma_hf(o[2 * ng + 1], pa[ks], &vl4[2]);
                }
        }
        __syncthreads();
    }

    // epilogue: gate by T_q / l, write bf16 hi/lo (B,S,D)
    float g[2];
#pragma unroll
    for (int i = 0; i < 2; i++) {
        int srow = wr0 + r + i * 8;
        float ph = phase[(size_t)b * S_ + srow];
        float cq = cosf((ph - cp) * 0.5f);
        g[i] = (cq * cq) / lsum[i];
    }
#pragma unroll
    for (int nj = 0; nj < 8; nj++)
#pragma unroll
        for (int i = 0; i < 2; i++) {
            int srow = wr0 + r + i * 8;
            size_t off = ((size_t)b * S_ + srow) * D_ + h * DH_ + nj * 8 + 2 * c;
            uint32_t hi, lo;
            packbf2(o[nj][i * 2] * g[i], o[nj][i * 2 + 1] * g[i], hi, lo);
            *(uint32_t*)&g_ao_hi[off] = hi;
            *(uint32_t*)&g_ao_lo[off] = lo;
        }
}

// ---------------------------------------------------------------------------
extern "C" void kernel_launch(void* const* d_in, const int* in_sizes, int n_in,
                              void* d_out, int out_size) {
    const float* x     = (const float*)d_in[0];
    const float* phase = (const float*)d_in[1];
    const float* Wq    = (const float*)d_in[2];
    const float* Wk    = (const float*)d_in[3];
    const float* Wv    = (const float*)d_in[4];
    const float* Wo    = (const float*)d_in[5];
    const float* gamma = (const float*)d_in[6];
    const float* beta  = (const float*)d_in[7];
    const float* exps  = (const float*)d_in[8];
    const float* cph   = (const float*)d_in[9];
    const float* bal   = (const float*)d_in[10];
    float* y = (float*)d_out;

    static __nv_bfloat16 *wthi[4], *wtlo[4];
    static __nv_bfloat16 *hhi, *hlo, *aohi, *aolo;
    static bool got = false;
    if (!got) {
        cudaGetSymbolAddress((void**)&wthi[0], g_wt_hi);
        cudaGetSymbolAddress((void**)&wtlo[0], g_wt_lo);
        for (int i = 1; i < 4; i++) {
            wthi[i] = wthi[0] + (size_t)i * D_ * D_;
            wtlo[i] = wtlo[0] + (size_t)i * D_ * D_;
        }
        cudaGetSymbolAddress((void**)&hhi, g_h_hi);
        cudaGetSymbolAddress((void**)&hlo, g_h_lo);
        cudaGetSymbolAddress((void**)&aohi, g_ao_hi);
        cudaGetSymbolAddress((void**)&aolo, g_ao_lo);
        cudaFuncSetAttribute((const void*)attn_kernel,
                             cudaFuncAttributeMaxDynamicSharedMemorySize, ATT_SMEM);
        got = true;
    }

    ln_kernel<<<M_, 256>>>(x, gamma, beta);

    dim3 wg(32, 32);
    wconv_kernel<<<wg, dim3(32, 8)>>>(Wq, wthi[0], wtlo[0]);
    wconv_kernel<<<wg, dim3(32, 8)>>>(Wk, wthi[1], wtlo[1]);
    wconv_kernel<<<wg, dim3(32, 8)>>>(Wv, wthi[2], wtlo[2]);
    wconv_kernel<<<wg, dim3(32, 8)>>>(Wo, wthi[3], wtlo[3]);

    dim3 gg(D_ / 64, M_ / 128);
    gemm_mma_kernel<<<gg, 256>>>(hhi, hlo, wthi[0], wtlo[0], exps, x, y, 0);
    gemm_mma_kernel<<<gg, 256>>>(hhi, hlo, wthi[1], wtlo[1], exps, x, y, 1);
    gemm_mma_kernel<<<gg, 256>>>(hhi, hlo, wthi[2], wtlo[2], exps, x, y, 2);

    attn_kernel<<<dim3(S_ / 128, B_ * H_), 256, ATT_SMEM>>>(phase, cph, bal);

    gemm_mma_kernel<<<gg, 256>>>(aohi, aolo, wthi[3], wtlo[3], exps, x, y, 3);
}

// round 11
// speedup vs baseline: 2.5597x; 1.1403x over previous
#include <cuda_runtime.h>
#include <cuda_bf16.h>
#include <cuda_fp16.h>
#include <math.h>
#include <stdint.h>

#define B_  2
#define S_  2048
#define D_  1024
#define H_  16
#define DH_ 64
#define M_  (B_*S_)

// ---------------------------------------------------------------------------
// Scratch
// ---------------------------------------------------------------------------
__device__ __nv_bfloat16 g_h_hi [M_*D_];
__device__ __nv_bfloat16 g_h_lo [M_*D_];
__device__ __nv_bfloat16 g_wt_hi[4][D_*D_];
__device__ __nv_bfloat16 g_wt_lo[4][D_*D_];
__device__ __nv_bfloat16 g_q_hi [M_*D_];   // (B,H,S,DH)
__device__ __nv_bfloat16 g_q_lo [M_*D_];
__device__ __nv_bfloat16 g_k_hi [M_*D_];
__device__ __nv_bfloat16 g_k_lo [M_*D_];
__device__ __half        g_v_hi [M_*D_];
__device__ __half        g_v_lo [M_*D_];
__device__ __nv_bfloat16 g_ao_hi[M_*D_];   // (B,S,D)
__device__ __nv_bfloat16 g_ao_lo[M_*D_];

// ---------------------------------------------------------------------------
// helpers
// ---------------------------------------------------------------------------
__device__ __forceinline__ uint32_t smem_u32(const void* p) {
    uint32_t a;
    asm("{ .reg .u64 t; cvta.to.shared.u64 t, %1; cvt.u32.u64 %0, t; }"
        : "=r"(a) : "l"(p));
    return a;
}
__device__ __forceinline__ void ldsm4(uint32_t* r, uint32_t addr) {
    asm volatile("ldmatrix.sync.aligned.m8n8.x4.shared.b16 {%0,%1,%2,%3}, [%4];"
                 : "=r"(r[0]), "=r"(r[1]), "=r"(r[2]), "=r"(r[3]) : "r"(addr));
}
__device__ __forceinline__ void ldsm4t(uint32_t* r, uint32_t addr) {
    asm volatile("ldmatrix.sync.aligned.m8n8.x4.trans.shared.b16 {%0,%1,%2,%3}, [%4];"
                 : "=r"(r[0]), "=r"(r[1]), "=r"(r[2]), "=r"(r[3]) : "r"(addr));
}
__device__ __forceinline__ void mma_bf(float* c, const uint32_t* a, const uint32_t* b) {
    asm volatile(
        "mma.sync.aligned.m16n8k16.row.col.f32.bf16.bf16.f32 "
        "{%0,%1,%2,%3}, {%4,%5,%6,%7}, {%8,%9}, {%0,%1,%2,%3};"
        : "+f"(c[0]), "+f"(c[1]), "+f"(c[2]), "+f"(c[3])
        : "r"(a[0]), "r"(a[1]), "r"(a[2]), "r"(a[3]), "r"(b[0]), "r"(b[1]));
}
__device__ __forceinline__ void mma_hf(float* c, const uint32_t* a, const uint32_t* b) {
    asm volatile(
        "mma.sync.aligned.m16n8k16.row.col.f32.f16.f16.f32 "
        "{%0,%1,%2,%3}, {%4,%5,%6,%7}, {%8,%9}, {%0,%1,%2,%3};"
        : "+f"(c[0]), "+f"(c[1]), "+f"(c[2]), "+f"(c[3])
        : "r"(a[0]), "r"(a[1]), "r"(a[2]), "r"(a[3]), "r"(b[0]), "r"(b[1]));
}
__device__ __forceinline__ void cpa16(uint32_t smaddr, const void* g) {
    asm volatile("cp.async.cg.shared.global [%0], [%1], 16;"
                 :: "r"(smaddr), "l"(__cvta_generic_to_global(g)));
}
#define CP_COMMIT() asm volatile("cp.async.commit_group;" ::: "memory")
#define CP_WAIT1()  asm volatile("cp.async.wait_group 1;" ::: "memory")
#define CP_WAIT0()  asm volatile("cp.async.wait_group 0;" ::: "memory")

__device__ __forceinline__ void packbf2(float x0, float x1, uint32_t& hi, uint32_t& lo) {
    asm("cvt.rn.bf16x2.f32 %0, %1, %2;" : "=r"(hi) : "f"(x1), "f"(x0));
    float h0 = __int_as_float(hi << 16);
    float h1 = __int_as_float(hi & 0xFFFF0000u);
    asm("cvt.rn.bf16x2.f32 %0, %1, %2;" : "=r"(lo) : "f"(x1 - h1), "f"(x0 - h0));
}
__device__ __forceinline__ void packhf2(float x0, float x1, uint32_t& hi, uint32_t& lo) {
    __half2 h = __floats2half2_rn(x0, x1);
    hi = *reinterpret_cast<uint32_t*>(&h);
    float2 hf = __half22float2(h);
    __half2 l = __floats2half2_rn(x0 - hf.x, x1 - hf.y);
    lo = *reinterpret_cast<uint32_t*>(&l);
}
__device__ __forceinline__ uint32_t packh(float x0, float x1) {
    __half2 h = __floats2half2_rn(x0, x1);
    return *reinterpret_cast<uint32_t*>(&h);
}
// exp2 on the fma pipe; valid for z <= 0 (clamped at -80)
__device__ __forceinline__ float exp2_fast(float z) {
    z = fmaxf(z, -80.f);
    float fm = z + 12582912.f;
    int i = __float_as_int(fm) - 0x4B400000;
    float f = z - (fm - 12582912.f);
    float p = 1.333356e-3f;
    p = fmaf(p, f, 9.618129e-3f);
    p = fmaf(p, f, 5.5504109e-2f);
    p = fmaf(p, f, 2.40226507e-1f);
    p = fmaf(p, f, 6.93147181e-1f);
    p = fmaf(p, f, 1.0f);
    return p * __int_as_float((i + 127) << 23);
}

// ---------------------------------------------------------------------------
// 1) LayerNorm -> hi/lo bf16
// ---------------------------------------------------------------------------
__global__ __launch_bounds__(256) void ln_kernel(const float* __restrict__ x,
                                                 const float* __restrict__ gamma,
                                                 const float* __restrict__ beta) {
    int row = blockIdx.x;
    const float* xr = x + (size_t)row * D_;
    float v[4];
    float s = 0.f, s2 = 0.f;
#pragma unroll
    for (int i = 0; i < 4; i++) {
        v[i] = xr[threadIdx.x + i * 256];
        s += v[i]; s2 += v[i] * v[i];
    }
#pragma unroll
    for (int o = 16; o; o >>= 1) {
        s  += __shfl_xor_sync(0xffffffffu, s,  o);
        s2 += __shfl_xor_sync(0xffffffffu, s2, o);
    }
    __shared__ float red[16];
    int w = threadIdx.x >> 5;
    if ((threadIdx.x & 31) == 0) { red[w] = s; red[w + 8] = s2; }
    __syncthreads();
    float ts = 0.f, ts2 = 0.f;
#pragma unroll
    for (int i = 0; i < 8; i++) { ts += red[i]; ts2 += red[i + 8]; }
    float mean = ts * (1.0f / D_);
    float var  = ts2 * (1.0f / D_) - mean * mean;
    float rstd = rsqrtf(var + 1e-5f);
#pragma unroll
    for (int i = 0; i < 4; i++) {
        int c = threadIdx.x + i * 256;
        float hv = (v[i] - mean) * rstd * gamma[c] + beta[c];
        __nv_bfloat16 hb = __float2bfloat16(hv);
        g_h_hi[(size_t)row * D_ + c] = hb;
        g_h_lo[(size_t)row * D_ + c] = __float2bfloat16(hv - __bfloat162float(hb));
    }
}

// ---------------------------------------------------------------------------
// 2) Weight transpose+convert (all 4 weights, blockIdx.z selects)
// ---------------------------------------------------------------------------
__global__ __launch_bounds__(256) void wconv_kernel(const float* __restrict__ W0,
                                                    const float* __restrict__ W1,
                                                    const float* __restrict__ W2,
                                                    const float* __restrict__ W3) {
    __shared__ float tl[32][33];
    int wz = blockIdx.z;
    const float* W = (wz == 0) ? W0 : (wz == 1) ? W1 : (wz == 2) ? W2 : W3;
    __nv_bfloat16* Thi = g_wt_hi[wz];
    __nv_bfloat16* Tlo = g_wt_lo[wz];
    int n0 = blockIdx.x * 32, k0 = blockIdx.y * 32;
    int tx = threadIdx.x, ty = threadIdx.y;
#pragma unroll
    for (int j = 0; j < 4; j++)
        tl[ty + j * 8][tx] = W[(size_t)(k0 + ty + j * 8) * D_ + n0 + tx];
    __syncthreads();
#pragma unroll
    for (int j = 0; j < 4; j++) {
        int n = n0 + ty + j * 8;
        float v = tl[tx][ty + j * 8];
        __nv_bfloat16 hb = __float2bfloat16(v);
        Thi[(size_t)n * D_ + k0 + tx] = hb;
        Tlo[(size_t)n * D_ + k0 + tx] = __float2bfloat16(v - __bfloat162float(hb));
    }
}

// ---------------------------------------------------------------------------
// 3) HMMA GEMM, cp.async 2-stage pipeline, 128x64 tile, BK=32
//    which = -1: QKV fused (blockIdx.z = 0/1/2);  which = 3: out-proj
// ---------------------------------------------------------------------------
#define BK    32
#define G_AH  0
#define G_AL  10240
#define G_BH  20480
#define G_BL  25600
#define G_STG 30720
#define GEMM_SMEM 61440

__global__ __launch_bounds__(256) void gemm_mma_kernel(
        const __nv_bfloat16* __restrict__ Ahi, const __nv_bfloat16* __restrict__ Alo,
        const float* __restrict__ exps, const float* __restrict__ x,
        float* __restrict__ y, int which) {
    extern __shared__ __align__(128) char gsm[];
    uint32_t sb = smem_u32(gsm);
    int we = (which < 0) ? (int)blockIdx.z : which;
    const __nv_bfloat16* __restrict__ Bhi = g_wt_hi[we];
    const __nv_bfloat16* __restrict__ Blo = g_wt_lo[we];

    int t = threadIdx.x, lane = t & 31, wid = t >> 5;
    int wm = wid & 3, wn = wid >> 2;
    int m0 = blockIdx.y * 128, n0 = blockIdx.x * 64;
    float acc[2][4][4] = {};

    auto fill = [&](int kc, int buf) {
        int k0 = kc * BK;
        uint32_t bo = sb + buf * G_STG;
#pragma unroll
        for (int i = 0; i < 2; i++) {
            int idx = t + i * 256;
            int row = idx >> 2, seg = idx & 3;
            uint32_t d = bo + row * 80 + seg * 16;
            size_t go = (size_t)(m0 + row) * D_ + k0 + seg * 8;
            cpa16(d + G_AH, Ahi + go);
            cpa16(d + G_AL, Alo + go);
        }
        {
            int row = t >> 2, seg = t & 3;
            uint32_t d = bo + row * 80 + seg * 16;
            size_t go = (size_t)(n0 + row) * D_ + k0 + seg * 8;
            cpa16(d + G_BH, Bhi + go);
            cpa16(d + G_BL, Blo + go);
        }
    };

    fill(0, 0); CP_COMMIT();
    fill(1, 1); CP_COMMIT();

    for (int kc = 0; kc < D_ / BK; kc++) {
        if (kc + 1 < D_ / BK) { CP_WAIT1(); } else { CP_WAIT0(); }
        __syncthreads();
        uint32_t bo = sb + (kc & 1) * G_STG;
#pragma unroll
        for (int ks = 0; ks < BK; ks += 16) {
            uint32_t ah[2][4], al[2][4], bh[2][4], bl[2][4];
#pragma unroll
            for (int mi = 0; mi < 2; mi++) {
                int ar = wm * 32 + mi * 16 + (lane & 15);
                int ac = ks + ((lane >> 4) << 3);
                ldsm4(ah[mi], bo + G_AH + ar * 80 + ac * 2);
                ldsm4(al[mi], bo + G_AL + ar * 80 + ac * 2);
            }
#pragma unroll
            for (int p = 0; p < 2; p++) {
                int br = wn * 32 + p * 16 + (lane & 7) + ((lane & 16) ? 8 : 0);
                int bc = ks + ((lane & 8) ? 8 : 0);
                ldsm4(bh[p], bo + G_BH + br * 80 + bc * 2);
                ldsm4(bl[p], bo + G_BL + br * 80 + bc * 2);
            }
#pragma unroll
            for (int mi = 0; mi < 2; mi++)
#pragma unroll
                for (int nj = 0; nj < 4; nj++) {
                    const uint32_t* fbh = &bh[nj >> 1][(nj & 1) * 2];
                    const uint32_t* fbl = &bl[nj >> 1][(nj & 1) * 2];
                    mma_bf(acc[mi][nj], ah[mi], fbh);
                    mma_bf(acc[mi][nj], ah[mi], fbl);
                    mma_bf(acc[mi][nj], al[mi], fbh);
                }
        }
        __syncthreads();
        if (kc + 2 < D_ / BK) { fill(kc + 2, kc & 1); CP_COMMIT(); }
    }

    int head = blockIdx.x;
    float e = (we == 1 || we == 2) ? exps[head] : 0.f;
#pragma unroll
    for (int mi = 0; mi < 2; mi++)
#pragma unroll
        for (int nj = 0; nj < 4; nj++)
#pragma unroll
            for (int h2 = 0; h2 < 2; h2++) {
                int m = m0 + wm * 32 + mi * 16 + (lane >> 2) + h2 * 8;
                int nc = wn * 32 + nj * 8 + (lane & 3) * 2;
                float v0 = acc[mi][nj][h2 * 2];
                float v1 = acc[mi][nj][h2 * 2 + 1];
                if (which < 0) {
                    if (we != 0) {
                        float mg0 = fmaxf(fabsf(v0), 1e-8f);
                        float r0 = exp2f(e * log2f(mg0));
                        v0 = (v0 > 0.f) ? r0 : (v0 < 0.f ? -r0 : 0.f);
                        float mg1 = fmaxf(fabsf(v1), 1e-8f);
                        float r1 = exp2f(e * log2f(mg1));
                        v1 = (v1 > 0.f) ? r1 : (v1 < 0.f ? -r1 : 0.f);
                    }
                    int b = m >> 11, s = m & (S_ - 1);
                    size_t off = (((size_t)b * H_ + head) * S_ + s) * DH_ + nc;
                    uint32_t hi, lo;
                    if (we == 2) {
                        packhf2(v0, v1, hi, lo);
                        *(uint32_t*)&g_v_hi[off] = hi;
                        *(uint32_t*)&g_v_lo[off] = lo;
                    } else if (we == 1) {
                        packbf2(v0, v1, hi, lo);
                        *(uint32_t*)&g_k_hi[off] = hi;
                        *(uint32_t*)&g_k_lo[off] = lo;
                    } else {
                        packbf2(v0, v1, hi, lo);
                        *(uint32_t*)&g_q_hi[off] = hi;
                        *(uint32_t*)&g_q_lo[off] = lo;
                    }
                } else {
                    size_t off = (size_t)m * D_ + n0 + nc;
                    float2 xr = *(const float2*)(x + off);
                    *(float2*)(y + off) = make_float2(xr.x + v0, xr.y + v1);
                }
            }
}

// ---------------------------------------------------------------------------
// 4) HMMA flash attention: 128 q-rows/CTA, 64-key tiles, cp.async 2-stage
// ---------------------------------------------------------------------------
#define APAD_B 144          // bytes per smem row (72 halfs)
#define A_KH 0
#define A_KL 9216
#define A_VH 18432
#define A_VL 27648
#define ABUF 36864
#define A_LK 73728
#define ATT_SMEM (73728 + 512)

__global__ __launch_bounds__(256) void attn_kernel(const float* __restrict__ phase,
                                                   const float* __restrict__ cph,
                                                   const float* __restrict__ bal) {
    extern __shared__ __align__(128) char asmem[];
    uint32_t sb = smem_u32(asmem);
    float* lk2 = (float*)(asmem + A_LK);

    int t = threadIdx.x, lane = t & 31, w = t >> 5;
    int bh = blockIdx.y, b = bh >> 4, h = bh & 15;
    int qt = blockIdx.x, m0 = qt * 128;
    int wr0 = m0 + w * 16;
    int r = lane >> 2, c = lane & 3;
    int nkt = 2 * qt + 2;

    float bv  = bal[0];
    float tau = fminf(fmaxf(1.0f / (2.0f * bv + 1e-8f), 0.1f), 10.0f);
    float itau = 1.0f / tau;
    float qscl = 0.125f * itau * 1.44269504f;
    float cp   = cph[h];

    uint32_t qh[4][4], ql[4][4];
    {
        const __nv_bfloat16* qhp = g_q_hi + ((size_t)bh * S_ + wr0) * DH_;
        const __nv_bfloat16* qlp = g_q_lo + ((size_t)bh * S_ + wr0) * DH_;
#pragma unroll
        for (int ks = 0; ks < 4; ks++) {
            int k0 = ks * 16 + 2 * c;
            qh[ks][0] = *(const uint32_t*)(qhp + (size_t)r * DH_ + k0);
            qh[ks][1] = *(const uint32_t*)(qhp + (size_t)(r + 8) * DH_ + k0);
            qh[ks][2] = *(const uint32_t*)(qhp + (size_t)r * DH_ + k0 + 8);
            qh[ks][3] = *(const uint32_t*)(qhp + (size_t)(r + 8) * DH_ + k0 + 8);
            ql[ks][0] = *(const uint32_t*)(qlp + (size_t)r * DH_ + k0);
            ql[ks][1] = *(const uint32_t*)(qlp + (size_t)(r + 8) * DH_ + k0);
            ql[ks][2] = *(const uint32_t*)(qlp + (size_t)r * DH_ + k0 + 8);
            ql[ks][3] = *(const uint32_t*)(qlp + (size_t)(r + 8) * DH_ + k0 + 8);
        }
    }

    float o[8][4] = {};
    float mx[2] = {-1e30f, -1e30f}, lsum[2] = {0.f, 0.f};

#define LOAD_TILE(kt_, buf_) do {                                              \
    int kb_ = (kt_) * 64;                                                      \
    uint32_t bo_ = sb + (buf_) * ABUF;                                         \
    size_t gb_ = ((size_t)bh * S_ + kb_) * DH_;                                \
    _Pragma("unroll")                                                          \
    for (int i_ = 0; i_ < 2; i_++) {                                           \
        int idx_ = t + i_ * 256;                                               \
        int row_ = idx_ >> 3, seg_ = idx_ & 7;                                 \
        uint32_t d_ = bo_ + row_ * APAD_B + seg_ * 16;                         \
        size_t go_ = gb_ + (size_t)row_ * DH_ + seg_ * 8;                      \
        cpa16(d_ + A_KH, g_k_hi + go_);                                        \
        cpa16(d_ + A_KL, g_k_lo + go_);                                        \
        cpa16(d_ + A_VH, g_v_hi + go_);                                        \
        cpa16(d_ + A_VL, g_v_lo + go_);                                        \
    }                                                                          \
} while (0)

    LOAD_TILE(0, 0);
    CP_COMMIT();

    for (int kt = 0; kt < nkt; kt++) {
        int kb = kt * 64;
        if (kt + 1 < nkt) { LOAD_TILE(kt + 1, (kt + 1) & 1); CP_COMMIT(); }
        if (t < 64) {
            float ph = phase[(size_t)b * S_ + kb + t];
            float cc = cosf((ph - cp) * 0.5f);
            lk2[(kt & 1) * 64 + t] = log2f(cc * cc + 1e-6f) * itau;
        }
        if (kt + 1 < nkt) { CP_WAIT1(); } else { CP_WAIT0(); }
        __syncthreads();

        if (kb <= wr0 + 15) {
            uint32_t bo = sb + (kt & 1) * ABUF;
            float s[8][4];
#pragma unroll
            for (int nj = 0; nj < 8; nj++)
                s[nj][0] = s[nj][1] = s[nj][2] = s[nj][3] = 0.f;
#pragma unroll
            for (int ks = 0; ks < 4; ks++)
#pragma unroll
                for (int ng = 0; ng < 4; ng++) {
                    uint32_t kh4[4], kl4[4];
                    int srow = ng * 16 + (lane & 7) + ((lane & 16) ? 8 : 0);
                    int scol = ks * 16 + ((lane & 8) ? 8 : 0);
                    ldsm4(kh4, bo + A_KH + srow * APAD_B + scol * 2);
                    ldsm4(kl4, bo + A_KL + srow * APAD_B + scol * 2);
                    mma_bf(s[2 * ng], qh[ks], &kh4[0]);
                    mma_bf(s[2 * ng], qh[ks], &kl4[0]);
                    mma_bf(s[2 * ng], ql[ks], &kh4[0]);
                    mma_bf(s[2 * ng + 1], qh[ks], &kh4[2]);
                    mma_bf(s[2 * ng + 1], qh[ks], &kl4[2]);
                    mma_bf(s[2 * ng + 1], ql[ks], &kh4[2]);
                }

            bool needmask = (kb + 63 > wr0);
            const float* lkp = &lk2[(kt & 1) * 64];
            float tmax[2] = {-1e30f, -1e30f};
#pragma unroll
            for (int nj = 0; nj < 8; nj++) {
                int key0 = kb + nj * 8 + 2 * c;
                float l0 = lkp[nj * 8 + 2 * c], l1 = lkp[nj * 8 + 2 * c + 1];
#pragma unroll
                for (int e = 0; e < 4; e++) {
                    float z = s[nj][e] * qscl + ((e & 1) ? l1 : l0);
                    if (needmask) {
                        int qrow = wr0 + r + ((e >> 1) ? 8 : 0);
                        if (key0 + (e & 1) > qrow) z = -1e30f;
                    }
                    s[nj][e] = z;
                    int half = e >> 1;
                    tmax[half] = fmaxf(tmax[half], z);
                }
            }
#pragma unroll
            for (int i = 0; i < 2; i++) {
                tmax[i] = fmaxf(tmax[i], __shfl_xor_sync(0xffffffffu, tmax[i], 1));
                tmax[i] = fmaxf(tmax[i], __shfl_xor_sync(0xffffffffu, tmax[i], 2));
            }
            float alpha[2], rsum[2] = {0.f, 0.f};
#pragma unroll
            for (int i = 0; i < 2; i++) {
                float mn = fmaxf(mx[i], tmax[i]);
                alpha[i] = exp2_fast(mx[i] - mn);
                mx[i] = mn;
            }
#pragma unroll
            for (int nj = 0; nj < 8; nj++)
#pragma unroll
                for (int e = 0; e < 4; e++) {
                    int half = e >> 1;
                    float p = exp2_fast(s[nj][e] - mx[half]);
                    s[nj][e] = p;
                    rsum[half] += p;
                }
#pragma unroll
            for (int i = 0; i < 2; i++) {
                rsum[i] += __shfl_xor_sync(0xffffffffu, rsum[i], 1);
                rsum[i] += __shfl_xor_sync(0xffffffffu, rsum[i], 2);
                lsum[i] = lsum[i] * alpha[i] + rsum[i];
            }
#pragma unroll
            for (int nj = 0; nj < 8; nj++) {
                o[nj][0] *= alpha[0]; o[nj][1] *= alpha[0];
                o[nj][2] *= alpha[1]; o[nj][3] *= alpha[1];
            }
            uint32_t pa[4][4];
#pragma unroll
            for (int ks = 0; ks < 4; ks++) {
                pa[ks][0] = packh(s[2 * ks][0], s[2 * ks][1]);
                pa[ks][1] = packh(s[2 * ks][2], s[2 * ks][3]);
                pa[ks][2] = packh(s[2 * ks + 1][0], s[2 * ks + 1][1]);
                pa[ks][3] = packh(s[2 * ks + 1][2], s[2 * ks + 1][3]);
            }
#pragma unroll
            for (int ng = 0; ng < 4; ng++)
#pragma unroll
                for (int ks = 0; ks < 4; ks++) {
                    uint32_t vh4[4], vl4[4];
                    int srow = ks * 16 + (lane & 7) + ((lane & 8) ? 8 : 0);
                    int scol = ng * 16 + ((lane & 16) ? 8 : 0);
                    ldsm4t(vh4, bo + A_VH + srow * APAD_B + scol * 2);
                    ldsm4t(vl4, bo + A_VL + srow * APAD_B + scol * 2);
                    mma_hf(o[2 * ng],     pa[ks], &vh4[0]);
                    mma_hf(o[2 * ng],     pa[ks], &vl4[0]);
                    mma_hf(o[2 * ng + 1], pa[ks], &vh4[2]);
                    mma_hf(o[2 * ng + 1], pa[ks], &vl4[2]);
                }
        }
        __syncthreads();
    }

    float g[2];
#pragma unroll
    for (int i = 0; i < 2; i++) {
        int srow = wr0 + r + i * 8;
        float ph = phase[(size_t)b * S_ + srow];
        float cq = cosf((ph - cp) * 0.5f);
        g[i] = (cq * cq) / lsum[i];
    }
#pragma unroll
    for (int nj = 0; nj < 8; nj++)
#pragma unroll
        for (int i = 0; i < 2; i++) {
            int srow = wr0 + r + i * 8;
            size_t off = ((size_t)b * S_ + srow) * D_ + h * DH_ + nj * 8 + 2 * c;
            uint32_t hi, lo;
            packbf2(o[nj][i * 2] * g[i], o[nj][i * 2 + 1] * g[i], hi, lo);
            *(uint32_t*)&g_ao_hi[off] = hi;
            *(uint32_t*)&g_ao_lo[off] = lo;
        }
}

// ---------------------------------------------------------------------------
extern "C" void kernel_launch(void* const* d_in, const int* in_sizes, int n_in,
                              void* d_out, int out_size) {
    const float* x     = (const float*)d_in[0];
    const float* phase = (const float*)d_in[1];
    const float* Wq    = (const float*)d_in[2];
    const float* Wk    = (const float*)d_in[3];
    const float* Wv    = (const float*)d_in[4];
    const float* Wo    = (const float*)d_in[5];
    const float* gamma = (const float*)d_in[6];
    const float* beta  = (const float*)d_in[7];
    const float* exps  = (const float*)d_in[8];
    const float* cph   = (const float*)d_in[9];
    const float* bal   = (const float*)d_in[10];
    float* y = (float*)d_out;

    static __nv_bfloat16 *hhi, *hlo, *aohi, *aolo;
    static bool got = false;
    if (!got) {
        cudaGetSymbolAddress((void**)&hhi, g_h_hi);
        cudaGetSymbolAddress((void**)&hlo, g_h_lo);
        cudaGetSymbolAddress((void**)&aohi, g_ao_hi);
        cudaGetSymbolAddress((void**)&aolo, g_ao_lo);
        cudaFuncSetAttribute((const void*)attn_kernel,
                             cudaFuncAttributeMaxDynamicSharedMemorySize, ATT_SMEM);
        cudaFuncSetAttribute((const void*)gemm_mma_kernel,
                             cudaFuncAttributeMaxDynamicSharedMemorySize, GEMM_SMEM);
        got = true;
    }

    ln_kernel<<<M_, 256>>>(x, gamma, beta);

    wconv_kernel<<<dim3(32, 32, 4), dim3(32, 8)>>>(Wq, Wk, Wv, Wo);

    gemm_mma_kernel<<<dim3(D_ / 64, M_ / 128, 3), 256, GEMM_SMEM>>>(
        hhi, hlo, exps, x, y, -1);

    attn_kernel<<<dim3(S_ / 128, B_ * H_), 256, ATT_SMEM>>>(phase, cph, bal);

    gemm_mma_kernel<<<dim3(D_ / 64, M_ / 128, 1), 256, GEMM_SMEM>>>(
        aohi, aolo, exps, x, y, 3);
}

// round 12
// speedup vs baseline: 2.6751x; 1.0451x over previous
#include <cuda_runtime.h>
#include <cuda_bf16.h>
#include <cuda_fp16.h>
#include <math.h>
#include <stdint.h>

#define B_  2
#define S_  2048
#define D_  1024
#define H_  16
#define DH_ 64
#define M_  (B_*S_)

// ---------------------------------------------------------------------------
// Scratch
// ---------------------------------------------------------------------------
__device__ __nv_bfloat16 g_h_hi [M_*D_];
__device__ __nv_bfloat16 g_h_lo [M_*D_];
__device__ __nv_bfloat16 g_wt_hi[4][D_*D_];
__device__ __nv_bfloat16 g_wt_lo[4][D_*D_];
__device__ __nv_bfloat16 g_q_hi [M_*D_];   // (B,H,S,DH)
__device__ __nv_bfloat16 g_q_lo [M_*D_];
__device__ __nv_bfloat16 g_k_hi [M_*D_];
__device__ __nv_bfloat16 g_k_lo [M_*D_];
__device__ __half        g_v_hi [M_*D_];
__device__ __half        g_v_lo [M_*D_];
__device__ __nv_bfloat16 g_ao_hi[M_*D_];   // (B,S,D)
__device__ __nv_bfloat16 g_ao_lo[M_*D_];
__device__ float         g_lk   [B_*H_*S_]; // key-side log2-resonance / tau

// ---------------------------------------------------------------------------
// helpers
// ---------------------------------------------------------------------------
__device__ __forceinline__ uint32_t smem_u32(const void* p) {
    uint32_t a;
    asm("{ .reg .u64 t; cvta.to.shared.u64 t, %1; cvt.u32.u64 %0, t; }"
        : "=r"(a) : "l"(p));
    return a;
}
__device__ __forceinline__ void ldsm4(uint32_t* r, uint32_t addr) {
    asm volatile("ldmatrix.sync.aligned.m8n8.x4.shared.b16 {%0,%1,%2,%3}, [%4];"
                 : "=r"(r[0]), "=r"(r[1]), "=r"(r[2]), "=r"(r[3]) : "r"(addr));
}
__device__ __forceinline__ void ldsm4t(uint32_t* r, uint32_t addr) {
    asm volatile("ldmatrix.sync.aligned.m8n8.x4.trans.shared.b16 {%0,%1,%2,%3}, [%4];"
                 : "=r"(r[0]), "=r"(r[1]), "=r"(r[2]), "=r"(r[3]) : "r"(addr));
}
__device__ __forceinline__ void mma_bf(float* c, const uint32_t* a, const uint32_t* b) {
    asm volatile(
        "mma.sync.aligned.m16n8k16.row.col.f32.bf16.bf16.f32 "
        "{%0,%1,%2,%3}, {%4,%5,%6,%7}, {%8,%9}, {%0,%1,%2,%3};"
        : "+f"(c[0]), "+f"(c[1]), "+f"(c[2]), "+f"(c[3])
        : "r"(a[0]), "r"(a[1]), "r"(a[2]), "r"(a[3]), "r"(b[0]), "r"(b[1]));
}
__device__ __forceinline__ void mma_hf(float* c, const uint32_t* a, const uint32_t* b) {
    asm volatile(
        "mma.sync.aligned.m16n8k16.row.col.f32.f16.f16.f32 "
        "{%0,%1,%2,%3}, {%4,%5,%6,%7}, {%8,%9}, {%0,%1,%2,%3};"
        : "+f"(c[0]), "+f"(c[1]), "+f"(c[2]), "+f"(c[3])
        : "r"(a[0]), "r"(a[1]), "r"(a[2]), "r"(a[3]), "r"(b[0]), "r"(b[1]));
}
__device__ __forceinline__ void cpa16(uint32_t smaddr, const void* g) {
    asm volatile("cp.async.cg.shared.global [%0], [%1], 16;"
                 :: "r"(smaddr), "l"(__cvta_generic_to_global(g)));
}
#define CP_COMMIT() asm volatile("cp.async.commit_group;" ::: "memory")
#define CP_WAIT1()  asm volatile("cp.async.wait_group 1;" ::: "memory")
#define CP_WAIT0()  asm volatile("cp.async.wait_group 0;" ::: "memory")

__device__ __forceinline__ void packbf2(float x0, float x1, uint32_t& hi, uint32_t& lo) {
    asm("cvt.rn.bf16x2.f32 %0, %1, %2;" : "=r"(hi) : "f"(x1), "f"(x0));
    float h0 = __int_as_float(hi << 16);
    float h1 = __int_as_float(hi & 0xFFFF0000u);
    asm("cvt.rn.bf16x2.f32 %0, %1, %2;" : "=r"(lo) : "f"(x1 - h1), "f"(x0 - h0));
}
__device__ __forceinline__ void packhf2(float x0, float x1, uint32_t& hi, uint32_t& lo) {
    __half2 h = __floats2half2_rn(x0, x1);
    hi = *reinterpret_cast<uint32_t*>(&h);
    float2 hf = __half22float2(h);
    __half2 l = __floats2half2_rn(x0 - hf.x, x1 - hf.y);
    lo = *reinterpret_cast<uint32_t*>(&l);
}
__device__ __forceinline__ uint32_t packh(float x0, float x1) {
    __half2 h = __floats2half2_rn(x0, x1);
    return *reinterpret_cast<uint32_t*>(&h);
}
// exp2 on the fma pipe; valid for z <= 0 (clamped at -80)
__device__ __forceinline__ float exp2_fast(float z) {
    z = fmaxf(z, -80.f);
    float fm = z + 12582912.f;
    int i = __float_as_int(fm) - 0x4B400000;
    float f = z - (fm - 12582912.f);
    float p = 1.333356e-3f;
    p = fmaf(p, f, 9.618129e-3f);
    p = fmaf(p, f, 5.5504109e-2f);
    p = fmaf(p, f, 2.40226507e-1f);
    p = fmaf(p, f, 6.93147181e-1f);
    p = fmaf(p, f, 1.0f);
    return p * __int_as_float((i + 127) << 23);
}

// ---------------------------------------------------------------------------
// 0) key-side resonance precompute: g_lk[bh][s] = log2(cos^2+1e-6) * itau
// ---------------------------------------------------------------------------
__global__ __launch_bounds__(256) void lkg_kernel(const float* __restrict__ phase,
                                                  const float* __restrict__ cph,
                                                  const float* __restrict__ bal) {
    int bh = blockIdx.y, b = bh >> 4, h = bh & 15;
    int s = blockIdx.x * 256 + threadIdx.x;
    float bv  = bal[0];
    float tau = fminf(fmaxf(1.0f / (2.0f * bv + 1e-8f), 0.1f), 10.0f);
    float itau = 1.0f / tau;
    float cc = cosf((phase[(size_t)b * S_ + s] - cph[h]) * 0.5f);
    g_lk[(size_t)bh * S_ + s] = log2f(cc * cc + 1e-6f) * itau;
}

// ---------------------------------------------------------------------------
// 1) LayerNorm -> hi/lo bf16
// ---------------------------------------------------------------------------
__global__ __launch_bounds__(256) void ln_kernel(const float* __restrict__ x,
                                                 const float* __restrict__ gamma,
                                                 const float* __restrict__ beta) {
    int row = blockIdx.x;
    const float* xr = x + (size_t)row * D_;
    float v[4];
    float s = 0.f, s2 = 0.f;
#pragma unroll
    for (int i = 0; i < 4; i++) {
        v[i] = xr[threadIdx.x + i * 256];
        s += v[i]; s2 += v[i] * v[i];
    }
#pragma unroll
    for (int o = 16; o; o >>= 1) {
        s  += __shfl_xor_sync(0xffffffffu, s,  o);
        s2 += __shfl_xor_sync(0xffffffffu, s2, o);
    }
    __shared__ float red[16];
    int w = threadIdx.x >> 5;
    if ((threadIdx.x & 31) == 0) { red[w] = s; red[w + 8] = s2; }
    __syncthreads();
    float ts = 0.f, ts2 = 0.f;
#pragma unroll
    for (int i = 0; i < 8; i++) { ts += red[i]; ts2 += red[i + 8]; }
    float mean = ts * (1.0f / D_);
    float var  = ts2 * (1.0f / D_) - mean * mean;
    float rstd = rsqrtf(var + 1e-5f);
#pragma unroll
    for (int i = 0; i < 4; i++) {
        int c = threadIdx.x + i * 256;
        float hv = (v[i] - mean) * rstd * gamma[c] + beta[c];
        __nv_bfloat16 hb = __float2bfloat16(hv);
        g_h_hi[(size_t)row * D_ + c] = hb;
        g_h_lo[(size_t)row * D_ + c] = __float2bfloat16(hv - __bfloat162float(hb));
    }
}

// ---------------------------------------------------------------------------
// 2) Weight transpose+convert (all 4 weights, blockIdx.z selects)
// ---------------------------------------------------------------------------
__global__ __launch_bounds__(256) void wconv_kernel(const float* __restrict__ W0,
                                                    const float* __restrict__ W1,
                                                    const float* __restrict__ W2,
                                                    const float* __restrict__ W3) {
    __shared__ float tl[32][33];
    int wz = blockIdx.z;
    const float* W = (wz == 0) ? W0 : (wz == 1) ? W1 : (wz == 2) ? W2 : W3;
    __nv_bfloat16* Thi = g_wt_hi[wz];
    __nv_bfloat16* Tlo = g_wt_lo[wz];
    int n0 = blockIdx.x * 32, k0 = blockIdx.y * 32;
    int tx = threadIdx.x, ty = threadIdx.y;
#pragma unroll
    for (int j = 0; j < 4; j++)
        tl[ty + j * 8][tx] = W[(size_t)(k0 + ty + j * 8) * D_ + n0 + tx];
    __syncthreads();
#pragma unroll
    for (int j = 0; j < 4; j++) {
        int n = n0 + ty + j * 8;
        float v = tl[tx][ty + j * 8];
        __nv_bfloat16 hb = __float2bfloat16(v);
        Thi[(size_t)n * D_ + k0 + tx] = hb;
        Tlo[(size_t)n * D_ + k0 + tx] = __float2bfloat16(v - __bfloat162float(hb));
    }
}

// ---------------------------------------------------------------------------
// 3) HMMA GEMM, cp.async 2-stage pipeline, 128x64 tile, BK=32
// ---------------------------------------------------------------------------
#define BK    32
#define G_AH  0
#define G_AL  10240
#define G_BH  20480
#define G_BL  25600
#define G_STG 30720
#define GEMM_SMEM 61440

__global__ __launch_bounds__(256) void gemm_mma_kernel(
        const __nv_bfloat16* __restrict__ Ahi, const __nv_bfloat16* __restrict__ Alo,
        const float* __restrict__ exps, const float* __restrict__ x,
        float* __restrict__ y, int which) {
    extern __shared__ __align__(128) char gsm[];
    uint32_t sb = smem_u32(gsm);
    int we = (which < 0) ? (int)blockIdx.z : which;
    const __nv_bfloat16* __restrict__ Bhi = g_wt_hi[we];
    const __nv_bfloat16* __restrict__ Blo = g_wt_lo[we];

    int t = threadIdx.x, lane = t & 31, wid = t >> 5;
    int wm = wid & 3, wn = wid >> 2;
    int m0 = blockIdx.y * 128, n0 = blockIdx.x * 64;
    float acc[2][4][4] = {};

    auto fill = [&](int kc, int buf) {
        int k0 = kc * BK;
        uint32_t bo = sb + buf * G_STG;
#pragma unroll
        for (int i = 0; i < 2; i++) {
            int idx = t + i * 256;
            int row = idx >> 2, seg = idx & 3;
            uint32_t d = bo + row * 80 + seg * 16;
            size_t go = (size_t)(m0 + row) * D_ + k0 + seg * 8;
            cpa16(d + G_AH, Ahi + go);
            cpa16(d + G_AL, Alo + go);
        }
        {
            int row = t >> 2, seg = t & 3;
            uint32_t d = bo + row * 80 + seg * 16;
            size_t go = (size_t)(n0 + row) * D_ + k0 + seg * 8;
            cpa16(d + G_BH, Bhi + go);
            cpa16(d + G_BL, Blo + go);
        }
    };

    fill(0, 0); CP_COMMIT();
    fill(1, 1); CP_COMMIT();

    for (int kc = 0; kc < D_ / BK; kc++) {
        if (kc + 1 < D_ / BK) { CP_WAIT1(); } else { CP_WAIT0(); }
        __syncthreads();
        uint32_t bo = sb + (kc & 1) * G_STG;
#pragma unroll
        for (int ks = 0; ks < BK; ks += 16) {
            uint32_t ah[2][4], al[2][4], bh[2][4], bl[2][4];
#pragma unroll
            for (int mi = 0; mi < 2; mi++) {
                int ar = wm * 32 + mi * 16 + (lane & 15);
                int ac = ks + ((lane >> 4) << 3);
                ldsm4(ah[mi], bo + G_AH + ar * 80 + ac * 2);
                ldsm4(al[mi], bo + G_AL + ar * 80 + ac * 2);
            }
#pragma unroll
            for (int p = 0; p < 2; p++) {
                int br = wn * 32 + p * 16 + (lane & 7) + ((lane & 16) ? 8 : 0);
                int bc = ks + ((lane & 8) ? 8 : 0);
                ldsm4(bh[p], bo + G_BH + br * 80 + bc * 2);
                ldsm4(bl[p], bo + G_BL + br * 80 + bc * 2);
            }
#pragma unroll
            for (int mi = 0; mi < 2; mi++)
#pragma unroll
                for (int nj = 0; nj < 4; nj++) {
                    const uint32_t* fbh = &bh[nj >> 1][(nj & 1) * 2];
                    const uint32_t* fbl = &bl[nj >> 1][(nj & 1) * 2];
                    mma_bf(acc[mi][nj], ah[mi], fbh);
                    mma_bf(acc[mi][nj], ah[mi], fbl);
                    mma_bf(acc[mi][nj], al[mi], fbh);
                }
        }
        __syncthreads();
        if (kc + 2 < D_ / BK) { fill(kc + 2, kc & 1); CP_COMMIT(); }
    }

    int head = blockIdx.x;
    float e = (we == 1 || we == 2) ? exps[head] : 0.f;
#pragma unroll
    for (int mi = 0; mi < 2; mi++)
#pragma unroll
        for (int nj = 0; nj < 4; nj++)
#pragma unroll
            for (int h2 = 0; h2 < 2; h2++) {
                int m = m0 + wm * 32 + mi * 16 + (lane >> 2) + h2 * 8;
                int nc = wn * 32 + nj * 8 + (lane & 3) * 2;
                float v0 = acc[mi][nj][h2 * 2];
                float v1 = acc[mi][nj][h2 * 2 + 1];
                if (which < 0) {
                    if (we != 0) {
                        float mg0 = fmaxf(fabsf(v0), 1e-8f);
                        float r0 = exp2f(e * log2f(mg0));
                        v0 = (v0 > 0.f) ? r0 : (v0 < 0.f ? -r0 : 0.f);
                        float mg1 = fmaxf(fabsf(v1), 1e-8f);
                        float r1 = exp2f(e * log2f(mg1));
                        v1 = (v1 > 0.f) ? r1 : (v1 < 0.f ? -r1 : 0.f);
                    }
                    int b = m >> 11, s = m & (S_ - 1);
                    size_t off = (((size_t)b * H_ + head) * S_ + s) * DH_ + nc;
                    uint32_t hi, lo;
                    if (we == 2) {
                        packhf2(v0, v1, hi, lo);
                        *(uint32_t*)&g_v_hi[off] = hi;
                        *(uint32_t*)&g_v_lo[off] = lo;
                    } else if (we == 1) {
                        packbf2(v0, v1, hi, lo);
                        *(uint32_t*)&g_k_hi[off] = hi;
                        *(uint32_t*)&g_k_lo[off] = lo;
                    } else {
                        packbf2(v0, v1, hi, lo);
                        *(uint32_t*)&g_q_hi[off] = hi;
                        *(uint32_t*)&g_q_lo[off] = lo;
                    }
                } else {
                    size_t off = (size_t)m * D_ + n0 + nc;
                    float2 xr = *(const float2*)(x + off);
                    *(float2*)(y + off) = make_float2(xr.x + v0, xr.y + v1);
                }
            }
}

// ---------------------------------------------------------------------------
// 4) HMMA flash attention: 128 q-rows/CTA, 64-key tiles, cp.async 2-stage
//    __launch_bounds__(256, 2): cap 128 regs -> 2 CTAs/SM
// ---------------------------------------------------------------------------
#define APAD_B 144
#define A_KH 0
#define A_KL 9216
#define A_VH 18432
#define A_VL 27648
#define ABUF 36864
#define A_LK 73728
#define ATT_SMEM (73728 + 512)

__global__ __launch_bounds__(256, 2) void attn_kernel(const float* __restrict__ phase,
                                                      const float* __restrict__ cph,
                                                      const float* __restrict__ bal) {
    extern __shared__ __align__(128) char asmem[];
    uint32_t sb = smem_u32(asmem);
    float* lk2 = (float*)(asmem + A_LK);

    int t = threadIdx.x, lane = t & 31, w = t >> 5;
    int bh = blockIdx.y, b = bh >> 4, h = bh & 15;
    int qt = blockIdx.x, m0 = qt * 128;
    int wr0 = m0 + w * 16;
    int r = lane >> 2, c = lane & 3;
    int nkt = 2 * qt + 2;

    float bv  = bal[0];
    float tau = fminf(fmaxf(1.0f / (2.0f * bv + 1e-8f), 0.1f), 10.0f);
    float itau = 1.0f / tau;
    float qscl = 0.125f * itau * 1.44269504f;
    float cp   = cph[h];

    uint32_t qh[4][4], ql[4][4];
    {
        const __nv_bfloat16* qhp = g_q_hi + ((size_t)bh * S_ + wr0) * DH_;
        const __nv_bfloat16* qlp = g_q_lo + ((size_t)bh * S_ + wr0) * DH_;
#pragma unroll
        for (int ks = 0; ks < 4; ks++) {
            int k0 = ks * 16 + 2 * c;
            qh[ks][0] = *(const uint32_t*)(qhp + (size_t)r * DH_ + k0);
            qh[ks][1] = *(const uint32_t*)(qhp + (size_t)(r + 8) * DH_ + k0);
            qh[ks][2] = *(const uint32_t*)(qhp + (size_t)r * DH_ + k0 + 8);
            qh[ks][3] = *(const uint32_t*)(qhp + (size_t)(r + 8) * DH_ + k0 + 8);
            ql[ks][0] = *(const uint32_t*)(qlp + (size_t)r * DH_ + k0);
            ql[ks][1] = *(const uint32_t*)(qlp + (size_t)(r + 8) * DH_ + k0);
            ql[ks][2] = *(const uint32_t*)(qlp + (size_t)r * DH_ + k0 + 8);
            ql[ks][3] = *(const uint32_t*)(qlp + (size_t)(r + 8) * DH_ + k0 + 8);
        }
    }

    float o[8][4] = {};
    float mx[2] = {-1e30f, -1e30f}, lsum[2] = {0.f, 0.f};

#define LOAD_TILE(kt_, buf_) do {                                              \
    int kb_ = (kt_) * 64;                                                      \
    uint32_t bo_ = sb + (buf_) * ABUF;                                         \
    size_t gb_ = ((size_t)bh * S_ + kb_) * DH_;                                \
    _Pragma("unroll")                                                          \
    for (int i_ = 0; i_ < 2; i_++) {                                           \
        int idx_ = t + i_ * 256;                                               \
        int row_ = idx_ >> 3, seg_ = idx_ & 7;                                 \
        uint32_t d_ = bo_ + row_ * APAD_B + seg_ * 16;                         \
        size_t go_ = gb_ + (size_t)row_ * DH_ + seg_ * 8;                      \
        cpa16(d_ + A_KH, g_k_hi + go_);                                        \
        cpa16(d_ + A_KL, g_k_lo + go_);                                        \
        cpa16(d_ + A_VH, g_v_hi + go_);                                        \
        cpa16(d_ + A_VL, g_v_lo + go_);                                        \
    }                                                                          \
} while (0)

    LOAD_TILE(0, 0);
    CP_COMMIT();

    for (int kt = 0; kt < nkt; kt++) {
        int kb = kt * 64;
        if (kt + 1 < nkt) { LOAD_TILE(kt + 1, (kt + 1) & 1); CP_COMMIT(); }
        if (t < 64)
            lk2[(kt & 1) * 64 + t] = g_lk[(size_t)bh * S_ + kb + t];
        if (kt + 1 < nkt) { CP_WAIT1(); } else { CP_WAIT0(); }
        __syncthreads();

        if (kb <= wr0 + 15) {
            uint32_t bo = sb + (kt & 1) * ABUF;
            float s[8][4];
#pragma unroll
            for (int nj = 0; nj < 8; nj++)
                s[nj][0] = s[nj][1] = s[nj][2] = s[nj][3] = 0.f;
#pragma unroll
            for (int ks = 0; ks < 4; ks++)
#pragma unroll
                for (int ng = 0; ng < 4; ng++) {
                    uint32_t kh4[4], kl4[4];
                    int srow = ng * 16 + (lane & 7) + ((lane & 16) ? 8 : 0);
                    int scol = ks * 16 + ((lane & 8) ? 8 : 0);
                    ldsm4(kh4, bo + A_KH + srow * APAD_B + scol * 2);
                    ldsm4(kl4, bo + A_KL + srow * APAD_B + scol * 2);
                    mma_bf(s[2 * ng], qh[ks], &kh4[0]);
                    mma_bf(s[2 * ng], qh[ks], &kl4[0]);
                    mma_bf(s[2 * ng], ql[ks], &kh4[0]);
                    mma_bf(s[2 * ng + 1], qh[ks], &kh4[2]);
                    mma_bf(s[2 * ng + 1], qh[ks], &kl4[2]);
                    mma_bf(s[2 * ng + 1], ql[ks], &kh4[2]);
                }

            bool needmask = (kb + 63 > wr0);
            const float* lkp = &lk2[(kt & 1) * 64];
            float tmax[2] = {-1e30f, -1e30f};
#pragma unroll
            for (int nj = 0; nj < 8; nj++) {
                int key0 = kb + nj * 8 + 2 * c;
                float l0 = lkp[nj * 8 + 2 * c], l1 = lkp[nj * 8 + 2 * c + 1];
#pragma unroll
                for (int e = 0; e < 4; e++) {
                    float z = s[nj][e] * qscl + ((e & 1) ? l1 : l0);
                    if (needmask) {
                        int qrow = wr0 + r + ((e >> 1) ? 8 : 0);
                        if (key0 + (e & 1) > qrow) z = -1e30f;
                    }
                    s[nj][e] = z;
                    int half = e >> 1;
                    tmax[half] = fmaxf(tmax[half], z);
                }
            }
#pragma unroll
            for (int i = 0; i < 2; i++) {
                tmax[i] = fmaxf(tmax[i], __shfl_xor_sync(0xffffffffu, tmax[i], 1));
                tmax[i] = fmaxf(tmax[i], __shfl_xor_sync(0xffffffffu, tmax[i], 2));
            }
            float alpha[2], rsum[2] = {0.f, 0.f};
#pragma unroll
            for (int i = 0; i < 2; i++) {
                float mn = fmaxf(mx[i], tmax[i]);
                alpha[i] = exp2_fast(mx[i] - mn);
                mx[i] = mn;
            }
#pragma unroll
            for (int nj = 0; nj < 8; nj++)
#pragma unroll
                for (int e = 0; e < 4; e++) {
                    int half = e >> 1;
                    float p = exp2_fast(s[nj][e] - mx[half]);
                    s[nj][e] = p;
                    rsum[half] += p;
                }
#pragma unroll
            for (int i = 0; i < 2; i++) {
                rsum[i] += __shfl_xor_sync(0xffffffffu, rsum[i], 1);
                rsum[i] += __shfl_xor_sync(0xffffffffu, rsum[i], 2);
                lsum[i] = lsum[i] * alpha[i] + rsum[i];
            }
#pragma unroll
            for (int nj = 0; nj < 8; nj++) {
                o[nj][0] *= alpha[0]; o[nj][1] *= alpha[0];
                o[nj][2] *= alpha[1]; o[nj][3] *= alpha[1];
            }
            uint32_t pa[4][4];
#pragma unroll
            for (int ks = 0; ks < 4; ks++) {
                pa[ks][0] = packh(s[2 * ks][0], s[2 * ks][1]);
                pa[ks][1] = packh(s[2 * ks][2], s[2 * ks][3]);
                pa[ks][2] = packh(s[2 * ks + 1][0], s[2 * ks + 1][1]);
                pa[ks][3] = packh(s[2 * ks + 1][2], s[2 * ks + 1][3]);
            }
#pragma unroll
            for (int ng = 0; ng < 4; ng++)
#pragma unroll
                for (int ks = 0; ks < 4; ks++) {
                    uint32_t vh4[4], vl4[4];
                    int srow = ks * 16 + (lane & 7) + ((lane & 8) ? 8 : 0);
                    int scol = ng * 16 + ((lane & 16) ? 8 : 0);
                    ldsm4t(vh4, bo + A_VH + srow * APAD_B + scol * 2);
                    ldsm4t(vl4, bo + A_VL + srow * APAD_B + scol * 2);
                    mma_hf(o[2 * ng],     pa[ks], &vh4[0]);
                    mma_hf(o[2 * ng],     pa[ks], &vl4[0]);
                    mma_hf(o[2 * ng + 1], pa[ks], &vh4[2]);
                    mma_hf(o[2 * ng + 1], pa[ks], &vl4[2]);
                }
        }
        __syncthreads();
    }

    float g[2];
#pragma unroll
    for (int i = 0; i < 2; i++) {
        int srow = wr0 + r + i * 8;
        float ph = phase[(size_t)b * S_ + srow];
        float cq = cosf((ph - cp) * 0.5f);
        g[i] = (cq * cq) / lsum[i];
    }
#pragma unroll
    for (int nj = 0; nj < 8; nj++)
#pragma unroll
        for (int i = 0; i < 2; i++) {
            int srow = wr0 + r + i * 8;
            size_t off = ((size_t)b * S_ + srow) * D_ + h * DH_ + nj * 8 + 2 * c;
            uint32_t hi, lo;
            packbf2(o[nj][i * 2] * g[i], o[nj][i * 2 + 1] * g[i], hi, lo);
            *(uint32_t*)&g_ao_hi[off] = hi;
            *(uint32_t*)&g_ao_lo[off] = lo;
        }
}

// ---------------------------------------------------------------------------
extern "C" void kernel_launch(void* const* d_in, const int* in_sizes, int n_in,
                              void* d_out, int out_size) {
    const float* x     = (const float*)d_in[0];
    const float* phase = (const float*)d_in[1];
    const float* Wq    = (const float*)d_in[2];
    const float* Wk    = (const float*)d_in[3];
    const float* Wv    = (const float*)d_in[4];
    const float* Wo    = (const float*)d_in[5];
    const float* gamma = (const float*)d_in[6];
    const float* beta  = (const float*)d_in[7];
    const float* exps  = (const float*)d_in[8];
    const float* cph   = (const float*)d_in[9];
    const float* bal   = (const float*)d_in[10];
    float* y = (float*)d_out;

    static __nv_bfloat16 *hhi, *hlo, *aohi, *aolo;
    static bool got = false;
    if (!got) {
        cudaGetSymbolAddress((void**)&hhi, g_h_hi);
        cudaGetSymbolAddress((void**)&hlo, g_h_lo);
        cudaGetSymbolAddress((void**)&aohi, g_ao_hi);
        cudaGetSymbolAddress((void**)&aolo, g_ao_lo);
        cudaFuncSetAttribute((const void*)attn_kernel,
                             cudaFuncAttributeMaxDynamicSharedMemorySize, ATT_SMEM);
        cudaFuncSetAttribute((const void*)gemm_mma_kernel,
                             cudaFuncAttributeMaxDynamicSharedMemorySize, GEMM_SMEM);
        got = true;
    }

    ln_kernel<<<M_, 256>>>(x, gamma, beta);
    lkg_kernel<<<dim3(S_ / 256, B_ * H_), 256>>>(phase, cph, bal);

    wconv_kernel<<<dim3(32, 32, 4), dim3(32, 8)>>>(Wq, Wk, Wv, Wo);

    gemm_mma_kernel<<<dim3(D_ / 64, M_ / 128, 3), 256, GEMM_SMEM>>>(
        hhi, hlo, exps, x, y, -1);

    attn_kernel<<<dim3(S_ / 128, B_ * H_), 256, ATT_SMEM>>>(phase, cph, bal);

    gemm_mma_kernel<<<dim3(D_ / 64, M_ / 128, 1), 256, GEMM_SMEM>>>(
        aohi, aolo, exps, x, y, 3);
}

// round 13
// speedup vs baseline: 2.7609x; 1.0321x over previous
#include <cuda_runtime.h>
#include <cuda_bf16.h>
#include <cuda_fp16.h>
#include <math.h>
#include <stdint.h>

#define B_  2
#define S_  2048
#define D_  1024
#define H_  16
#define DH_ 64
#define M_  (B_*S_)

// ---------------------------------------------------------------------------
// Scratch
// ---------------------------------------------------------------------------
__device__ __nv_bfloat16 g_h_hi [M_*D_];
__device__ __nv_bfloat16 g_h_lo [M_*D_];
__device__ __nv_bfloat16 g_wt_hi[4][D_*D_];
__device__ __nv_bfloat16 g_wt_lo[4][D_*D_];
__device__ __nv_bfloat16 g_q_hi [M_*D_];   // (B,H,S,DH)
__device__ __nv_bfloat16 g_k_hi [M_*D_];
__device__ __nv_bfloat16 g_k_lo [M_*D_];
__device__ __half        g_v_hi [M_*D_];
__device__ __half        g_v_lo [M_*D_];
__device__ __nv_bfloat16 g_ao_hi[M_*D_];   // (B,S,D)
__device__ __nv_bfloat16 g_ao_lo[M_*D_];
__device__ float         g_lk   [B_*H_*S_]; // key-side log2-resonance / tau

// ---------------------------------------------------------------------------
// helpers
// ---------------------------------------------------------------------------
__device__ __forceinline__ uint32_t smem_u32(const void* p) {
    uint32_t a;
    asm("{ .reg .u64 t; cvta.to.shared.u64 t, %1; cvt.u32.u64 %0, t; }"
        : "=r"(a) : "l"(p));
    return a;
}
__device__ __forceinline__ void ldsm4(uint32_t* r, uint32_t addr) {
    asm volatile("ldmatrix.sync.aligned.m8n8.x4.shared.b16 {%0,%1,%2,%3}, [%4];"
                 : "=r"(r[0]), "=r"(r[1]), "=r"(r[2]), "=r"(r[3]) : "r"(addr));
}
__device__ __forceinline__ void ldsm4t(uint32_t* r, uint32_t addr) {
    asm volatile("ldmatrix.sync.aligned.m8n8.x4.trans.shared.b16 {%0,%1,%2,%3}, [%4];"
                 : "=r"(r[0]), "=r"(r[1]), "=r"(r[2]), "=r"(r[3]) : "r"(addr));
}
__device__ __forceinline__ void mma_bf(float* c, const uint32_t* a, const uint32_t* b) {
    asm volatile(
        "mma.sync.aligned.m16n8k16.row.col.f32.bf16.bf16.f32 "
        "{%0,%1,%2,%3}, {%4,%5,%6,%7}, {%8,%9}, {%0,%1,%2,%3};"
        : "+f"(c[0]), "+f"(c[1]), "+f"(c[2]), "+f"(c[3])
        : "r"(a[0]), "r"(a[1]), "r"(a[2]), "r"(a[3]), "r"(b[0]), "r"(b[1]));
}
__device__ __forceinline__ void mma_hf(float* c, const uint32_t* a, const uint32_t* b) {
    asm volatile(
        "mma.sync.aligned.m16n8k16.row.col.f32.f16.f16.f32 "
        "{%0,%1,%2,%3}, {%4,%5,%6,%7}, {%8,%9}, {%0,%1,%2,%3};"
        : "+f"(c[0]), "+f"(c[1]), "+f"(c[2]), "+f"(c[3])
        : "r"(a[0]), "r"(a[1]), "r"(a[2]), "r"(a[3]), "r"(b[0]), "r"(b[1]));
}
__device__ __forceinline__ void cpa16(uint32_t smaddr, const void* g) {
    asm volatile("cp.async.cg.shared.global [%0], [%1], 16;"
                 :: "r"(smaddr), "l"(__cvta_generic_to_global(g)));
}
#define CP_COMMIT() asm volatile("cp.async.commit_group;" ::: "memory")
#define CP_WAIT1()  asm volatile("cp.async.wait_group 1;" ::: "memory")
#define CP_WAIT0()  asm volatile("cp.async.wait_group 0;" ::: "memory")

__device__ __forceinline__ void packbf2(float x0, float x1, uint32_t& hi, uint32_t& lo) {
    asm("cvt.rn.bf16x2.f32 %0, %1, %2;" : "=r"(hi) : "f"(x1), "f"(x0));
    float h0 = __int_as_float(hi << 16);
    float h1 = __int_as_float(hi & 0xFFFF0000u);
    asm("cvt.rn.bf16x2.f32 %0, %1, %2;" : "=r"(lo) : "f"(x1 - h1), "f"(x0 - h0));
}
__device__ __forceinline__ uint32_t packbf1(float x0, float x1) {
    uint32_t hi;
    asm("cvt.rn.bf16x2.f32 %0, %1, %2;" : "=r"(hi) : "f"(x1), "f"(x0));
    return hi;
}
__device__ __forceinline__ void packhf2(float x0, float x1, uint32_t& hi, uint32_t& lo) {
    __half2 h = __floats2half2_rn(x0, x1);
    hi = *reinterpret_cast<uint32_t*>(&h);
    float2 hf = __half22float2(h);
    __half2 l = __floats2half2_rn(x0 - hf.x, x1 - hf.y);
    lo = *reinterpret_cast<uint32_t*>(&l);
}
__device__ __forceinline__ uint32_t packh(float x0, float x1) {
    __half2 h = __floats2half2_rn(x0, x1);
    return *reinterpret_cast<uint32_t*>(&h);
}
// exp2 on the fma pipe; valid for z <= 0 (clamped at -80)
__device__ __forceinline__ float exp2_fast(float z) {
    z = fmaxf(z, -80.f);
    float fm = z + 12582912.f;
    int i = __float_as_int(fm) - 0x4B400000;
    float f = z - (fm - 12582912.f);
    float p = 1.333356e-3f;
    p = fmaf(p, f, 9.618129e-3f);
    p = fmaf(p, f, 5.5504109e-2f);
    p = fmaf(p, f, 2.40226507e-1f);
    p = fmaf(p, f, 6.93147181e-1f);
    p = fmaf(p, f, 1.0f);
    return p * __int_as_float((i + 127) << 23);
}

// ---------------------------------------------------------------------------
// 0) key-side resonance precompute
// ---------------------------------------------------------------------------
__global__ __launch_bounds__(256) void lkg_kernel(const float* __restrict__ phase,
                                                  const float* __restrict__ cph,
                                                  const float* __restrict__ bal) {
    int bh = blockIdx.y, b = bh >> 4, h = bh & 15;
    int s = blockIdx.x * 256 + threadIdx.x;
    float bv  = bal[0];
    float tau = fminf(fmaxf(1.0f / (2.0f * bv + 1e-8f), 0.1f), 10.0f);
    float itau = 1.0f / tau;
    float cc = cosf((phase[(size_t)b * S_ + s] - cph[h]) * 0.5f);
    g_lk[(size_t)bh * S_ + s] = log2f(cc * cc + 1e-6f) * itau;
}

// ---------------------------------------------------------------------------
// 1) LayerNorm -> hi/lo bf16
// ---------------------------------------------------------------------------
__global__ __launch_bounds__(256) void ln_kernel(const float* __restrict__ x,
                                                 const float* __restrict__ gamma,
                                                 const float* __restrict__ beta) {
    int row = blockIdx.x;
    const float* xr = x + (size_t)row * D_;
    float v[4];
    float s = 0.f, s2 = 0.f;
#pragma unroll
    for (int i = 0; i < 4; i++) {
        v[i] = xr[threadIdx.x + i * 256];
        s += v[i]; s2 += v[i] * v[i];
    }
#pragma unroll
    for (int o = 16; o; o >>= 1) {
        s  += __shfl_xor_sync(0xffffffffu, s,  o);
        s2 += __shfl_xor_sync(0xffffffffu, s2, o);
    }
    __shared__ float red[16];
    int w = threadIdx.x >> 5;
    if ((threadIdx.x & 31) == 0) { red[w] = s; red[w + 8] = s2; }
    __syncthreads();
    float ts = 0.f, ts2 = 0.f;
#pragma unroll
    for (int i = 0; i < 8; i++) { ts += red[i]; ts2 += red[i + 8]; }
    float mean = ts * (1.0f / D_);
    float var  = ts2 * (1.0f / D_) - mean * mean;
    float rstd = rsqrtf(var + 1e-5f);
#pragma unroll
    for (int i = 0; i < 4; i++) {
        int c = threadIdx.x + i * 256;
        float hv = (v[i] - mean) * rstd * gamma[c] + beta[c];
        __nv_bfloat16 hb = __float2bfloat16(hv);
        g_h_hi[(size_t)row * D_ + c] = hb;
        g_h_lo[(size_t)row * D_ + c] = __float2bfloat16(hv - __bfloat162float(hb));
    }
}

// ---------------------------------------------------------------------------
// 2) Weight transpose+convert (all 4 weights, blockIdx.z selects)
// ---------------------------------------------------------------------------
__global__ __launch_bounds__(256) void wconv_kernel(const float* __restrict__ W0,
                                                    const float* __restrict__ W1,
                                                    const float* __restrict__ W2,
                                                    const float* __restrict__ W3) {
    __shared__ float tl[32][33];
    int wz = blockIdx.z;
    const float* W = (wz == 0) ? W0 : (wz == 1) ? W1 : (wz == 2) ? W2 : W3;
    __nv_bfloat16* Thi = g_wt_hi[wz];
    __nv_bfloat16* Tlo = g_wt_lo[wz];
    int n0 = blockIdx.x * 32, k0 = blockIdx.y * 32;
    int tx = threadIdx.x, ty = threadIdx.y;
#pragma unroll
    for (int j = 0; j < 4; j++)
        tl[ty + j * 8][tx] = W[(size_t)(k0 + ty + j * 8) * D_ + n0 + tx];
    __syncthreads();
#pragma unroll
    for (int j = 0; j < 4; j++) {
        int n = n0 + ty + j * 8;
        float v = tl[tx][ty + j * 8];
        __nv_bfloat16 hb = __float2bfloat16(v);
        Thi[(size_t)n * D_ + k0 + tx] = hb;
        Tlo[(size_t)n * D_ + k0 + tx] = __float2bfloat16(v - __bfloat162float(hb));
    }
}

// ---------------------------------------------------------------------------
// 3) HMMA GEMM, 3-stage cp.async pipeline, single sync/chunk, 128x64, BK=32
// ---------------------------------------------------------------------------
#define BK    32
#define NCHUNK (D_/BK)
#define G_AH  0
#define G_AL  10240
#define G_BH  20480
#define G_BL  25600
#define G_STG 30720
#define GEMM_SMEM (3*G_STG)

__global__ __launch_bounds__(256) void gemm_mma_kernel(
        const __nv_bfloat16* __restrict__ Ahi, const __nv_bfloat16* __restrict__ Alo,
        const float* __restrict__ exps, const float* __restrict__ x,
        float* __restrict__ y, int which) {
    extern __shared__ __align__(128) char gsm[];
    uint32_t sb = smem_u32(gsm);
    int we = (which < 0) ? (int)blockIdx.z : which;
    const __nv_bfloat16* __restrict__ Bhi = g_wt_hi[we];
    const __nv_bfloat16* __restrict__ Blo = g_wt_lo[we];

    int t = threadIdx.x, lane = t & 31, wid = t >> 5;
    int wm = wid & 3, wn = wid >> 2;
    int m0 = blockIdx.y * 128, n0 = blockIdx.x * 64;
    float acc[2][4][4] = {};

    auto fill = [&](int kc, int buf) {
        int k0 = kc * BK;
        uint32_t bo = sb + buf * G_STG;
#pragma unroll
        for (int i = 0; i < 2; i++) {
            int idx = t + i * 256;
            int row = idx >> 2, seg = idx & 3;
            uint32_t d = bo + row * 80 + seg * 16;
            size_t go = (size_t)(m0 + row) * D_ + k0 + seg * 8;
            cpa16(d + G_AH, Ahi + go);
            cpa16(d + G_AL, Alo + go);
        }
        {
            int row = t >> 2, seg = t & 3;
            uint32_t d = bo + row * 80 + seg * 16;
            size_t go = (size_t)(n0 + row) * D_ + k0 + seg * 8;
            cpa16(d + G_BH, Bhi + go);
            cpa16(d + G_BL, Blo + go);
        }
    };

    fill(0, 0); CP_COMMIT();
    fill(1, 1); CP_COMMIT();

    for (int kc = 0; kc < NCHUNK; kc++) {
        if (kc + 1 < NCHUNK) { CP_WAIT1(); } else { CP_WAIT0(); }
        __syncthreads();
        if (kc + 2 < NCHUNK) { fill(kc + 2, (kc + 2) % 3); CP_COMMIT(); }
        uint32_t bo = sb + (kc % 3) * G_STG;
#pragma unroll
        for (int ks = 0; ks < BK; ks += 16) {
            uint32_t ah[2][4], al[2][4], bh[2][4], bl[2][4];
#pragma unroll
            for (int mi = 0; mi < 2; mi++) {
                int ar = wm * 32 + mi * 16 + (lane & 15);
                int ac = ks + ((lane >> 4) << 3);
                ldsm4(ah[mi], bo + G_AH + ar * 80 + ac * 2);
                ldsm4(al[mi], bo + G_AL + ar * 80 + ac * 2);
            }
#pragma unroll
            for (int p = 0; p < 2; p++) {
                int br = wn * 32 + p * 16 + (lane & 7) + ((lane & 16) ? 8 : 0);
                int bc = ks + ((lane & 8) ? 8 : 0);
                ldsm4(bh[p], bo + G_BH + br * 80 + bc * 2);
                ldsm4(bl[p], bo + G_BL + br * 80 + bc * 2);
            }
#pragma unroll
            for (int mi = 0; mi < 2; mi++)
#pragma unroll
                for (int nj = 0; nj < 4; nj++) {
                    const uint32_t* fbh = &bh[nj >> 1][(nj & 1) * 2];
                    const uint32_t* fbl = &bl[nj >> 1][(nj & 1) * 2];
                    mma_bf(acc[mi][nj], ah[mi], fbh);
                    mma_bf(acc[mi][nj], ah[mi], fbl);
                    mma_bf(acc[mi][nj], al[mi], fbh);
                }
        }
    }

    int head = blockIdx.x;
    float e = (we == 1 || we == 2) ? exps[head] : 0.f;
#pragma unroll
    for (int mi = 0; mi < 2; mi++)
#pragma unroll
        for (int nj = 0; nj < 4; nj++)
#pragma unroll
            for (int h2 = 0; h2 < 2; h2++) {
                int m = m0 + wm * 32 + mi * 16 + (lane >> 2) + h2 * 8;
                int nc = wn * 32 + nj * 8 + (lane & 3) * 2;
                float v0 = acc[mi][nj][h2 * 2];
                float v1 = acc[mi][nj][h2 * 2 + 1];
                if (which < 0) {
                    if (we != 0) {
                        float mg0 = fmaxf(fabsf(v0), 1e-8f);
                        float r0 = exp2f(e * log2f(mg0));
                        v0 = (v0 > 0.f) ? r0 : (v0 < 0.f ? -r0 : 0.f);
                        float mg1 = fmaxf(fabsf(v1), 1e-8f);
                        float r1 = exp2f(e * log2f(mg1));
                        v1 = (v1 > 0.f) ? r1 : (v1 < 0.f ? -r1 : 0.f);
                    }
                    int b = m >> 11, s = m & (S_ - 1);
                    size_t off = (((size_t)b * H_ + head) * S_ + s) * DH_ + nc;
                    uint32_t hi, lo;
                    if (we == 2) {
                        packhf2(v0, v1, hi, lo);
                        *(uint32_t*)&g_v_hi[off] = hi;
                        *(uint32_t*)&g_v_lo[off] = lo;
                    } else if (we == 1) {
                        packbf2(v0, v1, hi, lo);
                        *(uint32_t*)&g_k_hi[off] = hi;
                        *(uint32_t*)&g_k_lo[off] = lo;
                    } else {
                        *(uint32_t*)&g_q_hi[off] = packbf1(v0, v1);
                    }
                } else {
                    size_t off = (size_t)m * D_ + n0 + nc;
                    float2 xr = *(const float2*)(x + off);
                    *(float2*)(y + off) = make_float2(xr.x + v0, xr.y + v1);
                }
            }
}

// ---------------------------------------------------------------------------
// 4) HMMA flash attention: 128 q-rows/CTA, 64-key tiles, 3-stage, 1 sync/tile
// ---------------------------------------------------------------------------
#define APAD_B 144
#define A_KH 0
#define A_KL 9216
#define A_VH 18432
#define A_VL 27648
#define ABUF 36864
#define A_LKO (3*ABUF)
#define ATT_SMEM (3*ABUF + 3*256)

__global__ __launch_bounds__(256, 2) void attn_kernel(const float* __restrict__ phase,
                                                      const float* __restrict__ cph,
                                                      const float* __restrict__ bal) {
    extern __shared__ __align__(128) char asmem[];
    uint32_t sb = smem_u32(asmem);

    int t = threadIdx.x, lane = t & 31, w = t >> 5;
    int bh = blockIdx.y, b = bh >> 4, h = bh & 15;
    int qt = blockIdx.x, m0 = qt * 128;
    int wr0 = m0 + w * 16;
    int r = lane >> 2, c = lane & 3;
    int nkt = 2 * qt + 2;

    float bv  = bal[0];
    float tau = fminf(fmaxf(1.0f / (2.0f * bv + 1e-8f), 0.1f), 10.0f);
    float itau = 1.0f / tau;
    float qscl = 0.125f * itau * 1.44269504f;
    float cp   = cph[h];

    uint32_t qh[4][4];
    {
        const __nv_bfloat16* qhp = g_q_hi + ((size_t)bh * S_ + wr0) * DH_;
#pragma unroll
        for (int ks = 0; ks < 4; ks++) {
            int k0 = ks * 16 + 2 * c;
            qh[ks][0] = *(const uint32_t*)(qhp + (size_t)r * DH_ + k0);
            qh[ks][1] = *(const uint32_t*)(qhp + (size_t)(r + 8) * DH_ + k0);
            qh[ks][2] = *(const uint32_t*)(qhp + (size_t)r * DH_ + k0 + 8);
            qh[ks][3] = *(const uint32_t*)(qhp + (size_t)(r + 8) * DH_ + k0 + 8);
        }
    }

    float o[8][4] = {};
    float mx[2] = {-1e30f, -1e30f}, lsum[2] = {0.f, 0.f};

#define LOAD_TILE(kt_, st_) do {                                               \
    int kb_ = (kt_) * 64;                                                      \
    uint32_t bo_ = sb + (st_) * ABUF;                                          \
    size_t gb_ = ((size_t)bh * S_ + kb_) * DH_;                                \
    _Pragma("unroll")                                                          \
    for (int i_ = 0; i_ < 2; i_++) {                                           \
        int idx_ = t + i_ * 256;                                               \
        int row_ = idx_ >> 3, seg_ = idx_ & 7;                                 \
        uint32_t d_ = bo_ + row_ * APAD_B + seg_ * 16;                         \
        size_t go_ = gb_ + (size_t)row_ * DH_ + seg_ * 8;                      \
        cpa16(d_ + A_KH, g_k_hi + go_);                                        \
        cpa16(d_ + A_KL, g_k_lo + go_);                                        \
        cpa16(d_ + A_VH, g_v_hi + go_);                                        \
        cpa16(d_ + A_VL, g_v_lo + go_);                                        \
    }                                                                          \
    if (t < 16)                                                                \
        cpa16(sb + A_LKO + (st_) * 256 + t * 16,                               \
              g_lk + (size_t)bh * S_ + kb_ + t * 4);                           \
} while (0)

    LOAD_TILE(0, 0); CP_COMMIT();
    LOAD_TILE(1, 1); CP_COMMIT();

    for (int kt = 0; kt < nkt; kt++) {
        int kb = kt * 64;
        if (kt + 1 < nkt) { CP_WAIT1(); } else { CP_WAIT0(); }
        __syncthreads();
        if (kt + 2 < nkt) { LOAD_TILE(kt + 2, (kt + 2) % 3); CP_COMMIT(); }

        if (kb <= wr0 + 15) {
            uint32_t bo = sb + (kt % 3) * ABUF;
            const float* lkp = (const float*)(asmem + A_LKO + (kt % 3) * 256);
            float s[8][4];
#pragma unroll
            for (int nj = 0; nj < 8; nj++)
                s[nj][0] = s[nj][1] = s[nj][2] = s[nj][3] = 0.f;
#pragma unroll
            for (int ks = 0; ks < 4; ks++)
#pragma unroll
                for (int ng = 0; ng < 4; ng++) {
                    uint32_t kh4[4], kl4[4];
                    int srow = ng * 16 + (lane & 7) + ((lane & 16) ? 8 : 0);
                    int scol = ks * 16 + ((lane & 8) ? 8 : 0);
                    ldsm4(kh4, bo + A_KH + srow * APAD_B + scol * 2);
                    ldsm4(kl4, bo + A_KL + srow * APAD_B + scol * 2);
                    mma_bf(s[2 * ng], qh[ks], &kh4[0]);
                    mma_bf(s[2 * ng], qh[ks], &kl4[0]);
                    mma_bf(s[2 * ng + 1], qh[ks], &kh4[2]);
                    mma_bf(s[2 * ng + 1], qh[ks], &kl4[2]);
                }

            bool needmask = (kb + 63 > wr0);
            float tmax[2] = {-1e30f, -1e30f};
#pragma unroll
            for (int nj = 0; nj < 8; nj++) {
                int key0 = kb + nj * 8 + 2 * c;
                float l0 = lkp[nj * 8 + 2 * c], l1 = lkp[nj * 8 + 2 * c + 1];
#pragma unroll
                for (int e = 0; e < 4; e++) {
                    float z = s[nj][e] * qscl + ((e & 1) ? l1 : l0);
                    if (needmask) {
                        int qrow = wr0 + r + ((e >> 1) ? 8 : 0);
                        if (key0 + (e & 1) > qrow) z = -1e30f;
                    }
                    s[nj][e] = z;
                    int half = e >> 1;
                    tmax[half] = fmaxf(tmax[half], z);
                }
            }
#pragma unroll
            for (int i = 0; i < 2; i++) {
                tmax[i] = fmaxf(tmax[i], __shfl_xor_sync(0xffffffffu, tmax[i], 1));
                tmax[i] = fmaxf(tmax[i], __shfl_xor_sync(0xffffffffu, tmax[i], 2));
            }
            float alpha[2], rsum[2] = {0.f, 0.f};
#pragma unroll
            for (int i = 0; i < 2; i++) {
                float mn = fmaxf(mx[i], tmax[i]);
                alpha[i] = exp2_fast(mx[i] - mn);
                mx[i] = mn;
            }
#pragma unroll
            for (int nj = 0; nj < 8; nj++)
#pragma unroll
                for (int e = 0; e < 4; e++) {
                    int half = e >> 1;
                    float p = exp2_fast(s[nj][e] - mx[half]);
                    s[nj][e] = p;
                    rsum[half] += p;
                }
#pragma unroll
            for (int i = 0; i < 2; i++) {
                rsum[i] += __shfl_xor_sync(0xffffffffu, rsum[i], 1);
                rsum[i] += __shfl_xor_sync(0xffffffffu, rsum[i], 2);
                lsum[i] = lsum[i] * alpha[i] + rsum[i];
            }
#pragma unroll
            for (int nj = 0; nj < 8; nj++) {
                o[nj][0] *= alpha[0]; o[nj][1] *= alpha[0];
                o[nj][2] *= alpha[1]; o[nj][3] *= alpha[1];
            }
            uint32_t pa[4][4];
#pragma unroll
            for (int ks = 0; ks < 4; ks++) {
                pa[ks][0] = packh(s[2 * ks][0], s[2 * ks][1]);
                pa[ks][1] = packh(s[2 * ks][2], s[2 * ks][3]);
                pa[ks][2] = packh(s[2 * ks + 1][0], s[2 * ks + 1][1]);
                pa[ks][3] = packh(s[2 * ks + 1][2], s[2 * ks + 1][3]);
            }
#pragma unroll
            for (int ng = 0; ng < 4; ng++)
#pragma unroll
                for (int ks = 0; ks < 4; ks++) {
                    uint32_t vh4[4], vl4[4];
                    int srow = ks * 16 + (lane & 7) + ((lane & 8) ? 8 : 0);
                    int scol = ng * 16 + ((lane & 16) ? 8 : 0);
                    ldsm4t(vh4, bo + A_VH + srow * APAD_B + scol * 2);
                    ldsm4t(vl4, bo + A_VL + srow * APAD_B + scol * 2);
                    mma_hf(o[2 * ng],     pa[ks], &vh4[0]);
                    mma_hf(o[2 * ng],     pa[ks], &vl4[0]);
                    mma_hf(o[2 * ng + 1], pa[ks], &vh4[2]);
                    mma_hf(o[2 * ng + 1], pa[ks], &vl4[2]);
                }
        }
    }

    float g[2];
#pragma unroll
    for (int i = 0; i < 2; i++) {
        int srow = wr0 + r + i * 8;
        float ph = phase[(size_t)b * S_ + srow];
        float cq = cosf((ph - cp) * 0.5f);
        g[i] = (cq * cq) / lsum[i];
    }
#pragma unroll
    for (int nj = 0; nj < 8; nj++)
#pragma unroll
        for (int i = 0; i < 2; i++) {
            int srow = wr0 + r + i * 8;
            size_t off = ((size_t)b * S_ + srow) * D_ + h * DH_ + nj * 8 + 2 * c;
            uint32_t hi, lo;
            packbf2(o[nj][i * 2] * g[i], o[nj][i * 2 + 1] * g[i], hi, lo);
            *(uint32_t*)&g_ao_hi[off] = hi;
            *(uint32_t*)&g_ao_lo[off] = lo;
        }
}

// ---------------------------------------------------------------------------
extern "C" void kernel_launch(void* const* d_in, const int* in_sizes, int n_in,
                              void* d_out, int out_size) {
    const float* x     = (const float*)d_in[0];
    const float* phase = (const float*)d_in[1];
    const float* Wq    = (const float*)d_in[2];
    const float* Wk    = (const float*)d_in[3];
    const float* Wv    = (const float*)d_in[4];
    const float* Wo    = (const float*)d_in[5];
    const float* gamma = (const float*)d_in[6];
    const float* beta  = (const float*)d_in[7];
    const float* exps  = (const float*)d_in[8];
    const float* cph   = (const float*)d_in[9];
    const float* bal   = (const float*)d_in[10];
    float* y = (float*)d_out;

    static __nv_bfloat16 *hhi, *hlo, *aohi, *aolo;
    static bool got = false;
    if (!got) {
        cudaGetSymbolAddress((void**)&hhi, g_h_hi);
        cudaGetSymbolAddress((void**)&hlo, g_h_lo);
        cudaGetSymbolAddress((void**)&aohi, g_ao_hi);
        cudaGetSymbolAddress((void**)&aolo, g_ao_lo);
        cudaFuncSetAttribute((const void*)attn_kernel,
                             cudaFuncAttributeMaxDynamicSharedMemorySize, ATT_SMEM);
        cudaFuncSetAttribute((const void*)gemm_mma_kernel,
                             cudaFuncAttributeMaxDynamicSharedMemorySize, GEMM_SMEM);
        got = true;
    }

    ln_kernel<<<M_, 256>>>(x, gamma, beta);
    lkg_kernel<<<dim3(S_ / 256, B_ * H_), 256>>>(phase, cph, bal);

    wconv_kernel<<<dim3(32, 32, 4), dim3(32, 8)>>>(Wq, Wk, Wv, Wo);

    gemm_mma_kernel<<<dim3(D_ / 64, M_ / 128, 3), 256, GEMM_SMEM>>>(
        hhi, hlo, exps, x, y, -1);

    attn_kernel<<<dim3(S_ / 128, B_ * H_), 256, ATT_SMEM>>>(phase, cph, bal);

    gemm_mma_kernel<<<dim3(D_ / 64, M_ / 128, 1), 256, GEMM_SMEM>>>(
        aohi, aolo, exps, x, y, 3);
}

// round 14
// speedup vs baseline: 3.8018x; 1.3770x over previous
#include <cuda_runtime.h>
#include <cuda_bf16.h>
#include <cuda_fp16.h>
#include <math.h>
#include <stdint.h>

#define B_  2
#define S_  2048
#define D_  1024
#define H_  16
#define DH_ 64
#define M_  (B_*S_)

// ---------------------------------------------------------------------------
// Scratch (all fp16 now)
// ---------------------------------------------------------------------------
__device__ __half g_h  [M_*D_];            // LN out, single fp16
__device__ __half g_wt_hi[4][D_*D_];       // transposed weights [N][K]
__device__ __half g_wt_lo[4][D_*D_];
__device__ __half g_q  [M_*D_];            // (B,H,S,DH) single
__device__ __half g_k  [M_*D_];            // single
__device__ __half g_v_hi[M_*D_];
__device__ __half g_v_lo[M_*D_];
__device__ __half g_ao [M_*D_];            // (B,S,D) single
__device__ float  g_lk [B_*H_*S_];         // key-side log2-resonance / tau

// ---------------------------------------------------------------------------
// helpers
// ---------------------------------------------------------------------------
__device__ __forceinline__ uint32_t smem_u32(const void* p) {
    uint32_t a;
    asm("{ .reg .u64 t; cvta.to.shared.u64 t, %1; cvt.u32.u64 %0, t; }"
        : "=r"(a) : "l"(p));
    return a;
}
__device__ __forceinline__ void ldsm4(uint32_t* r, uint32_t addr) {
    asm volatile("ldmatrix.sync.aligned.m8n8.x4.shared.b16 {%0,%1,%2,%3}, [%4];"
                 : "=r"(r[0]), "=r"(r[1]), "=r"(r[2]), "=r"(r[3]) : "r"(addr));
}
__device__ __forceinline__ void ldsm4t(uint32_t* r, uint32_t addr) {
    asm volatile("ldmatrix.sync.aligned.m8n8.x4.trans.shared.b16 {%0,%1,%2,%3}, [%4];"
                 : "=r"(r[0]), "=r"(r[1]), "=r"(r[2]), "=r"(r[3]) : "r"(addr));
}
__device__ __forceinline__ void mma_hf(float* c, const uint32_t* a, const uint32_t* b) {
    asm volatile(
        "mma.sync.aligned.m16n8k16.row.col.f32.f16.f16.f32 "
        "{%0,%1,%2,%3}, {%4,%5,%6,%7}, {%8,%9}, {%0,%1,%2,%3};"
        : "+f"(c[0]), "+f"(c[1]), "+f"(c[2]), "+f"(c[3])
        : "r"(a[0]), "r"(a[1]), "r"(a[2]), "r"(a[3]), "r"(b[0]), "r"(b[1]));
}
__device__ __forceinline__ void cpa16(uint32_t smaddr, const void* g) {
    asm volatile("cp.async.cg.shared.global [%0], [%1], 16;"
                 :: "r"(smaddr), "l"(__cvta_generic_to_global(g)));
}
#define CP_COMMIT() asm volatile("cp.async.commit_group;" ::: "memory")
#define CP_WAIT1()  asm volatile("cp.async.wait_group 1;" ::: "memory")
#define CP_WAIT0()  asm volatile("cp.async.wait_group 0;" ::: "memory")

__device__ __forceinline__ void packhf2(float x0, float x1, uint32_t& hi, uint32_t& lo) {
    __half2 h = __floats2half2_rn(x0, x1);
    hi = *reinterpret_cast<uint32_t*>(&h);
    float2 hf = __half22float2(h);
    __half2 l = __floats2half2_rn(x0 - hf.x, x1 - hf.y);
    lo = *reinterpret_cast<uint32_t*>(&l);
}
__device__ __forceinline__ uint32_t packh(float x0, float x1) {
    __half2 h = __floats2half2_rn(x0, x1);
    return *reinterpret_cast<uint32_t*>(&h);
}
// exp2 on the fma pipe; valid for z <= 0 (clamped at -80)
__device__ __forceinline__ float exp2_fast(float z) {
    z = fmaxf(z, -80.f);
    float fm = z + 12582912.f;
    int i = __float_as_int(fm) - 0x4B400000;
    float f = z - (fm - 12582912.f);
    float p = 1.333356e-3f;
    p = fmaf(p, f, 9.618129e-3f);
    p = fmaf(p, f, 5.5504109e-2f);
    p = fmaf(p, f, 2.40226507e-1f);
    p = fmaf(p, f, 6.93147181e-1f);
    p = fmaf(p, f, 1.0f);
    return p * __int_as_float((i + 127) << 23);
}

// ---------------------------------------------------------------------------
// 0) key-side resonance precompute
// ---------------------------------------------------------------------------
__global__ __launch_bounds__(256) void lkg_kernel(const float* __restrict__ phase,
                                                  const float* __restrict__ cph,
                                                  const float* __restrict__ bal) {
    int bh = blockIdx.y, b = bh >> 4, h = bh & 15;
    int s = blockIdx.x * 256 + threadIdx.x;
    float bv  = bal[0];
    float tau = fminf(fmaxf(1.0f / (2.0f * bv + 1e-8f), 0.1f), 10.0f);
    float itau = 1.0f / tau;
    float cc = cosf((phase[(size_t)b * S_ + s] - cph[h]) * 0.5f);
    g_lk[(size_t)bh * S_ + s] = log2f(cc * cc + 1e-6f) * itau;
}

// ---------------------------------------------------------------------------
// 1) LayerNorm -> single fp16
// ---------------------------------------------------------------------------
__global__ __launch_bounds__(256) void ln_kernel(const float* __restrict__ x,
                                                 const float* __restrict__ gamma,
                                                 const float* __restrict__ beta) {
    int row = blockIdx.x;
    const float* xr = x + (size_t)row * D_;
    float v[4];
    float s = 0.f, s2 = 0.f;
#pragma unroll
    for (int i = 0; i < 4; i++) {
        v[i] = xr[threadIdx.x + i * 256];
        s += v[i]; s2 += v[i] * v[i];
    }
#pragma unroll
    for (int o = 16; o; o >>= 1) {
        s  += __shfl_xor_sync(0xffffffffu, s,  o);
        s2 += __shfl_xor_sync(0xffffffffu, s2, o);
    }
    __shared__ float red[16];
    int w = threadIdx.x >> 5;
    if ((threadIdx.x & 31) == 0) { red[w] = s; red[w + 8] = s2; }
    __syncthreads();
    float ts = 0.f, ts2 = 0.f;
#pragma unroll
    for (int i = 0; i < 8; i++) { ts += red[i]; ts2 += red[i + 8]; }
    float mean = ts * (1.0f / D_);
    float var  = ts2 * (1.0f / D_) - mean * mean;
    float rstd = rsqrtf(var + 1e-5f);
#pragma unroll
    for (int i = 0; i < 4; i++) {
        int c = threadIdx.x + i * 256;
        float hv = (v[i] - mean) * rstd * gamma[c] + beta[c];
        g_h[(size_t)row * D_ + c] = __float2half(hv);
    }
}

// ---------------------------------------------------------------------------
// 2) Weight transpose+convert -> fp16 hi/lo
// ---------------------------------------------------------------------------
__global__ __launch_bounds__(256) void wconv_kernel(const float* __restrict__ W0,
                                                    const float* __restrict__ W1,
                                                    const float* __restrict__ W2,
                                                    const float* __restrict__ W3) {
    __shared__ float tl[32][33];
    int wz = blockIdx.z;
    const float* W = (wz == 0) ? W0 : (wz == 1) ? W1 : (wz == 2) ? W2 : W3;
    __half* Thi = g_wt_hi[wz];
    __half* Tlo = g_wt_lo[wz];
    int n0 = blockIdx.x * 32, k0 = blockIdx.y * 32;
    int tx = threadIdx.x, ty = threadIdx.y;
#pragma unroll
    for (int j = 0; j < 4; j++)
        tl[ty + j * 8][tx] = W[(size_t)(k0 + ty + j * 8) * D_ + n0 + tx];
    __syncthreads();
#pragma unroll
    for (int j = 0; j < 4; j++) {
        int n = n0 + ty + j * 8;
        float v = tl[tx][ty + j * 8];
        __half hb = __float2half(v);
        Thi[(size_t)n * D_ + k0 + tx] = hb;
        Tlo[(size_t)n * D_ + k0 + tx] = __float2half(v - __half2float(hb));
    }
}

// ---------------------------------------------------------------------------
// 3) fp16 HMMA GEMM, 2-stage cp.async, A single / B hi+lo, 2 mma terms
// ---------------------------------------------------------------------------
#define BK    32
#define NCHUNK (D_/BK)
#define G_AH  0
#define G_BH  10240
#define G_BL  15360
#define G_STG 20480
#define GEMM_SMEM (2*G_STG)

__global__ __launch_bounds__(256) void gemm_mma_kernel(
        const __half* __restrict__ Ah,
        const float* __restrict__ exps, const float* __restrict__ x,
        float* __restrict__ y, int which) {
    extern __shared__ __align__(128) char gsm[];
    uint32_t sb = smem_u32(gsm);
    int we = (which < 0) ? (int)blockIdx.z : which;
    const __half* __restrict__ Bhi = g_wt_hi[we];
    const __half* __restrict__ Blo = g_wt_lo[we];

    int t = threadIdx.x, lane = t & 31, wid = t >> 5;
    int wm = wid & 3, wn = wid >> 2;
    int m0 = blockIdx.y * 128, n0 = blockIdx.x * 64;
    float acc[2][4][4] = {};

    auto fill = [&](int kc, int buf) {
        int k0 = kc * BK;
        uint32_t bo = sb + buf * G_STG;
#pragma unroll
        for (int i = 0; i < 2; i++) {
            int idx = t + i * 256;
            int row = idx >> 2, seg = idx & 3;
            cpa16(bo + G_AH + row * 80 + seg * 16,
                  Ah + (size_t)(m0 + row) * D_ + k0 + seg * 8);
        }
        {
            int row = t >> 2, seg = t & 3;
            uint32_t d = bo + row * 80 + seg * 16;
            size_t go = (size_t)(n0 + row) * D_ + k0 + seg * 8;
            cpa16(d + G_BH, Bhi + go);
            cpa16(d + G_BL, Blo + go);
        }
    };

    fill(0, 0); CP_COMMIT();
    fill(1, 1); CP_COMMIT();

    for (int kc = 0; kc < NCHUNK; kc++) {
        if (kc + 1 < NCHUNK) { CP_WAIT1(); } else { CP_WAIT0(); }
        __syncthreads();
        uint32_t bo = sb + (kc & 1) * G_STG;
#pragma unroll
        for (int ks = 0; ks < BK; ks += 16) {
            uint32_t ah[2][4], bh[2][4], bl[2][4];
#pragma unroll
            for (int mi = 0; mi < 2; mi++) {
                int ar = wm * 32 + mi * 16 + (lane & 15);
                int ac = ks + ((lane >> 4) << 3);
                ldsm4(ah[mi], bo + G_AH + ar * 80 + ac * 2);
            }
#pragma unroll
            for (int p = 0; p < 2; p++) {
                int br = wn * 32 + p * 16 + (lane & 7) + ((lane & 16) ? 8 : 0);
                int bc = ks + ((lane & 8) ? 8 : 0);
                ldsm4(bh[p], bo + G_BH + br * 80 + bc * 2);
                ldsm4(bl[p], bo + G_BL + br * 80 + bc * 2);
            }
#pragma unroll
            for (int mi = 0; mi < 2; mi++)
#pragma unroll
                for (int nj = 0; nj < 4; nj++) {
                    const uint32_t* fbh = &bh[nj >> 1][(nj & 1) * 2];
                    const uint32_t* fbl = &bl[nj >> 1][(nj & 1) * 2];
                    mma_hf(acc[mi][nj], ah[mi], fbh);
                    mma_hf(acc[mi][nj], ah[mi], fbl);
                }
        }
        __syncthreads();
        if (kc + 2 < NCHUNK) { fill(kc + 2, kc & 1); CP_COMMIT(); }
    }

    int head = blockIdx.x;
    float e = (we == 1 || we == 2) ? exps[head] : 0.f;
#pragma unroll
    for (int mi = 0; mi < 2; mi++)
#pragma unroll
        for (int nj = 0; nj < 4; nj++)
#pragma unroll
            for (int h2 = 0; h2 < 2; h2++) {
                int m = m0 + wm * 32 + mi * 16 + (lane >> 2) + h2 * 8;
                int nc = wn * 32 + nj * 8 + (lane & 3) * 2;
                float v0 = acc[mi][nj][h2 * 2];
                float v1 = acc[mi][nj][h2 * 2 + 1];
                if (which < 0) {
                    if (we != 0) {
                        float mg0 = fmaxf(fabsf(v0), 1e-8f);
                        float r0 = exp2f(e * log2f(mg0));
                        v0 = (v0 > 0.f) ? r0 : (v0 < 0.f ? -r0 : 0.f);
                        float mg1 = fmaxf(fabsf(v1), 1e-8f);
                        float r1 = exp2f(e * log2f(mg1));
                        v1 = (v1 > 0.f) ? r1 : (v1 < 0.f ? -r1 : 0.f);
                    }
                    int b = m >> 11, s = m & (S_ - 1);
                    size_t off = (((size_t)b * H_ + head) * S_ + s) * DH_ + nc;
                    if (we == 2) {
                        uint32_t hi, lo;
                        packhf2(v0, v1, hi, lo);
                        *(uint32_t*)&g_v_hi[off] = hi;
                        *(uint32_t*)&g_v_lo[off] = lo;
                    } else if (we == 1) {
                        *(uint32_t*)&g_k[off] = packh(v0, v1);
                    } else {
                        *(uint32_t*)&g_q[off] = packh(v0, v1);
                    }
                } else {
                    size_t off = (size_t)m * D_ + n0 + nc;
                    float2 xr = *(const float2*)(x + off);
                    *(float2*)(y + off) = make_float2(xr.x + v0, xr.y + v1);
                }
            }
}

// ---------------------------------------------------------------------------
// 4) fp16 HMMA flash attention: q,k single; v hi/lo; 3-stage; big-first
// ---------------------------------------------------------------------------
#define APAD_B 144
#define A_KH 0
#define A_VH 9216
#define A_VL 18432
#define ABUF 27648
#define A_LKO (3*ABUF)
#define ATT_SMEM (3*ABUF + 3*256)

__global__ __launch_bounds__(256, 2) void attn_kernel(const float* __restrict__ phase,
                                                      const float* __restrict__ cph,
                                                      const float* __restrict__ bal) {
    extern __shared__ __align__(128) char asmem[];
    uint32_t sb = smem_u32(asmem);

    int t = threadIdx.x, lane = t & 31, w = t >> 5;
    int bh = blockIdx.y, b = bh >> 4, h = bh & 15;
    int qt = gridDim.x - 1 - blockIdx.x;      // big-first scheduling
    int m0 = qt * 128;
    int wr0 = m0 + w * 16;
    int r = lane >> 2, c = lane & 3;
    int nkt = 2 * qt + 2;

    float bv  = bal[0];
    float tau = fminf(fmaxf(1.0f / (2.0f * bv + 1e-8f), 0.1f), 10.0f);
    float itau = 1.0f / tau;
    float qscl = 0.125f * itau * 1.44269504f;
    float cp   = cph[h];

    uint32_t qh[4][4];
    {
        const __half* qp = g_q + ((size_t)bh * S_ + wr0) * DH_;
#pragma unroll
        for (int ks = 0; ks < 4; ks++) {
            int k0 = ks * 16 + 2 * c;
            qh[ks][0] = *(const uint32_t*)(qp + (size_t)r * DH_ + k0);
            qh[ks][1] = *(const uint32_t*)(qp + (size_t)(r + 8) * DH_ + k0);
            qh[ks][2] = *(const uint32_t*)(qp + (size_t)r * DH_ + k0 + 8);
            qh[ks][3] = *(const uint32_t*)(qp + (size_t)(r + 8) * DH_ + k0 + 8);
        }
    }

    float o[8][4] = {};
    float mx[2] = {-1e30f, -1e30f}, lsum[2] = {0.f, 0.f};

#define LOAD_TILE(kt_, st_) do {                                               \
    int kb_ = (kt_) * 64;                                                      \
    uint32_t bo_ = sb + (st_) * ABUF;                                          \
    size_t gb_ = ((size_t)bh * S_ + kb_) * DH_;                                \
    _Pragma("unroll")                                                          \
    for (int i_ = 0; i_ < 2; i_++) {                                           \
        int idx_ = t + i_ * 256;                                               \
        int row_ = idx_ >> 3, seg_ = idx_ & 7;                                 \
        uint32_t d_ = bo_ + row_ * APAD_B + seg_ * 16;                         \
        size_t go_ = gb_ + (size_t)row_ * DH_ + seg_ * 8;                      \
        cpa16(d_ + A_KH, g_k + go_);                                           \
        cpa16(d_ + A_VH, g_v_hi + go_);                                        \
        cpa16(d_ + A_VL, g_v_lo + go_);                                        \
    }                                                                          \
    if (t < 16)                                                                \
        cpa16(sb + A_LKO + (st_) * 256 + t * 16,                               \
              g_lk + (size_t)bh * S_ + kb_ + t * 4);                           \
} while (0)

    LOAD_TILE(0, 0); CP_COMMIT();
    LOAD_TILE(1, 1); CP_COMMIT();

    for (int kt = 0; kt < nkt; kt++) {
        int kb = kt * 64;
        if (kt + 1 < nkt) { CP_WAIT1(); } else { CP_WAIT0(); }
        __syncthreads();
        if (kt + 2 < nkt) { LOAD_TILE(kt + 2, (kt + 2) % 3); CP_COMMIT(); }

        if (kb <= wr0 + 15) {
            uint32_t bo = sb + (kt % 3) * ABUF;
            const float* lkp = (const float*)(asmem + A_LKO + (kt % 3) * 256);
            float s[8][4];
#pragma unroll
            for (int nj = 0; nj < 8; nj++)
                s[nj][0] = s[nj][1] = s[nj][2] = s[nj][3] = 0.f;
#pragma unroll
            for (int ks = 0; ks < 4; ks++)
#pragma unroll
                for (int ng = 0; ng < 4; ng++) {
                    uint32_t kh4[4];
                    int srow = ng * 16 + (lane & 7) + ((lane & 16) ? 8 : 0);
                    int scol = ks * 16 + ((lane & 8) ? 8 : 0);
                    ldsm4(kh4, bo + A_KH + srow * APAD_B + scol * 2);
                    mma_hf(s[2 * ng],     qh[ks], &kh4[0]);
                    mma_hf(s[2 * ng + 1], qh[ks], &kh4[2]);
                }

            bool needmask = (kb + 63 > wr0);
            float tmax[2] = {-1e30f, -1e30f};
#pragma unroll
            for (int nj = 0; nj < 8; nj++) {
                int key0 = kb + nj * 8 + 2 * c;
                float l0 = lkp[nj * 8 + 2 * c], l1 = lkp[nj * 8 + 2 * c + 1];
#pragma unroll
                for (int e = 0; e < 4; e++) {
                    float z = s[nj][e] * qscl + ((e & 1) ? l1 : l0);
                    if (needmask) {
                        int qrow = wr0 + r + ((e >> 1) ? 8 : 0);
                        if (key0 + (e & 1) > qrow) z = -1e30f;
                    }
                    s[nj][e] = z;
                    int half = e >> 1;
                    tmax[half] = fmaxf(tmax[half], z);
                }
            }
#pragma unroll
            for (int i = 0; i < 2; i++) {
                tmax[i] = fmaxf(tmax[i], __shfl_xor_sync(0xffffffffu, tmax[i], 1));
                tmax[i] = fmaxf(tmax[i], __shfl_xor_sync(0xffffffffu, tmax[i], 2));
            }
            float alpha[2], rsum[2] = {0.f, 0.f};
#pragma unroll
            for (int i = 0; i < 2; i++) {
                float mn = fmaxf(mx[i], tmax[i]);
                alpha[i] = exp2_fast(mx[i] - mn);
                mx[i] = mn;
            }
#pragma unroll
            for (int nj = 0; nj < 8; nj++)
#pragma unroll
                for (int e = 0; e < 4; e++) {
                    int half = e >> 1;
                    float p = exp2_fast(s[nj][e] - mx[half]);
                    s[nj][e] = p;
                    rsum[half] += p;
                }
#pragma unroll
            for (int i = 0; i < 2; i++) {
                rsum[i] += __shfl_xor_sync(0xffffffffu, rsum[i], 1);
                rsum[i] += __shfl_xor_sync(0xffffffffu, rsum[i], 2);
                lsum[i] = lsum[i] * alpha[i] + rsum[i];
            }
#pragma unroll
            for (int nj = 0; nj < 8; nj++) {
                o[nj][0] *= alpha[0]; o[nj][1] *= alpha[0];
                o[nj][2] *= alpha[1]; o[nj][3] *= alpha[1];
            }
            uint32_t pa[4][4];
#pragma unroll
            for (int ks = 0; ks < 4; ks++) {
                pa[ks][0] = packh(s[2 * ks][0], s[2 * ks][1]);
                pa[ks][1] = packh(s[2 * ks][2], s[2 * ks][3]);
                pa[ks][2] = packh(s[2 * ks + 1][0], s[2 * ks + 1][1]);
                pa[ks][3] = packh(s[2 * ks + 1][2], s[2 * ks + 1][3]);
            }
#pragma unroll
            for (int ng = 0; ng < 4; ng++)
#pragma unroll
                for (int ks = 0; ks < 4; ks++) {
                    uint32_t vh4[4], vl4[4];
                    int srow = ks * 16 + (lane & 7) + ((lane & 8) ? 8 : 0);
                    int scol = ng * 16 + ((lane & 16) ? 8 : 0);
                    ldsm4t(vh4, bo + A_VH + srow * APAD_B + scol * 2);
                    ldsm4t(vl4, bo + A_VL + srow * APAD_B + scol * 2);
                    mma_hf(o[2 * ng],     pa[ks], &vh4[0]);
                    mma_hf(o[2 * ng],     pa[ks], &vl4[0]);
                    mma_hf(o[2 * ng + 1], pa[ks], &vh4[2]);
                    mma_hf(o[2 * ng + 1], pa[ks], &vl4[2]);
                }
        }
    }

    float g[2];
#pragma unroll
    for (int i = 0; i < 2; i++) {
        int srow = wr0 + r + i * 8;
        float ph = phase[(size_t)b * S_ + srow];
        float cq = cosf((ph - cp) * 0.5f);
        g[i] = (cq * cq) / lsum[i];
    }
#pragma unroll
    for (int nj = 0; nj < 8; nj++)
#pragma unroll
        for (int i = 0; i < 2; i++) {
            int srow = wr0 + r + i * 8;
            size_t off = ((size_t)b * S_ + srow) * D_ + h * DH_ + nj * 8 + 2 * c;
            *(uint32_t*)&g_ao[off] = packh(o[nj][i * 2] * g[i],
                                           o[nj][i * 2 + 1] * g[i]);
        }
}

// ---------------------------------------------------------------------------
extern "C" void kernel_launch(void* const* d_in, const int* in_sizes, int n_in,
                              void* d_out, int out_size) {
    const float* x     = (const float*)d_in[0];
    const float* phase = (const float*)d_in[1];
    const float* Wq    = (const float*)d_in[2];
    const float* Wk    = (const float*)d_in[3];
    const float* Wv    = (const float*)d_in[4];
    const float* Wo    = (const float*)d_in[5];
    const float* gamma = (const float*)d_in[6];
    const float* beta  = (const float*)d_in[7];
    const float* exps  = (const float*)d_in[8];
    const float* cph   = (const float*)d_in[9];
    const float* bal   = (const float*)d_in[10];
    float* y = (float*)d_out;

    static __half *hh, *aoh;
    static bool got = false;
    if (!got) {
        cudaGetSymbolAddress((void**)&hh, g_h);
        cudaGetSymbolAddress((void**)&aoh, g_ao);
        cudaFuncSetAttribute((const void*)attn_kernel,
                             cudaFuncAttributeMaxDynamicSharedMemorySize, ATT_SMEM);
        cudaFuncSetAttribute((const void*)gemm_mma_kernel,
                             cudaFuncAttributeMaxDynamicSharedMemorySize, GEMM_SMEM);
        got = true;
    }

    ln_kernel<<<M_, 256>>>(x, gamma, beta);
    lkg_kernel<<<dim3(S_ / 256, B_ * H_), 256>>>(phase, cph, bal);

    wconv_kernel<<<dim3(32, 32, 4), dim3(32, 8)>>>(Wq, Wk, Wv, Wo);

    gemm_mma_kernel<<<dim3(D_ / 64, M_ / 128, 3), 256, GEMM_SMEM>>>(
        hh, exps, x, y, -1);

    attn_kernel<<<dim3(S_ / 128, B_ * H_), 256, ATT_SMEM>>>(phase, cph, bal);

    gemm_mma_kernel<<<dim3(D_ / 64, M_ / 128, 1), 256, GEMM_SMEM>>>(
        aoh, exps, x, y, 3);
}

// round 15
// speedup vs baseline: 4.1117x; 1.0815x over previous
#include <cuda_runtime.h>
#include <cuda_bf16.h>
#include <cuda_fp16.h>
#include <math.h>
#include <stdint.h>

#define B_  2
#define S_  2048
#define D_  1024
#define H_  16
#define DH_ 64
#define M_  (B_*S_)

// ---------------------------------------------------------------------------
// Scratch (all fp16)
// ---------------------------------------------------------------------------
__device__ __half g_h  [M_*D_];            // LN out, single fp16
__device__ __half g_wt_hi[4][D_*D_];       // transposed weights [N][K]
__device__ __half g_wt_lo[4][D_*D_];
__device__ __half g_q  [M_*D_];            // (B,H,S,DH) single
__device__ __half g_k  [M_*D_];            // single
__device__ __half g_v_hi[M_*D_];
__device__ __half g_v_lo[M_*D_];
__device__ __half g_ao [M_*D_];            // (B,S,D) single
__device__ float  g_lk [B_*H_*S_];         // key-side log2-resonance / tau

// ---------------------------------------------------------------------------
// helpers
// ---------------------------------------------------------------------------
__device__ __forceinline__ uint32_t smem_u32(const void* p) {
    uint32_t a;
    asm("{ .reg .u64 t; cvta.to.shared.u64 t, %1; cvt.u32.u64 %0, t; }"
        : "=r"(a) : "l"(p));
    return a;
}
__device__ __forceinline__ void ldsm4(uint32_t* r, uint32_t addr) {
    asm volatile("ldmatrix.sync.aligned.m8n8.x4.shared.b16 {%0,%1,%2,%3}, [%4];"
                 : "=r"(r[0]), "=r"(r[1]), "=r"(r[2]), "=r"(r[3]) : "r"(addr));
}
__device__ __forceinline__ void ldsm4t(uint32_t* r, uint32_t addr) {
    asm volatile("ldmatrix.sync.aligned.m8n8.x4.trans.shared.b16 {%0,%1,%2,%3}, [%4];"
                 : "=r"(r[0]), "=r"(r[1]), "=r"(r[2]), "=r"(r[3]) : "r"(addr));
}
__device__ __forceinline__ void mma_hf(float* c, const uint32_t* a, const uint32_t* b) {
    asm volatile(
        "mma.sync.aligned.m16n8k16.row.col.f32.f16.f16.f32 "
        "{%0,%1,%2,%3}, {%4,%5,%6,%7}, {%8,%9}, {%0,%1,%2,%3};"
        : "+f"(c[0]), "+f"(c[1]), "+f"(c[2]), "+f"(c[3])
        : "r"(a[0]), "r"(a[1]), "r"(a[2]), "r"(a[3]), "r"(b[0]), "r"(b[1]));
}
__device__ __forceinline__ void cpa16(uint32_t smaddr, const void* g) {
    asm volatile("cp.async.cg.shared.global [%0], [%1], 16;"
                 :: "r"(smaddr), "l"(__cvta_generic_to_global(g)));
}
#define CP_COMMIT() asm volatile("cp.async.commit_group;" ::: "memory")
#define CP_WAIT1()  asm volatile("cp.async.wait_group 1;" ::: "memory")
#define CP_WAIT0()  asm volatile("cp.async.wait_group 0;" ::: "memory")

__device__ __forceinline__ void packhf2(float x0, float x1, uint32_t& hi, uint32_t& lo) {
    __half2 h = __floats2half2_rn(x0, x1);
    hi = *reinterpret_cast<uint32_t*>(&h);
    float2 hf = __half22float2(h);
    __half2 l = __floats2half2_rn(x0 - hf.x, x1 - hf.y);
    lo = *reinterpret_cast<uint32_t*>(&l);
}
__device__ __forceinline__ uint32_t packh(float x0, float x1) {
    __half2 h = __floats2half2_rn(x0, x1);
    return *reinterpret_cast<uint32_t*>(&h);
}
// exp2 on the fma pipe; valid for z <= 0 (clamped at -80)
__device__ __forceinline__ float exp2_fast(float z) {
    z = fmaxf(z, -80.f);
    float fm = z + 12582912.f;
    int i = __float_as_int(fm) - 0x4B400000;
    float f = z - (fm - 12582912.f);
    float p = 1.333356e-3f;
    p = fmaf(p, f, 9.618129e-3f);
    p = fmaf(p, f, 5.5504109e-2f);
    p = fmaf(p, f, 2.40226507e-1f);
    p = fmaf(p, f, 6.93147181e-1f);
    p = fmaf(p, f, 1.0f);
    return p * __int_as_float((i + 127) << 23);
}

// ---------------------------------------------------------------------------
// 0) key-side resonance precompute
// ---------------------------------------------------------------------------
__global__ __launch_bounds__(256) void lkg_kernel(const float* __restrict__ phase,
                                                  const float* __restrict__ cph,
                                                  const float* __restrict__ bal) {
    int bh = blockIdx.y, b = bh >> 4, h = bh & 15;
    int s = blockIdx.x * 256 + threadIdx.x;
    float bv  = bal[0];
    float tau = fminf(fmaxf(1.0f / (2.0f * bv + 1e-8f), 0.1f), 10.0f);
    float itau = 1.0f / tau;
    float cc = cosf((phase[(size_t)b * S_ + s] - cph[h]) * 0.5f);
    g_lk[(size_t)bh * S_ + s] = log2f(cc * cc + 1e-6f) * itau;
}

// ---------------------------------------------------------------------------
// 1) LayerNorm -> single fp16
// ---------------------------------------------------------------------------
__global__ __launch_bounds__(256) void ln_kernel(const float* __restrict__ x,
                                                 const float* __restrict__ gamma,
                                                 const float* __restrict__ beta) {
    int row = blockIdx.x;
    const float* xr = x + (size_t)row * D_;
    float v[4];
    float s = 0.f, s2 = 0.f;
#pragma unroll
    for (int i = 0; i < 4; i++) {
        v[i] = xr[threadIdx.x + i * 256];
        s += v[i]; s2 += v[i] * v[i];
    }
#pragma unroll
    for (int o = 16; o; o >>= 1) {
        s  += __shfl_xor_sync(0xffffffffu, s,  o);
        s2 += __shfl_xor_sync(0xffffffffu, s2, o);
    }
    __shared__ float red[16];
    int w = threadIdx.x >> 5;
    if ((threadIdx.x & 31) == 0) { red[w] = s; red[w + 8] = s2; }
    __syncthreads();
    float ts = 0.f, ts2 = 0.f;
#pragma unroll
    for (int i = 0; i < 8; i++) { ts += red[i]; ts2 += red[i + 8]; }
    float mean = ts * (1.0f / D_);
    float var  = ts2 * (1.0f / D_) - mean * mean;
    float rstd = rsqrtf(var + 1e-5f);
#pragma unroll
    for (int i = 0; i < 4; i++) {
        int c = threadIdx.x + i * 256;
        float hv = (v[i] - mean) * rstd * gamma[c] + beta[c];
        g_h[(size_t)row * D_ + c] = __float2half(hv);
    }
}

// ---------------------------------------------------------------------------
// 2) Weight transpose+convert -> fp16 hi/lo
// ---------------------------------------------------------------------------
__global__ __launch_bounds__(256) void wconv_kernel(const float* __restrict__ W0,
                                                    const float* __restrict__ W1,
                                                    const float* __restrict__ W2,
                                                    const float* __restrict__ W3) {
    __shared__ float tl[32][33];
    int wz = blockIdx.z;
    const float* W = (wz == 0) ? W0 : (wz == 1) ? W1 : (wz == 2) ? W2 : W3;
    __half* Thi = g_wt_hi[wz];
    __half* Tlo = g_wt_lo[wz];
    int n0 = blockIdx.x * 32, k0 = blockIdx.y * 32;
    int tx = threadIdx.x, ty = threadIdx.y;
#pragma unroll
    for (int j = 0; j < 4; j++)
        tl[ty + j * 8][tx] = W[(size_t)(k0 + ty + j * 8) * D_ + n0 + tx];
    __syncthreads();
#pragma unroll
    for (int j = 0; j < 4; j++) {
        int n = n0 + ty + j * 8;
        float v = tl[tx][ty + j * 8];
        __half hb = __float2half(v);
        Thi[(size_t)n * D_ + k0 + tx] = hb;
        Tlo[(size_t)n * D_ + k0 + tx] = __float2half(v - __half2float(hb));
    }
}

// ---------------------------------------------------------------------------
// 3) fp16 HMMA GEMM, 2-stage cp.async, 128x64, BK=32
//    QKV (which<0): A single x B single (1 mma term)
//    out-proj (which==3): A single x B hi+lo (2 mma terms)
// ---------------------------------------------------------------------------
#define BK    32
#define NCHUNK (D_/BK)
#define G_AH  0
#define G_BH  10240
#define G_BL  15360
#define G_STG 20480
#define GEMM_SMEM (2*G_STG)

__global__ __launch_bounds__(256, 4) void gemm_mma_kernel(
        const __half* __restrict__ Ah,
        const float* __restrict__ exps, const float* __restrict__ x,
        float* __restrict__ y, int which) {
    extern __shared__ __align__(128) char gsm[];
    uint32_t sb = smem_u32(gsm);
    int we = (which < 0) ? (int)blockIdx.z : which;
    const bool doLo = (which == 3);
    const __half* __restrict__ Bhi = g_wt_hi[we];
    const __half* __restrict__ Blo = g_wt_lo[we];

    int t = threadIdx.x, lane = t & 31, wid = t >> 5;
    int wm = wid & 3, wn = wid >> 2;
    int m0 = blockIdx.y * 128, n0 = blockIdx.x * 64;
    float acc[2][4][4] = {};

    auto fill = [&](int kc, int buf) {
        int k0 = kc * BK;
        uint32_t bo = sb + buf * G_STG;
#pragma unroll
        for (int i = 0; i < 2; i++) {
            int idx = t + i * 256;
            int row = idx >> 2, seg = idx & 3;
            cpa16(bo + G_AH + row * 80 + seg * 16,
                  Ah + (size_t)(m0 + row) * D_ + k0 + seg * 8);
        }
        {
            int row = t >> 2, seg = t & 3;
            uint32_t d = bo + row * 80 + seg * 16;
            size_t go = (size_t)(n0 + row) * D_ + k0 + seg * 8;
            cpa16(d + G_BH, Bhi + go);
            if (doLo) cpa16(d + G_BL, Blo + go);
        }
    };

    fill(0, 0); CP_COMMIT();
    fill(1, 1); CP_COMMIT();

    for (int kc = 0; kc < NCHUNK; kc++) {
        if (kc + 1 < NCHUNK) { CP_WAIT1(); } else { CP_WAIT0(); }
        __syncthreads();
        uint32_t bo = sb + (kc & 1) * G_STG;
#pragma unroll
        for (int ks = 0; ks < BK; ks += 16) {
            uint32_t ah[2][4], bh[2][4], bl[2][4];
#pragma unroll
            for (int mi = 0; mi < 2; mi++) {
                int ar = wm * 32 + mi * 16 + (lane & 15);
                int ac = ks + ((lane >> 4) << 3);
                ldsm4(ah[mi], bo + G_AH + ar * 80 + ac * 2);
            }
#pragma unroll
            for (int p = 0; p < 2; p++) {
                int br = wn * 32 + p * 16 + (lane & 7) + ((lane & 16) ? 8 : 0);
                int bc = ks + ((lane & 8) ? 8 : 0);
                ldsm4(bh[p], bo + G_BH + br * 80 + bc * 2);
                if (doLo) ldsm4(bl[p], bo + G_BL + br * 80 + bc * 2);
            }
#pragma unroll
            for (int mi = 0; mi < 2; mi++)
#pragma unroll
                for (int nj = 0; nj < 4; nj++) {
                    const uint32_t* fbh = &bh[nj >> 1][(nj & 1) * 2];
                    mma_hf(acc[mi][nj], ah[mi], fbh);
                    if (doLo) {
                        const uint32_t* fbl = &bl[nj >> 1][(nj & 1) * 2];
                        mma_hf(acc[mi][nj], ah[mi], fbl);
                    }
                }
        }
        __syncthreads();
        if (kc + 2 < NCHUNK) { fill(kc + 2, kc & 1); CP_COMMIT(); }
    }

    int head = blockIdx.x;
    float e = (we == 1 || we == 2) ? exps[head] : 0.f;
#pragma unroll
    for (int mi = 0; mi < 2; mi++)
#pragma unroll
        for (int nj = 0; nj < 4; nj++)
#pragma unroll
            for (int h2 = 0; h2 < 2; h2++) {
                int m = m0 + wm * 32 + mi * 16 + (lane >> 2) + h2 * 8;
                int nc = wn * 32 + nj * 8 + (lane & 3) * 2;
                float v0 = acc[mi][nj][h2 * 2];
                float v1 = acc[mi][nj][h2 * 2 + 1];
                if (which < 0) {
                    if (we != 0) {
                        float mg0 = fmaxf(fabsf(v0), 1e-8f);
                        float r0 = exp2f(e * log2f(mg0));
                        v0 = (v0 > 0.f) ? r0 : (v0 < 0.f ? -r0 : 0.f);
                        float mg1 = fmaxf(fabsf(v1), 1e-8f);
                        float r1 = exp2f(e * log2f(mg1));
                        v1 = (v1 > 0.f) ? r1 : (v1 < 0.f ? -r1 : 0.f);
                    }
                    int b = m >> 11, s = m & (S_ - 1);
                    size_t off = (((size_t)b * H_ + head) * S_ + s) * DH_ + nc;
                    if (we == 2) {
                        uint32_t hi, lo;
                        packhf2(v0, v1, hi, lo);
                        *(uint32_t*)&g_v_hi[off] = hi;
                        *(uint32_t*)&g_v_lo[off] = lo;
                    } else if (we == 1) {
                        *(uint32_t*)&g_k[off] = packh(v0, v1);
                    } else {
                        *(uint32_t*)&g_q[off] = packh(v0, v1);
                    }
                } else {
                    size_t off = (size_t)m * D_ + n0 + nc;
                    float2 xr = *(const float2*)(x + off);
                    *(float2*)(y + off) = make_float2(xr.x + v0, xr.y + v1);
                }
            }
}

// ---------------------------------------------------------------------------
// 4) fp16 HMMA flash attention: q,k single; v hi/lo; 3-stage; big-first
// ---------------------------------------------------------------------------
#define APAD_B 144
#define A_KH 0
#define A_VH 9216
#define A_VL 18432
#define ABUF 27648
#define A_LKO (3*ABUF)
#define ATT_SMEM (3*ABUF + 3*256)

__global__ __launch_bounds__(256, 2) void attn_kernel(const float* __restrict__ phase,
                                                      const float* __restrict__ cph,
                                                      const float* __restrict__ bal) {
    extern __shared__ __align__(128) char asmem[];
    uint32_t sb = smem_u32(asmem);

    int t = threadIdx.x, lane = t & 31, w = t >> 5;
    int bh = blockIdx.y, b = bh >> 4, h = bh & 15;
    int qt = gridDim.x - 1 - blockIdx.x;      // big-first scheduling
    int m0 = qt * 128;
    int wr0 = m0 + w * 16;
    int r = lane >> 2, c = lane & 3;
    int nkt = 2 * qt + 2;

    float bv  = bal[0];
    float tau = fminf(fmaxf(1.0f / (2.0f * bv + 1e-8f), 0.1f), 10.0f);
    float itau = 1.0f / tau;
    float qscl = 0.125f * itau * 1.44269504f;
    float cp   = cph[h];

    uint32_t qh[4][4];
    {
        const __half* qp = g_q + ((size_t)bh * S_ + wr0) * DH_;
#pragma unroll
        for (int ks = 0; ks < 4; ks++) {
            int k0 = ks * 16 + 2 * c;
            qh[ks][0] = *(const uint32_t*)(qp + (size_t)r * DH_ + k0);
            qh[ks][1] = *(const uint32_t*)(qp + (size_t)(r + 8) * DH_ + k0);
            qh[ks][2] = *(const uint32_t*)(qp + (size_t)r * DH_ + k0 + 8);
            qh[ks][3] = *(const uint32_t*)(qp + (size_t)(r + 8) * DH_ + k0 + 8);
        }
    }

    float o[8][4] = {};
    float mx[2] = {-1e30f, -1e30f}, lsum[2] = {0.f, 0.f};

#define LOAD_TILE(kt_, st_) do {                                               \
    int kb_ = (kt_) * 64;                                                      \
    uint32_t bo_ = sb + (st_) * ABUF;                                          \
    size_t gb_ = ((size_t)bh * S_ + kb_) * DH_;                                \
    _Pragma("unroll")                                                          \
    for (int i_ = 0; i_ < 2; i_++) {                                           \
        int idx_ = t + i_ * 256;                                               \
        int row_ = idx_ >> 3, seg_ = idx_ & 7;                                 \
        uint32_t d_ = bo_ + row_ * APAD_B + seg_ * 16;                         \
        size_t go_ = gb_ + (size_t)row_ * DH_ + seg_ * 8;                      \
        cpa16(d_ + A_KH, g_k + go_);                                           \
        cpa16(d_ + A_VH, g_v_hi + go_);                                        \
        cpa16(d_ + A_VL, g_v_lo + go_);                                        \
    }                                                                          \
    if (t < 16)                                                                \
        cpa16(sb + A_LKO + (st_) * 256 + t * 16,                               \
              g_lk + (size_t)bh * S_ + kb_ + t * 4);                           \
} while (0)

    LOAD_TILE(0, 0); CP_COMMIT();
    LOAD_TILE(1, 1); CP_COMMIT();

    for (int kt = 0; kt < nkt; kt++) {
        int kb = kt * 64;
        if (kt + 1 < nkt) { CP_WAIT1(); } else { CP_WAIT0(); }
        __syncthreads();
        if (kt + 2 < nkt) { LOAD_TILE(kt + 2, (kt + 2) % 3); CP_COMMIT(); }

        if (kb <= wr0 + 15) {
            uint32_t bo = sb + (kt % 3) * ABUF;
            const float* lkp = (const float*)(asmem + A_LKO + (kt % 3) * 256);
            float s[8][4];
#pragma unroll
            for (int nj = 0; nj < 8; nj++)
                s[nj][0] = s[nj][1] = s[nj][2] = s[nj][3] = 0.f;
#pragma unroll
            for (int ks = 0; ks < 4; ks++)
#pragma unroll
                for (int ng = 0; ng < 4; ng++) {
                    uint32_t kh4[4];
                    int srow = ng * 16 + (lane & 7) + ((lane & 16) ? 8 : 0);
                    int scol = ks * 16 + ((lane & 8) ? 8 : 0);
                    ldsm4(kh4, bo + A_KH + srow * APAD_B + scol * 2);
                    mma_hf(s[2 * ng],     qh[ks], &kh4[0]);
                    mma_hf(s[2 * ng + 1], qh[ks], &kh4[2]);
                }

            bool needmask = (kb + 63 > wr0);
            float tmax[2] = {-1e30f, -1e30f};
#pragma unroll
            for (int nj = 0; nj < 8; nj++) {
                int key0 = kb + nj * 8 + 2 * c;
                float l0 = lkp[nj * 8 + 2 * c], l1 = lkp[nj * 8 + 2 * c + 1];
#pragma unroll
                for (int e = 0; e < 4; e++) {
                    float z = s[nj][e] * qscl + ((e & 1) ? l1 : l0);
                    if (needmask) {
                        int qrow = wr0 + r + ((e >> 1) ? 8 : 0);
                        if (key0 + (e & 1) > qrow) z = -1e30f;
                    }
                    s[nj][e] = z;
                    int half = e >> 1;
                    tmax[half] = fmaxf(tmax[half], z);
                }
            }
#pragma unroll
            for (int i = 0; i < 2; i++) {
                tmax[i] = fmaxf(tmax[i], __shfl_xor_sync(0xffffffffu, tmax[i], 1));
                tmax[i] = fmaxf(tmax[i], __shfl_xor_sync(0xffffffffu, tmax[i], 2));
            }
            float alpha[2], rsum[2] = {0.f, 0.f};
#pragma unroll
            for (int i = 0; i < 2; i++) {
                float mn = fmaxf(mx[i], tmax[i]);
                alpha[i] = exp2_fast(mx[i] - mn);
                mx[i] = mn;
            }
#pragma unroll
            for (int nj = 0; nj < 8; nj++)
#pragma unroll
                for (int e = 0; e < 4; e++) {
                    int half = e >> 1;
                    float p = exp2_fast(s[nj][e] - mx[half]);
                    s[nj][e] = p;
                    rsum[half] += p;
                }
#pragma unroll
            for (int i = 0; i < 2; i++) {
                rsum[i] += __shfl_xor_sync(0xffffffffu, rsum[i], 1);
                rsum[i] += __shfl_xor_sync(0xffffffffu, rsum[i], 2);
                lsum[i] = lsum[i] * alpha[i] + rsum[i];
            }
#pragma unroll
            for (int nj = 0; nj < 8; nj++) {
                o[nj][0] *= alpha[0]; o[nj][1] *= alpha[0];
                o[nj][2] *= alpha[1]; o[nj][3] *= alpha[1];
            }
            uint32_t pa[4][4];
#pragma unroll
            for (int ks = 0; ks < 4; ks++) {
                pa[ks][0] = packh(s[2 * ks][0], s[2 * ks][1]);
                pa[ks][1] = packh(s[2 * ks][2], s[2 * ks][3]);
                pa[ks][2] = packh(s[2 * ks + 1][0], s[2 * ks + 1][1]);
                pa[ks][3] = packh(s[2 * ks + 1][2], s[2 * ks + 1][3]);
            }
#pragma unroll
            for (int ng = 0; ng < 4; ng++)
#pragma unroll
                for (int ks = 0; ks < 4; ks++) {
                    uint32_t vh4[4], vl4[4];
                    int srow = ks * 16 + (lane & 7) + ((lane & 8) ? 8 : 0);
                    int scol = ng * 16 + ((lane & 16) ? 8 : 0);
                    ldsm4t(vh4, bo + A_VH + srow * APAD_B + scol * 2);
                    ldsm4t(vl4, bo + A_VL + srow * APAD_B + scol * 2);
                    mma_hf(o[2 * ng],     pa[ks], &vh4[0]);
                    mma_hf(o[2 * ng],     pa[ks], &vl4[0]);
                    mma_hf(o[2 * ng + 1], pa[ks], &vh4[2]);
                    mma_hf(o[2 * ng + 1], pa[ks], &vl4[2]);
                }
        }
    }

    float g[2];
#pragma unroll
    for (int i = 0; i < 2; i++) {
        int srow = wr0 + r + i * 8;
        float ph = phase[(size_t)b * S_ + srow];
        float cq = cosf((ph - cp) * 0.5f);
        g[i] = (cq * cq) / lsum[i];
    }
#pragma unroll
    for (int nj = 0; nj < 8; nj++)
#pragma unroll
        for (int i = 0; i < 2; i++) {
            int srow = wr0 + r + i * 8;
            size_t off = ((size_t)b * S_ + srow) * D_ + h * DH_ + nj * 8 + 2 * c;
            *(uint32_t*)&g_ao[off] = packh(o[nj][i * 2] * g[i],
                                           o[nj][i * 2 + 1] * g[i]);
        }
}

// ---------------------------------------------------------------------------
extern "C" void kernel_launch(void* const* d_in, const int* in_sizes, int n_in,
                              void* d_out, int out_size) {
    const float* x     = (const float*)d_in[0];
    const float* phase = (const float*)d_in[1];
    const float* Wq    = (const float*)d_in[2];
    const float* Wk    = (const float*)d_in[3];
    const float* Wv    = (const float*)d_in[4];
    const float* Wo    = (const float*)d_in[5];
    const float* gamma = (const float*)d_in[6];
    const float* beta  = (const float*)d_in[7];
    const float* exps  = (const float*)d_in[8];
    const float* cph   = (const float*)d_in[9];
    const float* bal   = (const float*)d_in[10];
    float* y = (float*)d_out;

    static __half *hh, *aoh;
    static bool got = false;
    if (!got) {
        cudaGetSymbolAddress((void**)&hh, g_h);
        cudaGetSymbolAddress((void**)&aoh, g_ao);
        cudaFuncSetAttribute((const void*)attn_kernel,
                             cudaFuncAttributeMaxDynamicSharedMemorySize, ATT_SMEM);
        cudaFuncSetAttribute((const void*)gemm_mma_kernel,
                             cudaFuncAttributeMaxDynamicSharedMemorySize, GEMM_SMEM);
        got = true;
    }

    ln_kernel<<<M_, 256>>>(x, gamma, beta);
    lkg_kernel<<<dim3(S_ / 256, B_ * H_), 256>>>(phase, cph, bal);

    wconv_kernel<<<dim3(32, 32, 4), dim3(32, 8)>>>(Wq, Wk, Wv, Wo);

    gemm_mma_kernel<<<dim3(D_ / 64, M_ / 128, 3), 256, GEMM_SMEM>>>(
        hh, exps, x, y, -1);

    attn_kernel<<<dim3(S_ / 128, B_ * H_), 256, ATT_SMEM>>>(phase, cph, bal);

    gemm_mma_kernel<<<dim3(D_ / 64, M_ / 128, 1), 256, GEMM_SMEM>>>(
        aoh, exps, x, y, 3);
}

// round 16
// speedup vs baseline: 4.9558x; 1.2053x over previous
#include <cuda_runtime.h>
#include <cuda_bf16.h>
#include <cuda_fp16.h>
#include <math.h>
#include <stdint.h>

#define B_  2
#define S_  2048
#define D_  1024
#define H_  16
#define DH_ 64
#define M_  (B_*S_)

// ---------------------------------------------------------------------------
// Scratch (all fp16)
// ---------------------------------------------------------------------------
__device__ __half g_h  [M_*D_];            // LN out, single fp16
__device__ __half g_wt_hi[4][D_*D_];       // transposed weights [N][K]
__device__ __half g_wt_lo[4][D_*D_];
__device__ __half g_q  [M_*D_];            // (B,H,S,DH) single
__device__ __half g_k  [M_*D_];            // single
__device__ __half g_v  [M_*D_];            // single
__device__ __half g_ao [M_*D_];            // (B,S,D) single
__device__ float  g_lk [B_*H_*S_];         // key-side log2-resonance / tau

// ---------------------------------------------------------------------------
// helpers
// ---------------------------------------------------------------------------
__device__ __forceinline__ uint32_t smem_u32(const void* p) {
    uint32_t a;
    asm("{ .reg .u64 t; cvta.to.shared.u64 t, %1; cvt.u32.u64 %0, t; }"
        : "=r"(a) : "l"(p));
    return a;
}
__device__ __forceinline__ void ldsm4(uint32_t* r, uint32_t addr) {
    asm volatile("ldmatrix.sync.aligned.m8n8.x4.shared.b16 {%0,%1,%2,%3}, [%4];"
                 : "=r"(r[0]), "=r"(r[1]), "=r"(r[2]), "=r"(r[3]) : "r"(addr));
}
__device__ __forceinline__ void ldsm4t(uint32_t* r, uint32_t addr) {
    asm volatile("ldmatrix.sync.aligned.m8n8.x4.trans.shared.b16 {%0,%1,%2,%3}, [%4];"
                 : "=r"(r[0]), "=r"(r[1]), "=r"(r[2]), "=r"(r[3]) : "r"(addr));
}
__device__ __forceinline__ void mma_hf(float* c, const uint32_t* a, const uint32_t* b) {
    asm volatile(
        "mma.sync.aligned.m16n8k16.row.col.f32.f16.f16.f32 "
        "{%0,%1,%2,%3}, {%4,%5,%6,%7}, {%8,%9}, {%0,%1,%2,%3};"
        : "+f"(c[0]), "+f"(c[1]), "+f"(c[2]), "+f"(c[3])
        : "r"(a[0]), "r"(a[1]), "r"(a[2]), "r"(a[3]), "r"(b[0]), "r"(b[1]));
}
__device__ __forceinline__ void cpa16(uint32_t smaddr, const void* g) {
    asm volatile("cp.async.cg.shared.global [%0], [%1], 16;"
                 :: "r"(smaddr), "l"(__cvta_generic_to_global(g)));
}
#define CP_COMMIT() asm volatile("cp.async.commit_group;" ::: "memory")
#define CP_WAIT1()  asm volatile("cp.async.wait_group 1;" ::: "memory")
#define CP_WAIT0()  asm volatile("cp.async.wait_group 0;" ::: "memory")

__device__ __forceinline__ uint32_t packh(float x0, float x1) {
    __half2 h = __floats2half2_rn(x0, x1);
    return *reinterpret_cast<uint32_t*>(&h);
}
// exp2 on the fma pipe; valid for z <= 0 (clamped at -80)
__device__ __forceinline__ float exp2_fast(float z) {
    z = fmaxf(z, -80.f);
    float fm = z + 12582912.f;
    int i = __float_as_int(fm) - 0x4B400000;
    float f = z - (fm - 12582912.f);
    float p = 1.333356e-3f;
    p = fmaf(p, f, 9.618129e-3f);
    p = fmaf(p, f, 5.5504109e-2f);
    p = fmaf(p, f, 2.40226507e-1f);
    p = fmaf(p, f, 6.93147181e-1f);
    p = fmaf(p, f, 1.0f);
    return p * __int_as_float((i + 127) << 23);
}

// ---------------------------------------------------------------------------
// 0) key-side resonance precompute
// ---------------------------------------------------------------------------
__global__ __launch_bounds__(256) void lkg_kernel(const float* __restrict__ phase,
                                                  const float* __restrict__ cph,
                                                  const float* __restrict__ bal) {
    int bh = blockIdx.y, b = bh >> 4, h = bh & 15;
    int s = blockIdx.x * 256 + threadIdx.x;
    float bv  = bal[0];
    float tau = fminf(fmaxf(1.0f / (2.0f * bv + 1e-8f), 0.1f), 10.0f);
    float itau = 1.0f / tau;
    float cc = cosf((phase[(size_t)b * S_ + s] - cph[h]) * 0.5f);
    g_lk[(size_t)bh * S_ + s] = log2f(cc * cc + 1e-6f) * itau;
}

// ---------------------------------------------------------------------------
// 1) LayerNorm -> single fp16
// ---------------------------------------------------------------------------
__global__ __launch_bounds__(256) void ln_kernel(const float* __restrict__ x,
                                                 const float* __restrict__ gamma,
                                                 const float* __restrict__ beta) {
    int row = blockIdx.x;
    const float* xr = x + (size_t)row * D_;
    float v[4];
    float s = 0.f, s2 = 0.f;
#pragma unroll
    for (int i = 0; i < 4; i++) {
        v[i] = xr[threadIdx.x + i * 256];
        s += v[i]; s2 += v[i] * v[i];
    }
#pragma unroll
    for (int o = 16; o; o >>= 1) {
        s  += __shfl_xor_sync(0xffffffffu, s,  o);
        s2 += __shfl_xor_sync(0xffffffffu, s2, o);
    }
    __shared__ float red[16];
    int w = threadIdx.x >> 5;
    if ((threadIdx.x & 31) == 0) { red[w] = s; red[w + 8] = s2; }
    __syncthreads();
    float ts = 0.f, ts2 = 0.f;
#pragma unroll
    for (int i = 0; i < 8; i++) { ts += red[i]; ts2 += red[i + 8]; }
    float mean = ts * (1.0f / D_);
    float var  = ts2 * (1.0f / D_) - mean * mean;
    float rstd = rsqrtf(var + 1e-5f);
#pragma unroll
    for (int i = 0; i < 4; i++) {
        int c = threadIdx.x + i * 256;
        float hv = (v[i] - mean) * rstd * gamma[c] + beta[c];
        g_h[(size_t)row * D_ + c] = __float2half(hv);
    }
}

// ---------------------------------------------------------------------------
// 2) Weight transpose+convert -> fp16 hi/lo
// ---------------------------------------------------------------------------
__global__ __launch_bounds__(256) void wconv_kernel(const float* __restrict__ W0,
                                                    const float* __restrict__ W1,
                                                    const float* __restrict__ W2,
                                                    const float* __restrict__ W3) {
    __shared__ float tl[32][33];
    int wz = blockIdx.z;
    const float* W = (wz == 0) ? W0 : (wz == 1) ? W1 : (wz == 2) ? W2 : W3;
    __half* Thi = g_wt_hi[wz];
    __half* Tlo = g_wt_lo[wz];
    int n0 = blockIdx.x * 32, k0 = blockIdx.y * 32;
    int tx = threadIdx.x, ty = threadIdx.y;
#pragma unroll
    for (int j = 0; j < 4; j++)
        tl[ty + j * 8][tx] = W[(size_t)(k0 + ty + j * 8) * D_ + n0 + tx];
    __syncthreads();
#pragma unroll
    for (int j = 0; j < 4; j++) {
        int n = n0 + ty + j * 8;
        float v = tl[tx][ty + j * 8];
        __half hb = __float2half(v);
        Thi[(size_t)n * D_ + k0 + tx] = hb;
        Tlo[(size_t)n * D_ + k0 + tx] = __float2half(v - __half2float(hb));
    }
}

// ---------------------------------------------------------------------------
// 3) fp16 HMMA GEMM, 2-stage cp.async, CTA tile 128x128, BK=32
//    QKV (which<0): A single x B single (1 mma term), z selects weight
//    out-proj (which==3): A single x B hi+lo (2 mma terms)
// ---------------------------------------------------------------------------
#define BK    32
#define NCHUNK (D_/BK)
#define G_A   0
#define G_BH  10240
#define G_BL  20480
#define G_STG 30720
#define GEMM_SMEM (2*G_STG)

__global__ __launch_bounds__(256, 2) void gemm_mma_kernel(
        const __half* __restrict__ Ah,
        const float* __restrict__ exps, const float* __restrict__ x,
        float* __restrict__ y, int which) {
    extern __shared__ __align__(128) char gsm[];
    uint32_t sb = smem_u32(gsm);
    int we = (which < 0) ? (int)blockIdx.z : which;
    const bool doLo = (which == 3);
    const __half* __restrict__ Bhi = g_wt_hi[we];
    const __half* __restrict__ Blo = g_wt_lo[we];

    int t = threadIdx.x, lane = t & 31, wid = t >> 5;
    int wm = wid & 3, wn = wid >> 2;      // 4m x 2n; warp tile 32x64
    int m0 = blockIdx.y * 128, n0 = blockIdx.x * 128;
    float acc[2][8][4] = {};

    auto fill = [&](int kc, int buf) {
        int k0 = kc * BK;
        uint32_t bo = sb + buf * G_STG;
#pragma unroll
        for (int i = 0; i < 2; i++) {
            int idx = t + i * 256;
            int row = idx >> 2, seg = idx & 3;
            cpa16(bo + G_A + row * 80 + seg * 16,
                  Ah + (size_t)(m0 + row) * D_ + k0 + seg * 8);
        }
#pragma unroll
        for (int i = 0; i < 2; i++) {
            int idx = t + i * 256;
            int row = idx >> 2, seg = idx & 3;
            uint32_t d = bo + row * 80 + seg * 16;
            size_t go = (size_t)(n0 + row) * D_ + k0 + seg * 8;
            cpa16(d + G_BH, Bhi + go);
            if (doLo) cpa16(d + G_BL, Blo + go);
        }
    };

    fill(0, 0); CP_COMMIT();
    fill(1, 1); CP_COMMIT();

    for (int kc = 0; kc < NCHUNK; kc++) {
        if (kc + 1 < NCHUNK) { CP_WAIT1(); } else { CP_WAIT0(); }
        __syncthreads();
        uint32_t bo = sb + (kc & 1) * G_STG;
#pragma unroll
        for (int ks = 0; ks < BK; ks += 16) {
            uint32_t ah[2][4], bh[4][4];
#pragma unroll
            for (int mi = 0; mi < 2; mi++) {
                int ar = wm * 32 + mi * 16 + (lane & 15);
                int ac = ks + ((lane >> 4) << 3);
                ldsm4(ah[mi], bo + G_A + ar * 80 + ac * 2);
            }
#pragma unroll
            for (int p = 0; p < 4; p++) {
                int br = wn * 64 + p * 16 + (lane & 7) + ((lane & 16) ? 8 : 0);
                int bc = ks + ((lane & 8) ? 8 : 0);
                ldsm4(bh[p], bo + G_BH + br * 80 + bc * 2);
            }
#pragma unroll
            for (int mi = 0; mi < 2; mi++)
#pragma unroll
                for (int nj = 0; nj < 8; nj++)
                    mma_hf(acc[mi][nj], ah[mi], &bh[nj >> 1][(nj & 1) * 2]);
            if (doLo) {
                uint32_t bl[4][4];
#pragma unroll
                for (int p = 0; p < 4; p++) {
                    int br = wn * 64 + p * 16 + (lane & 7) + ((lane & 16) ? 8 : 0);
                    int bc = ks + ((lane & 8) ? 8 : 0);
                    ldsm4(bl[p], bo + G_BL + br * 80 + bc * 2);
                }
#pragma unroll
                for (int mi = 0; mi < 2; mi++)
#pragma unroll
                    for (int nj = 0; nj < 8; nj++)
                        mma_hf(acc[mi][nj], ah[mi], &bl[nj >> 1][(nj & 1) * 2]);
            }
        }
        __syncthreads();
        if (kc + 2 < NCHUNK) { fill(kc + 2, kc & 1); CP_COMMIT(); }
    }

    // head = full column / 64; within this CTA, head depends only on wn half
    float e = 0.f;
    if (we == 1 || we == 2) e = exps[(n0 >> 6) + wn];
#pragma unroll
    for (int mi = 0; mi < 2; mi++)
#pragma unroll
        for (int nj = 0; nj < 8; nj++)
#pragma unroll
            for (int h2 = 0; h2 < 2; h2++) {
                int m = m0 + wm * 32 + mi * 16 + (lane >> 2) + h2 * 8;
                int nc = wn * 64 + nj * 8 + (lane & 3) * 2;   // 0..127
                float v0 = acc[mi][nj][h2 * 2];
                float v1 = acc[mi][nj][h2 * 2 + 1];
                if (which < 0) {
                    if (we != 0) {
                        float mg0 = fmaxf(fabsf(v0), 1e-8f);
                        float r0 = exp2f(e * log2f(mg0));
                        v0 = (v0 > 0.f) ? r0 : (v0 < 0.f ? -r0 : 0.f);
                        float mg1 = fmaxf(fabsf(v1), 1e-8f);
                        float r1 = exp2f(e * log2f(mg1));
                        v1 = (v1 > 0.f) ? r1 : (v1 < 0.f ? -r1 : 0.f);
                    }
                    int head = (n0 + nc) >> 6;
                    int dh = (nc & 63);
                    int b = m >> 11, s = m & (S_ - 1);
                    size_t off = (((size_t)b * H_ + head) * S_ + s) * DH_ + dh;
                    uint32_t pk = packh(v0, v1);
                    if (we == 2)      *(uint32_t*)&g_v[off] = pk;
                    else if (we == 1) *(uint32_t*)&g_k[off] = pk;
                    else              *(uint32_t*)&g_q[off] = pk;
                } else {
                    size_t off = (size_t)m * D_ + n0 + nc;
                    float2 xr = *(const float2*)(x + off);
                    *(float2*)(y + off) = make_float2(xr.x + v0, xr.y + v1);
                }
            }
}

// ---------------------------------------------------------------------------
// 4) fp16 HMMA flash attention: q,k,v all single; 3-stage; big-first
// ---------------------------------------------------------------------------
#define APAD_B 144
#define A_KH 0
#define A_VH 9216
#define ABUF 18432
#define A_LKO (3*ABUF)
#define ATT_SMEM (3*ABUF + 3*256)

__global__ __launch_bounds__(256, 2) void attn_kernel(const float* __restrict__ phase,
                                                      const float* __restrict__ cph,
                                                      const float* __restrict__ bal) {
    extern __shared__ __align__(128) char asmem[];
    uint32_t sb = smem_u32(asmem);

    int t = threadIdx.x, lane = t & 31, w = t >> 5;
    int bh = blockIdx.y, b = bh >> 4, h = bh & 15;
    int qt = gridDim.x - 1 - blockIdx.x;      // big-first scheduling
    int m0 = qt * 128;
    int wr0 = m0 + w * 16;
    int r = lane >> 2, c = lane & 3;
    int nkt = 2 * qt + 2;

    float bv  = bal[0];
    float tau = fminf(fmaxf(1.0f / (2.0f * bv + 1e-8f), 0.1f), 10.0f);
    float itau = 1.0f / tau;
    float qscl = 0.125f * itau * 1.44269504f;
    float cp   = cph[h];

    uint32_t qh[4][4];
    {
        const __half* qp = g_q + ((size_t)bh * S_ + wr0) * DH_;
#pragma unroll
        for (int ks = 0; ks < 4; ks++) {
            int k0 = ks * 16 + 2 * c;
            qh[ks][0] = *(const uint32_t*)(qp + (size_t)r * DH_ + k0);
            qh[ks][1] = *(const uint32_t*)(qp + (size_t)(r + 8) * DH_ + k0);
            qh[ks][2] = *(const uint32_t*)(qp + (size_t)r * DH_ + k0 + 8);
            qh[ks][3] = *(const uint32_t*)(qp + (size_t)(r + 8) * DH_ + k0 + 8);
        }
    }

    float o[8][4] = {};
    float mx[2] = {-1e30f, -1e30f}, lsum[2] = {0.f, 0.f};

#define LOAD_TILE(kt_, st_) do {                                               \
    int kb_ = (kt_) * 64;                                                      \
    uint32_t bo_ = sb + (st_) * ABUF;                                          \
    size_t gb_ = ((size_t)bh * S_ + kb_) * DH_;                                \
    _Pragma("unroll")                                                          \
    for (int i_ = 0; i_ < 2; i_++) {                                           \
        int idx_ = t + i_ * 256;                                               \
        int row_ = idx_ >> 3, seg_ = idx_ & 7;                                 \
        uint32_t d_ = bo_ + row_ * APAD_B + seg_ * 16;                         \
        size_t go_ = gb_ + (size_t)row_ * DH_ + seg_ * 8;                      \
        cpa16(d_ + A_KH, g_k + go_);                                           \
        cpa16(d_ + A_VH, g_v + go_);                                           \
    }                                                                          \
    if (t < 16)                                                                \
        cpa16(sb + A_LKO + (st_) * 256 + t * 16,                               \
              g_lk + (size_t)bh * S_ + kb_ + t * 4);                           \
} while (0)

    LOAD_TILE(0, 0); CP_COMMIT();
    LOAD_TILE(1, 1); CP_COMMIT();

    for (int kt = 0; kt < nkt; kt++) {
        int kb = kt * 64;
        if (kt + 1 < nkt) { CP_WAIT1(); } else { CP_WAIT0(); }
        __syncthreads();
        if (kt + 2 < nkt) { LOAD_TILE(kt + 2, (kt + 2) % 3); CP_COMMIT(); }

        if (kb <= wr0 + 15) {
            uint32_t bo = sb + (kt % 3) * ABUF;
            const float* lkp = (const float*)(asmem + A_LKO + (kt % 3) * 256);
            float s[8][4];
#pragma unroll
            for (int nj = 0; nj < 8; nj++)
                s[nj][0] = s[nj][1] = s[nj][2] = s[nj][3] = 0.f;
#pragma unroll
            for (int ks = 0; ks < 4; ks++)
#pragma unroll
                for (int ng = 0; ng < 4; ng++) {
                    uint32_t kh4[4];
                    int srow = ng * 16 + (lane & 7) + ((lane & 16) ? 8 : 0);
                    int scol = ks * 16 + ((lane & 8) ? 8 : 0);
                    ldsm4(kh4, bo + A_KH + srow * APAD_B + scol * 2);
                    mma_hf(s[2 * ng],     qh[ks], &kh4[0]);
                    mma_hf(s[2 * ng + 1], qh[ks], &kh4[2]);
                }

            bool needmask = (kb + 63 > wr0);
            float tmax[2] = {-1e30f, -1e30f};
#pragma unroll
            for (int nj = 0; nj < 8; nj++) {
                int key0 = kb + nj * 8 + 2 * c;
                float l0 = lkp[nj * 8 + 2 * c], l1 = lkp[nj * 8 + 2 * c + 1];
#pragma unroll
                for (int e = 0; e < 4; e++) {
                    float z = s[nj][e] * qscl + ((e & 1) ? l1 : l0);
                    if (needmask) {
                        int qrow = wr0 + r + ((e >> 1) ? 8 : 0);
                        if (key0 + (e & 1) > qrow) z = -1e30f;
                    }
                    s[nj][e] = z;
                    int half = e >> 1;
                    tmax[half] = fmaxf(tmax[half], z);
                }
            }
#pragma unroll
            for (int i = 0; i < 2; i++) {
                tmax[i] = fmaxf(tmax[i], __shfl_xor_sync(0xffffffffu, tmax[i], 1));
                tmax[i] = fmaxf(tmax[i], __shfl_xor_sync(0xffffffffu, tmax[i], 2));
            }
            float alpha[2], rsum[2] = {0.f, 0.f};
#pragma unroll
            for (int i = 0; i < 2; i++) {
                float mn = fmaxf(mx[i], tmax[i]);
                alpha[i] = exp2_fast(mx[i] - mn);
                mx[i] = mn;
            }
#pragma unroll
            for (int nj = 0; nj < 8; nj++)
#pragma unroll
                for (int e = 0; e < 4; e++) {
                    int half = e >> 1;
                    float p = exp2_fast(s[nj][e] - mx[half]);
                    s[nj][e] = p;
                    rsum[half] += p;
                }
#pragma unroll
            for (int i = 0; i < 2; i++) {
                rsum[i] += __shfl_xor_sync(0xffffffffu, rsum[i], 1);
                rsum[i] += __shfl_xor_sync(0xffffffffu, rsum[i], 2);
                lsum[i] = lsum[i] * alpha[i] + rsum[i];
            }
#pragma unroll
            for (int nj = 0; nj < 8; nj++) {
                o[nj][0] *= alpha[0]; o[nj][1] *= alpha[0];
                o[nj][2] *= alpha[1]; o[nj][3] *= alpha[1];
            }
            uint32_t pa[4][4];
#pragma unroll
            for (int ks = 0; ks < 4; ks++) {
                pa[ks][0] = packh(s[2 * ks][0], s[2 * ks][1]);
                pa[ks][1] = packh(s[2 * ks][2], s[2 * ks][3]);
                pa[ks][2] = packh(s[2 * ks + 1][0], s[2 * ks + 1][1]);
                pa[ks][3] = packh(s[2 * ks + 1][2], s[2 * ks + 1][3]);
            }
#pragma unroll
            for (int ng = 0; ng < 4; ng++)
#pragma unroll
                for (int ks = 0; ks < 4; ks++) {
                    uint32_t vh4[4];
                    int srow = ks * 16 + (lane & 7) + ((lane & 8) ? 8 : 0);
                    int scol = ng * 16 + ((lane & 16) ? 8 : 0);
                    ldsm4t(vh4, bo + A_VH + srow * APAD_B + scol * 2);
                    mma_hf(o[2 * ng],     pa[ks], &vh4[0]);
                    mma_hf(o[2 * ng + 1], pa[ks], &vh4[2]);
                }
        }
    }

    float g[2];
#pragma unroll
    for (int i = 0; i < 2; i++) {
        int srow = wr0 + r + i * 8;
        float ph = phase[(size_t)b * S_ + srow];
        float cq = cosf((ph - cp) * 0.5f);
        g[i] = (cq * cq) / lsum[i];
    }
#pragma unroll
    for (int nj = 0; nj < 8; nj++)
#pragma unroll
        for (int i = 0; i < 2; i++) {
            int srow = wr0 + r + i * 8;
            size_t off = ((size_t)b * S_ + srow) * D_ + h * DH_ + nj * 8 + 2 * c;
            *(uint32_t*)&g_ao[off] = packh(o[nj][i * 2] * g[i],
                                           o[nj][i * 2 + 1] * g[i]);
        }
}

// ---------------------------------------------------------------------------
extern "C" void kernel_launch(void* const* d_in, const int* in_sizes, int n_in,
                              void* d_out, int out_size) {
    const float* x     = (const float*)d_in[0];
    const float* phase = (const float*)d_in[1];
    const float* Wq    = (const float*)d_in[2];
    const float* Wk    = (const float*)d_in[3];
    const float* Wv    = (const float*)d_in[4];
    const float* Wo    = (const float*)d_in[5];
    const float* gamma = (const float*)d_in[6];
    const float* beta  = (const float*)d_in[7];
    const float* exps  = (const float*)d_in[8];
    const float* cph   = (const float*)d_in[9];
    const float* bal   = (const float*)d_in[10];
    float* y = (float*)d_out;

    static __half *hh, *aoh;
    static bool got = false;
    if (!got) {
        cudaGetSymbolAddress((void**)&hh, g_h);
        cudaGetSymbolAddress((void**)&aoh, g_ao);
        cudaFuncSetAttribute((const void*)attn_kernel,
                             cudaFuncAttributeMaxDynamicSharedMemorySize, ATT_SMEM);
        cudaFuncSetAttribute((const void*)gemm_mma_kernel,
                             cudaFuncAttributeMaxDynamicSharedMemorySize, GEMM_SMEM);
        got = true;
    }

    ln_kernel<<<M_, 256>>>(x, gamma, beta);
    lkg_kernel<<<dim3(S_ / 256, B_ * H_), 256>>>(phase, cph, bal);

    wconv_kernel<<<dim3(32, 32, 4), dim3(32, 8)>>>(Wq, Wk, Wv, Wo);

    gemm_mma_kernel<<<dim3(D_ / 128, M_ / 128, 3), 256, GEMM_SMEM>>>(
        hh, exps, x, y, -1);

    attn_kernel<<<dim3(S_ / 128, B_ * H_), 256, ATT_SMEM>>>(phase, cph, bal);

    gemm_mma_kernel<<<dim3(D_ / 128, M_ / 128, 1), 256, GEMM_SMEM>>>(
        aoh, exps, x, y, 3);
}

// round 17
// speedup vs baseline: 5.6411x; 1.1383x over previous
#include <cuda_runtime.h>
#include <cuda_bf16.h>
#include <cuda_fp16.h>
#include <math.h>
#include <stdint.h>

#define B_  2
#define S_  2048
#define D_  1024
#define H_  16
#define DH_ 64
#define M_  (B_*S_)

// ---------------------------------------------------------------------------
// Scratch (all fp16)
// ---------------------------------------------------------------------------
__device__ __half g_h  [M_*D_];            // LN out, single fp16
__device__ __half g_wt [4][D_*D_];         // transposed weights [N][K], single
__device__ __half g_q  [M_*D_];            // (B,H,S,DH)
__device__ __half g_k  [M_*D_];
__device__ __half g_v  [M_*D_];
__device__ __half g_ao [M_*D_];            // (B,S,D)
__device__ float  g_lk [B_*H_*S_];         // key-side log2-resonance / tau

// ---------------------------------------------------------------------------
// helpers
// ---------------------------------------------------------------------------
__device__ __forceinline__ uint32_t smem_u32(const void* p) {
    uint32_t a;
    asm("{ .reg .u64 t; cvta.to.shared.u64 t, %1; cvt.u32.u64 %0, t; }"
        : "=r"(a) : "l"(p));
    return a;
}
__device__ __forceinline__ void ldsm4(uint32_t* r, uint32_t addr) {
    asm volatile("ldmatrix.sync.aligned.m8n8.x4.shared.b16 {%0,%1,%2,%3}, [%4];"
                 : "=r"(r[0]), "=r"(r[1]), "=r"(r[2]), "=r"(r[3]) : "r"(addr));
}
__device__ __forceinline__ void ldsm4t(uint32_t* r, uint32_t addr) {
    asm volatile("ldmatrix.sync.aligned.m8n8.x4.trans.shared.b16 {%0,%1,%2,%3}, [%4];"
                 : "=r"(r[0]), "=r"(r[1]), "=r"(r[2]), "=r"(r[3]) : "r"(addr));
}
__device__ __forceinline__ void mma_hf(float* c, const uint32_t* a, const uint32_t* b) {
    asm volatile(
        "mma.sync.aligned.m16n8k16.row.col.f32.f16.f16.f32 "
        "{%0,%1,%2,%3}, {%4,%5,%6,%7}, {%8,%9}, {%0,%1,%2,%3};"
        : "+f"(c[0]), "+f"(c[1]), "+f"(c[2]), "+f"(c[3])
        : "r"(a[0]), "r"(a[1]), "r"(a[2]), "r"(a[3]), "r"(b[0]), "r"(b[1]));
}
__device__ __forceinline__ void cpa16(uint32_t smaddr, const void* g) {
    asm volatile("cp.async.cg.shared.global [%0], [%1], 16;"
                 :: "r"(smaddr), "l"(__cvta_generic_to_global(g)));
}
#define CP_COMMIT() asm volatile("cp.async.commit_group;" ::: "memory")
#define CP_WAIT1()  asm volatile("cp.async.wait_group 1;" ::: "memory")
#define CP_WAIT0()  asm volatile("cp.async.wait_group 0;" ::: "memory")

__device__ __forceinline__ uint32_t packh(float x0, float x1) {
    __half2 h = __floats2half2_rn(x0, x1);
    return *reinterpret_cast<uint32_t*>(&h);
}
// exp2 on the fma pipe; valid for z <= 0 (clamped at -80)
__device__ __forceinline__ float exp2_fast(float z) {
    z = fmaxf(z, -80.f);
    float fm = z + 12582912.f;
    int i = __float_as_int(fm) - 0x4B400000;
    float f = z - (fm - 12582912.f);
    float p = 1.333356e-3f;
    p = fmaf(p, f, 9.618129e-3f);
    p = fmaf(p, f, 5.5504109e-2f);
    p = fmaf(p, f, 2.40226507e-1f);
    p = fmaf(p, f, 6.93147181e-1f);
    p = fmaf(p, f, 1.0f);
    return p * __int_as_float((i + 127) << 23);
}

// ---------------------------------------------------------------------------
// 0) key-side resonance precompute
// ---------------------------------------------------------------------------
__global__ __launch_bounds__(256) void lkg_kernel(const float* __restrict__ phase,
                                                  const float* __restrict__ cph,
                                                  const float* __restrict__ bal) {
    int bh = blockIdx.y, b = bh >> 4, h = bh & 15;
    int s = blockIdx.x * 256 + threadIdx.x;
    float bv  = bal[0];
    float tau = fminf(fmaxf(1.0f / (2.0f * bv + 1e-8f), 0.1f), 10.0f);
    float itau = 1.0f / tau;
    float cc = cosf((phase[(size_t)b * S_ + s] - cph[h]) * 0.5f);
    g_lk[(size_t)bh * S_ + s] = log2f(cc * cc + 1e-6f) * itau;
}

// ---------------------------------------------------------------------------
// 1) LayerNorm -> single fp16
// ---------------------------------------------------------------------------
__global__ __launch_bounds__(256) void ln_kernel(const float* __restrict__ x,
                                                 const float* __restrict__ gamma,
                                                 const float* __restrict__ beta) {
    int row = blockIdx.x;
    const float* xr = x + (size_t)row * D_;
    float v[4];
    float s = 0.f, s2 = 0.f;
#pragma unroll
    for (int i = 0; i < 4; i++) {
        v[i] = xr[threadIdx.x + i * 256];
        s += v[i]; s2 += v[i] * v[i];
    }
#pragma unroll
    for (int o = 16; o; o >>= 1) {
        s  += __shfl_xor_sync(0xffffffffu, s,  o);
        s2 += __shfl_xor_sync(0xffffffffu, s2, o);
    }
    __shared__ float red[16];
    int w = threadIdx.x >> 5;
    if ((threadIdx.x & 31) == 0) { red[w] = s; red[w + 8] = s2; }
    __syncthreads();
    float ts = 0.f, ts2 = 0.f;
#pragma unroll
    for (int i = 0; i < 8; i++) { ts += red[i]; ts2 += red[i + 8]; }
    float mean = ts * (1.0f / D_);
    float var  = ts2 * (1.0f / D_) - mean * mean;
    float rstd = rsqrtf(var + 1e-5f);
#pragma unroll
    for (int i = 0; i < 4; i++) {
        int c = threadIdx.x + i * 256;
        float hv = (v[i] - mean) * rstd * gamma[c] + beta[c];
        g_h[(size_t)row * D_ + c] = __float2half(hv);
    }
}

// ---------------------------------------------------------------------------
// 2) Weight transpose+convert -> single fp16
// ---------------------------------------------------------------------------
__global__ __launch_bounds__(256) void wconv_kernel(const float* __restrict__ W0,
                                                    const float* __restrict__ W1,
                                                    const float* __restrict__ W2,
                                                    const float* __restrict__ W3) {
    __shared__ float tl[32][33];
    int wz = blockIdx.z;
    const float* W = (wz == 0) ? W0 : (wz == 1) ? W1 : (wz == 2) ? W2 : W3;
    __half* Th = g_wt[wz];
    int n0 = blockIdx.x * 32, k0 = blockIdx.y * 32;
    int tx = threadIdx.x, ty = threadIdx.y;
#pragma unroll
    for (int j = 0; j < 4; j++)
        tl[ty + j * 8][tx] = W[(size_t)(k0 + ty + j * 8) * D_ + n0 + tx];
    __syncthreads();
#pragma unroll
    for (int j = 0; j < 4; j++) {
        int n = n0 + ty + j * 8;
        Th[(size_t)n * D_ + k0 + tx] = __float2half(tl[tx][ty + j * 8]);
    }
}

// ---------------------------------------------------------------------------
// 3) fp16 HMMA GEMM, 2-stage cp.async, CTA tile 128x128, BK=64
//    single x single (1 mma term). which<0: QKV via blockIdx.z; which==3: out
// ---------------------------------------------------------------------------
#define BK    64
#define NCHUNK (D_/BK)
#define GPITCH 144
#define G_A   0
#define G_B   18432
#define G_STG 36864
#define GEMM_SMEM (2*G_STG)

__global__ __launch_bounds__(256, 2) void gemm_mma_kernel(
        const __half* __restrict__ Ah,
        const float* __restrict__ exps, const float* __restrict__ x,
        float* __restrict__ y, int which) {
    extern __shared__ __align__(128) char gsm[];
    uint32_t sb = smem_u32(gsm);
    int we = (which < 0) ? (int)blockIdx.z : which;
    const __half* __restrict__ Bh = g_wt[we];

    int t = threadIdx.x, lane = t & 31, wid = t >> 5;
    int wm = wid & 3, wn = wid >> 2;      // 4m x 2n; warp tile 32x64
    int m0 = blockIdx.y * 128, n0 = blockIdx.x * 128;
    float acc[2][8][4] = {};

    auto fill = [&](int kc, int buf) {
        int k0 = kc * BK;
        uint32_t bo = sb + buf * G_STG;
#pragma unroll
        for (int i = 0; i < 4; i++) {
            int idx = t + i * 256;
            int row = idx >> 3, seg = idx & 7;
            cpa16(bo + G_A + row * GPITCH + seg * 16,
                  Ah + (size_t)(m0 + row) * D_ + k0 + seg * 8);
        }
#pragma unroll
        for (int i = 0; i < 4; i++) {
            int idx = t + i * 256;
            int row = idx >> 3, seg = idx & 7;
            cpa16(bo + G_B + row * GPITCH + seg * 16,
                  Bh + (size_t)(n0 + row) * D_ + k0 + seg * 8);
        }
    };

    fill(0, 0); CP_COMMIT();
    fill(1, 1); CP_COMMIT();

    for (int kc = 0; kc < NCHUNK; kc++) {
        if (kc + 1 < NCHUNK) { CP_WAIT1(); } else { CP_WAIT0(); }
        __syncthreads();
        uint32_t bo = sb + (kc & 1) * G_STG;
#pragma unroll
        for (int ks = 0; ks < BK; ks += 16) {
            uint32_t ah[2][4], bh[4][4];
#pragma unroll
            for (int mi = 0; mi < 2; mi++) {
                int ar = wm * 32 + mi * 16 + (lane & 15);
                int ac = ks + ((lane >> 4) << 3);
                ldsm4(ah[mi], bo + G_A + ar * GPITCH + ac * 2);
            }
#pragma unroll
            for (int p = 0; p < 4; p++) {
                int br = wn * 64 + p * 16 + (lane & 7) + ((lane & 16) ? 8 : 0);
                int bc = ks + ((lane & 8) ? 8 : 0);
                ldsm4(bh[p], bo + G_B + br * GPITCH + bc * 2);
            }
#pragma unroll
            for (int mi = 0; mi < 2; mi++)
#pragma unroll
                for (int nj = 0; nj < 8; nj++)
                    mma_hf(acc[mi][nj], ah[mi], &bh[nj >> 1][(nj & 1) * 2]);
        }
        __syncthreads();
        if (kc + 2 < NCHUNK) { fill(kc + 2, kc & 1); CP_COMMIT(); }
    }

    float e = 0.f;
    if (we == 1 || we == 2) e = exps[(n0 >> 6) + wn];
#pragma unroll
    for (int mi = 0; mi < 2; mi++)
#pragma unroll
        for (int nj = 0; nj < 8; nj++)
#pragma unroll
            for (int h2 = 0; h2 < 2; h2++) {
                int m = m0 + wm * 32 + mi * 16 + (lane >> 2) + h2 * 8;
                int nc = wn * 64 + nj * 8 + (lane & 3) * 2;   // 0..127
                float v0 = acc[mi][nj][h2 * 2];
                float v1 = acc[mi][nj][h2 * 2 + 1];
                if (which < 0) {
                    if (we != 0) {
                        float mg0 = fmaxf(fabsf(v0), 1e-8f);
                        float r0 = exp2f(e * log2f(mg0));
                        v0 = (v0 > 0.f) ? r0 : (v0 < 0.f ? -r0 : 0.f);
                        float mg1 = fmaxf(fabsf(v1), 1e-8f);
                        float r1 = exp2f(e * log2f(mg1));
                        v1 = (v1 > 0.f) ? r1 : (v1 < 0.f ? -r1 : 0.f);
                    }
                    int head = (n0 + nc) >> 6;
                    int dh = (nc & 63);
                    int b = m >> 11, s = m & (S_ - 1);
                    size_t off = (((size_t)b * H_ + head) * S_ + s) * DH_ + dh;
                    uint32_t pk = packh(v0, v1);
                    if (we == 2)      *(uint32_t*)&g_v[off] = pk;
                    else if (we == 1) *(uint32_t*)&g_k[off] = pk;
                    else              *(uint32_t*)&g_q[off] = pk;
                } else {
                    size_t off = (size_t)m * D_ + n0 + nc;
                    float2 xr = *(const float2*)(x + off);
                    *(float2*)(y + off) = make_float2(xr.x + v0, xr.y + v1);
                }
            }
}

// ---------------------------------------------------------------------------
// 4) fp16 HMMA flash attention: q,k,v all single; 3-stage; big-first
// ---------------------------------------------------------------------------
#define APAD_B 144
#define A_KH 0
#define A_VH 9216
#define ABUF 18432
#define A_LKO (3*ABUF)
#define ATT_SMEM (3*ABUF + 3*256)

__global__ __launch_bounds__(256, 2) void attn_kernel(const float* __restrict__ phase,
                                                      const float* __restrict__ cph,
                                                      const float* __restrict__ bal) {
    extern __shared__ __align__(128) char asmem[];
    uint32_t sb = smem_u32(asmem);

    int t = threadIdx.x, lane = t & 31, w = t >> 5;
    int bh = blockIdx.y, b = bh >> 4, h = bh & 15;
    int qt = gridDim.x - 1 - blockIdx.x;      // big-first scheduling
    int m0 = qt * 128;
    int wr0 = m0 + w * 16;
    int r = lane >> 2, c = lane & 3;
    int nkt = 2 * qt + 2;

    float bv  = bal[0];
    float tau = fminf(fmaxf(1.0f / (2.0f * bv + 1e-8f), 0.1f), 10.0f);
    float itau = 1.0f / tau;
    float qscl = 0.125f * itau * 1.44269504f;
    float cp   = cph[h];

    uint32_t qh[4][4];
    {
        const __half* qp = g_q + ((size_t)bh * S_ + wr0) * DH_;
#pragma unroll
        for (int ks = 0; ks < 4; ks++) {
            int k0 = ks * 16 + 2 * c;
            qh[ks][0] = *(const uint32_t*)(qp + (size_t)r * DH_ + k0);
            qh[ks][1] = *(const uint32_t*)(qp + (size_t)(r + 8) * DH_ + k0);
            qh[ks][2] = *(const uint32_t*)(qp + (size_t)r * DH_ + k0 + 8);
            qh[ks][3] = *(const uint32_t*)(qp + (size_t)(r + 8) * DH_ + k0 + 8);
        }
    }

    float o[8][4] = {};
    float mx[2] = {-1e30f, -1e30f}, lsum[2] = {0.f, 0.f};

#define LOAD_TILE(kt_, st_) do {                                               \
    int kb_ = (kt_) * 64;                                                      \
    uint32_t bo_ = sb + (st_) * ABUF;                                          \
    size_t gb_ = ((size_t)bh * S_ + kb_) * DH_;                                \
    _Pragma("unroll")                                                          \
    for (int i_ = 0; i_ < 2; i_++) {                                           \
        int idx_ = t + i_ * 256;                                               \
        int row_ = idx_ >> 3, seg_ = idx_ & 7;                                 \
        uint32_t d_ = bo_ + row_ * APAD_B + seg_ * 16;                         \
        size_t go_ = gb_ + (size_t)row_ * DH_ + seg_ * 8;                      \
        cpa16(d_ + A_KH, g_k + go_);                                           \
        cpa16(d_ + A_VH, g_v + go_);                                           \
    }                                                                          \
    if (t < 16)                                                                \
        cpa16(sb + A_LKO + (st_) * 256 + t * 16,                               \
              g_lk + (size_t)bh * S_ + kb_ + t * 4);                           \
} while (0)

    LOAD_TILE(0, 0); CP_COMMIT();
    LOAD_TILE(1, 1); CP_COMMIT();

    for (int kt = 0; kt < nkt; kt++) {
        int kb = kt * 64;
        if (kt + 1 < nkt) { CP_WAIT1(); } else { CP_WAIT0(); }
        __syncthreads();
        if (kt + 2 < nkt) { LOAD_TILE(kt + 2, (kt + 2) % 3); CP_COMMIT(); }

        if (kb <= wr0 + 15) {
            uint32_t bo = sb + (kt % 3) * ABUF;
            const float* lkp = (const float*)(asmem + A_LKO + (kt % 3) * 256);
            float s[8][4];
#pragma unroll
            for (int nj = 0; nj < 8; nj++)
                s[nj][0] = s[nj][1] = s[nj][2] = s[nj][3] = 0.f;
#pragma unroll
            for (int ks = 0; ks < 4; ks++)
#pragma unroll
                for (int ng = 0; ng < 4; ng++) {
                    uint32_t kh4[4];
                    int srow = ng * 16 + (lane & 7) + ((lane & 16) ? 8 : 0);
                    int scol = ks * 16 + ((lane & 8) ? 8 : 0);
                    ldsm4(kh4, bo + A_KH + srow * APAD_B + scol * 2);
                    mma_hf(s[2 * ng],     qh[ks], &kh4[0]);
                    mma_hf(s[2 * ng + 1], qh[ks], &kh4[2]);
                }

            bool needmask = (kb + 63 > wr0);
            float tmax[2] = {-1e30f, -1e30f};
#pragma unroll
            for (int nj = 0; nj < 8; nj++) {
                int key0 = kb + nj * 8 + 2 * c;
                float l0 = lkp[nj * 8 + 2 * c], l1 = lkp[nj * 8 + 2 * c + 1];
#pragma unroll
                for (int e = 0; e < 4; e++) {
                    float z = s[nj][e] * qscl + ((e & 1) ? l1 : l0);
                    if (needmask) {
                        int qrow = wr0 + r + ((e >> 1) ? 8 : 0);
                        if (key0 + (e & 1) > qrow) z = -1e30f;
                    }
                    s[nj][e] = z;
                    int half = e >> 1;
                    tmax[half] = fmaxf(tmax[half], z);
                }
            }
#pragma unroll
            for (int i = 0; i < 2; i++) {
                tmax[i] = fmaxf(tmax[i], __shfl_xor_sync(0xffffffffu, tmax[i], 1));
                tmax[i] = fmaxf(tmax[i], __shfl_xor_sync(0xffffffffu, tmax[i], 2));
            }
            float alpha[2], rsum[2] = {0.f, 0.f};
#pragma unroll
            for (int i = 0; i < 2; i++) {
                float mn = fmaxf(mx[i], tmax[i]);
                alpha[i] = exp2_fast(mx[i] - mn);
                mx[i] = mn;
            }
#pragma unroll
            for (int nj = 0; nj < 8; nj++)
#pragma unroll
                for (int e = 0; e < 4; e++) {
                    int half = e >> 1;
                    float p = exp2_fast(s[nj][e] - mx[half]);
                    s[nj][e] = p;
                    rsum[half] += p;
                }
#pragma unroll
            for (int i = 0; i < 2; i++) {
                rsum[i] += __shfl_xor_sync(0xffffffffu, rsum[i], 1);
                rsum[i] += __shfl_xor_sync(0xffffffffu, rsum[i], 2);
                lsum[i] = lsum[i] * alpha[i] + rsum[i];
            }
#pragma unroll
            for (int nj = 0; nj < 8; nj++) {
                o[nj][0] *= alpha[0]; o[nj][1] *= alpha[0];
                o[nj][2] *= alpha[1]; o[nj][3] *= alpha[1];
            }
            uint32_t pa[4][4];
#pragma unroll
            for (int ks = 0; ks < 4; ks++) {
                pa[ks][0] = packh(s[2 * ks][0], s[2 * ks][1]);
                pa[ks][1] = packh(s[2 * ks][2], s[2 * ks][3]);
                pa[ks][2] = packh(s[2 * ks + 1][0], s[2 * ks + 1][1]);
                pa[ks][3] = packh(s[2 * ks + 1][2], s[2 * ks + 1][3]);
            }
#pragma unroll
            for (int ng = 0; ng < 4; ng++)
#pragma unroll
                for (int ks = 0; ks < 4; ks++) {
                    uint32_t vh4[4];
                    int srow = ks * 16 + (lane & 7) + ((lane & 8) ? 8 : 0);
                    int scol = ng * 16 + ((lane & 16) ? 8 : 0);
                    ldsm4t(vh4, bo + A_VH + srow * APAD_B + scol * 2);
                    mma_hf(o[2 * ng],     pa[ks], &vh4[0]);
                    mma_hf(o[2 * ng + 1], pa[ks], &vh4[2]);
                }
        }
    }

    float g[2];
#pragma unroll
    for (int i = 0; i < 2; i++) {
        int srow = wr0 + r + i * 8;
        float ph = phase[(size_t)b * S_ + srow];
        float cq = cosf((ph - cp) * 0.5f);
        g[i] = (cq * cq) / lsum[i];
    }
#pragma unroll
    for (int nj = 0; nj < 8; nj++)
#pragma unroll
        for (int i = 0; i < 2; i++) {
            int srow = wr0 + r + i * 8;
            size_t off = ((size_t)b * S_ + srow) * D_ + h * DH_ + nj * 8 + 2 * c;
            *(uint32_t*)&g_ao[off] = packh(o[nj][i * 2] * g[i],
                                           o[nj][i * 2 + 1] * g[i]);
        }
}

// ---------------------------------------------------------------------------
extern "C" void kernel_launch(void* const* d_in, const int* in_sizes, int n_in,
                              void* d_out, int out_size) {
    const float* x     = (const float*)d_in[0];
    const float* phase = (const float*)d_in[1];
    const float* Wq    = (const float*)d_in[2];
    const float* Wk    = (const float*)d_in[3];
    const float* Wv    = (const float*)d_in[4];
    const float* Wo    = (const float*)d_in[5];
    const float* gamma = (const float*)d_in[6];
    const float* beta  = (const float*)d_in[7];
    const float* exps  = (const float*)d_in[8];
    const float* cph   = (const float*)d_in[9];
    const float* bal   = (const float*)d_in[10];
    float* y = (float*)d_out;

    static __half *hh, *aoh;
    static bool got = false;
    if (!got) {
        cudaGetSymbolAddress((void**)&hh, g_h);
        cudaGetSymbolAddress((void**)&aoh, g_ao);
        cudaFuncSetAttribute((const void*)attn_kernel,
                             cudaFuncAttributeMaxDynamicSharedMemorySize, ATT_SMEM);
        cudaFuncSetAttribute((const void*)gemm_mma_kernel,
                             cudaFuncAttributeMaxDynamicSharedMemorySize, GEMM_SMEM);
        got = true;
    }

    ln_kernel<<<M_, 256>>>(x, gamma, beta);
    lkg_kernel<<<dim3(S_ / 256, B_ * H_), 256>>>(phase, cph, bal);

    wconv_kernel<<<dim3(32, 32, 4), dim3(32, 8)>>>(Wq, Wk, Wv, Wo);

    gemm_mma_kernel<<<dim3(D_ / 128, M_ / 128, 3), 256, GEMM_SMEM>>>(
        hh, exps, x, y, -1);

    attn_kernel<<<dim3(S_ / 128, B_ * H_), 256, ATT_SMEM>>>(phase, cph, bal);

    gemm_mma_kernel<<<dim3(D_ / 128, M_ / 128, 1), 256, GEMM_SMEM>>>(
        aoh, exps, x, y, 3);
}